// round 11
// baseline (speedup 1.0000x reference)
#include <cuda_runtime.h>
#include <cuda_fp16.h>
#include <math.h>
#include <stdint.h>

// ---------------- problem constants ----------------
#define BB 8
#define LL 1024
#define CC 1024
#define HH 16
#define DKK 64
#define NTOK (BB*LL)            // 8192
#define EE 16
#define HIDD 64
#define CAPP 256
#define NCE ((size_t)NTOK * CC)

// ---------------- baseline-PTX tensor-core helpers (sm_80+) ----------------
__device__ __forceinline__ uint32_t smem_u32(const void* p) {
    uint32_t a;
    asm("{ .reg .u64 t; cvta.to.shared.u64 t, %1; cvt.u32.u64 %0, t; }" : "=r"(a) : "l"(p));
    return a;
}
#define LDSM4(d0, d1, d2, d3, a) \
    asm volatile("ldmatrix.sync.aligned.m8n8.x4.shared.b16 {%0,%1,%2,%3}, [%4];" \
        : "=r"(d0), "=r"(d1), "=r"(d2), "=r"(d3) : "r"(a))
#define LDSM4T(d0, d1, d2, d3, a) \
    asm volatile("ldmatrix.sync.aligned.m8n8.x4.trans.shared.b16 {%0,%1,%2,%3}, [%4];" \
        : "=r"(d0), "=r"(d1), "=r"(d2), "=r"(d3) : "r"(a))
#define MMA16816(c, a0, a1, a2, a3, b0, b1) \
    asm volatile("mma.sync.aligned.m16n8k16.row.col.f32.f16.f16.f32 " \
        "{%0,%1,%2,%3}, {%4,%5,%6,%7}, {%8,%9}, {%0,%1,%2,%3};" \
        : "+f"((c)[0]), "+f"((c)[1]), "+f"((c)[2]), "+f"((c)[3]) \
        : "r"(a0), "r"(a1), "r"(a2), "r"(a3), "r"(b0), "r"(b1))
#define CP_ASYNC16(dst, src) \
    asm volatile("cp.async.cg.shared.global [%0], [%1], 16;" :: "r"(dst), "l"(src))
#define CP_COMMIT() asm volatile("cp.async.commit_group;" ::: "memory")
#define CP_WAIT1()  asm volatile("cp.async.wait_group 1;" ::: "memory")

// ---------------- fp16 2-term split helpers ----------------
__device__ __forceinline__ void split2r(float a, __half& h0, __half& h1)
{
    h0 = __float2half_rn(a);
    h1 = __float2half_rn(a - __half2float(h0));
}
__device__ __forceinline__ uint32_t pkh(__half lo, __half hi)
{
    __half2 t = __halves2half2(lo, hi);
    return *reinterpret_cast<uint32_t*>(&t);
}
__device__ __forceinline__ void store_split_pair(
    __half* Y0, __half* Y1, size_t off, float e0, float e1)
{
    __half a0, a1, b0, b1;
    split2r(e0, a0, a1);
    split2r(e1, b0, b1);
    *(uint32_t*)(Y0 + off) = pkh(a0, b0);
    *(uint32_t*)(Y1 + off) = pkh(a1, b1);
}

// ---------------- scratch ----------------
__device__ float g_A [NTOK * CC];
__device__ float g_zn[NTOK * CC];
__device__ float g_eb[EE * CAPP * CC];
__device__ float g_h [EE * CAPP * HIDD];
__device__ float g_y [EE * CAPP * CC];
__device__ int   g_route[NTOK];
__device__ int   g_pos  [NTOK];
__device__ __half g_xq0[NTOK*CC], g_xq1[NTOK*CC];
__device__ __half g_xk0[NTOK*CC], g_xk1[NTOK*CC];
__device__ __half g_xv0[NTOK*CC], g_xv1[NTOK*CC];
__device__ __half g_wq0[CC*CC], g_wq1[CC*CC];
__device__ __half g_wk0[CC*CC], g_wk1[CC*CC];
__device__ __half g_wv0[CC*CC], g_wv1[CC*CC];
__device__ __half g_wo0[CC*CC], g_wo1[CC*CC];
__device__ __half g_q0[NTOK*CC], g_q1[NTOK*CC];
__device__ __half g_k0[NTOK*CC], g_k1[NTOK*CC];
__device__ __half g_v0[NTOK*CC], g_v1[NTOK*CC];

// ---------------- fp32 -> 2x fp16 split ----------------
__global__ void __launch_bounds__(256)
split2_kernel(const float* __restrict__ in, __half* __restrict__ o0,
              __half* __restrict__ o1, int n4)
{
    int i = blockIdx.x * 256 + threadIdx.x;
    if (i >= n4) return;
    float4 v = ((const float4*)in)[i];
    float a[4] = {v.x, v.y, v.z, v.w};
    union { __half b[4]; uint2 u; } s0, s1;
    #pragma unroll
    for (int j = 0; j < 4; j++) split2r(a[j], s0.b[j], s1.b[j]);
    ((uint2*)o0)[i] = s0.u;
    ((uint2*)o1)[i] = s1.u;
}

// ---------------- HMMA GEMM core (fp16x3), 2-stage, 2 CTAs/SM ----------------
#define APAD 40
#define TILE_B (128 * APAD * 2)     // 10240
#define STAGE4 (4 * TILE_B)         // 40960
#define GEMM_SMEM (2 * STAGE4)      // 81920
#define NCHUNK 32

template <int OutMode>
__device__ __forceinline__ void gemm_core(
    const __half* __restrict__ X0, const __half* __restrict__ X1,
    const __half* __restrict__ W0, const __half* __restrict__ W1,
    const float* __restrict__ bias,
    float* __restrict__ Yf,
    __half* __restrict__ Y0, __half* __restrict__ Y1,
    char* smem)
{
    const uint32_t sb = smem_u32(smem);
    const int tid = threadIdx.x, wid = tid >> 5, lane = tid & 31;
    const int bm = blockIdx.y * 128, bn = blockIdx.x * 128;
    const int wm = (wid >> 2) * 64, wn = (wid & 3) * 32;

    const __half* TS[4] = {X0, X1, W0, W1};

    #define G_LOAD(buf, ch) do { \
        int ko_ = (ch) * 32; \
        _Pragma("unroll") \
        for (int j_ = 0; j_ < 8; j_++) { \
            int e_ = j_ * 256 + tid; \
            int t_ = e_ >> 9; \
            int w_ = e_ & 511; \
            int r_ = w_ >> 2, c8_ = (w_ & 3) * 8; \
            int rowb_ = ((t_ < 2) ? bm : bn) + r_; \
            CP_ASYNC16(sb + (buf) * STAGE4 + t_ * TILE_B + (r_ * APAD + c8_) * 2, \
                       TS[t_] + (size_t)rowb_ * CC + ko_ + c8_); \
        } \
    } while (0)

    float acc[4][4][4];
    #pragma unroll
    for (int i = 0; i < 4; i++)
        #pragma unroll
        for (int j = 0; j < 4; j++)
            #pragma unroll
            for (int q = 0; q < 4; q++) acc[i][j][q] = 0.f;

    G_LOAD(0, 0); CP_COMMIT();
    G_LOAD(1, 1); CP_COMMIT();

    for (int c = 0; c < NCHUNK; c++) {
        int buf = c & 1;
        CP_WAIT1();
        __syncthreads();

        uint32_t stage = sb + buf * STAGE4;
        #pragma unroll
        for (int kk = 0; kk < 2; kk++) {
            uint32_t a[2][4][4];
            #pragma unroll
            for (int s = 0; s < 2; s++)
                #pragma unroll
                for (int i = 0; i < 4; i++) {
                    int arow = wm + i * 16 + (lane & 15);
                    int acol = kk * 16 + ((lane >> 4) << 3);
                    LDSM4(a[s][i][0], a[s][i][1], a[s][i][2], a[s][i][3],
                          stage + s * TILE_B + (uint32_t)(arow * APAD + acol) * 2);
                }
            #pragma unroll
            for (int jp = 0; jp < 2; jp++) {
                int g = lane >> 3;
                int brow = wn + jp * 16 + ((g & 2) << 2) + (lane & 7);
                int bcol = kk * 16 + ((g & 1) << 3);
                uint32_t boff = (uint32_t)(brow * APAD + bcol) * 2;
                uint32_t b0, b1, b2, b3;
                // ---- W0 fragment: issue grouped by product so each acc is
                // revisited only after 8 intervening independent MMAs.
                LDSM4(b0, b1, b2, b3, stage + 2 * TILE_B + boff);
                #pragma unroll
                for (int i = 0; i < 4; i++) {      // X0 * W0 (8 MMAs)
                    MMA16816(acc[i][2*jp],   a[0][i][0],a[0][i][1],a[0][i][2],a[0][i][3], b0,b1);
                    MMA16816(acc[i][2*jp+1], a[0][i][0],a[0][i][1],a[0][i][2],a[0][i][3], b2,b3);
                }
                #pragma unroll
                for (int i = 0; i < 4; i++) {      // X1 * W0 (8 MMAs)
                    MMA16816(acc[i][2*jp],   a[1][i][0],a[1][i][1],a[1][i][2],a[1][i][3], b0,b1);
                    MMA16816(acc[i][2*jp+1], a[1][i][0],a[1][i][1],a[1][i][2],a[1][i][3], b2,b3);
                }
                // ---- W1 fragment: X0 * W1 (8 MMAs)
                LDSM4(b0, b1, b2, b3, stage + 3 * TILE_B + boff);
                #pragma unroll
                for (int i = 0; i < 4; i++) {
                    MMA16816(acc[i][2*jp],   a[0][i][0],a[0][i][1],a[0][i][2],a[0][i][3], b0,b1);
                    MMA16816(acc[i][2*jp+1], a[0][i][0],a[0][i][1],a[0][i][2],a[0][i][3], b2,b3);
                }
            }
        }
        __syncthreads();
        if (c + 2 < NCHUNK) {
            G_LOAD(buf, c + 2);
        }
        CP_COMMIT();
    }

    #pragma unroll
    for (int i = 0; i < 4; i++) {
        int row = bm + wm + i * 16 + (lane >> 2);
        #pragma unroll
        for (int j = 0; j < 4; j++) {
            int col = bn + wn + j * 8 + ((lane & 3) << 1);
            float bx = bias[col], by = bias[col + 1];
            float e0 = acc[i][j][0] + bx, e1 = acc[i][j][1] + by;
            float e2 = acc[i][j][2] + bx, e3 = acc[i][j][3] + by;
            if (OutMode == 0) {
                float2 v0 = {e0, e1};
                float2 v1 = {e2, e3};
                *(float2*)(Yf + (size_t)row * CC + col) = v0;
                *(float2*)(Yf + (size_t)(row + 8) * CC + col) = v1;
            } else {
                store_split_pair(Y0, Y1, (size_t)row * CC + col, e0, e1);
                store_split_pair(Y0, Y1, (size_t)(row + 8) * CC + col, e2, e3);
            }
        }
    }
    #undef G_LOAD
}

__global__ void __launch_bounds__(256, 2)
mma_gemm(const __half* __restrict__ X0, const __half* __restrict__ X1,
         const __half* __restrict__ W0, const __half* __restrict__ W1,
         const float* __restrict__ bias, float* __restrict__ Y)
{
    extern __shared__ char smem[];
    gemm_core<0>(X0, X1, W0, W1, bias, Y, nullptr, nullptr, smem);
}

__global__ void __launch_bounds__(256, 2)
mma_gemm_s(const __half* __restrict__ X0, const __half* __restrict__ X1,
           const __half* __restrict__ W0, const __half* __restrict__ W1,
           const float* __restrict__ bias,
           __half* __restrict__ Y0, __half* __restrict__ Y1)
{
    extern __shared__ char smem[];
    gemm_core<1>(X0, X1, W0, W1, bias, nullptr, Y0, Y1, smem);
}

// ---------------- flash attention on HMMA (fp16x3), split-output epilogue ----
#define QTILE (128 * 72 * 2)      // 18432
#define KVTILE (64 * 72 * 2)      // 9216
#define AT_SOFF (2 * QTILE)       // 36864
#define AT_STG (4 * KVTILE)       // 36864
#define ATTN_SMEM (AT_SOFF + 2 * AT_STG)   // 110592

__global__ void __launch_bounds__(256)
attn_mma(const __half* __restrict__ Q0, const __half* __restrict__ Q1,
         const __half* __restrict__ K0, const __half* __restrict__ K1,
         const __half* __restrict__ V0, const __half* __restrict__ V1,
         __half* __restrict__ Z0, __half* __restrict__ Z1)
{
    extern __shared__ char smem[];
    const uint32_t sb = smem_u32(smem);
    const int tid = threadIdx.x, wid = tid >> 5, lane = tid & 31;
    const int bh = blockIdx.y;
    const int b = bh >> 4, hh = bh & 15;
    const int q0 = blockIdx.x * 128;

    const __half* QS[2] = {Q0, Q1};
    const __half* KS[2] = {K0, K1};
    const __half* VS[2] = {V0, V1};

    #pragma unroll
    for (int j = 0; j < 8; j++) {
        int e = j * 256 + tid;
        int t = e >> 10;
        int w = e & 1023;
        int r = w >> 3, c = w & 7;
        CP_ASYNC16(sb + t * QTILE + (uint32_t)(r * 72 + c * 8) * 2,
                   QS[t] + (size_t)(b * LL + q0 + r) * CC + hh * 64 + c * 8);
    }

    #define KV_LOAD(buf, kt) do { \
        _Pragma("unroll") \
        for (int j_ = 0; j_ < 8; j_++) { \
            int e_ = j_ * 256 + tid; \
            int t_ = e_ >> 9; \
            int w_ = e_ & 511; \
            int r_ = w_ >> 3, c_ = w_ & 7; \
            const __half* src_ = (t_ < 2) ? KS[t_] : VS[t_ - 2]; \
            CP_ASYNC16(sb + AT_SOFF + (buf) * AT_STG + t_ * KVTILE + \
                       (uint32_t)(r_ * 72 + c_ * 8) * 2, \
                       src_ + (size_t)(b * LL + (kt) * 64 + r_) * CC + hh * 64 + c_ * 8); \
        } \
    } while (0)

    KV_LOAD(0, 0); CP_COMMIT();
    KV_LOAD(1, 1); CP_COMMIT();

    float pv[8][4];
    #pragma unroll
    for (int j = 0; j < 8; j++)
        #pragma unroll
        for (int q = 0; q < 4; q++) pv[j][q] = 0.f;
    float m0 = -1e30f, m1 = -1e30f, l0 = 0.f, l1 = 0.f;
    uint32_t qf[2][4][4];

    for (int kt = 0; kt < LL / 64; kt++) {
        CP_WAIT1();
        __syncthreads();
        if (kt == 0) {
            #pragma unroll
            for (int s = 0; s < 2; s++)
                #pragma unroll
                for (int ks = 0; ks < 4; ks++) {
                    int arow = wid * 16 + (lane & 15);
                    int acol = ks * 16 + ((lane >> 4) << 3);
                    LDSM4(qf[s][ks][0], qf[s][ks][1], qf[s][ks][2], qf[s][ks][3],
                          sb + s * QTILE + (uint32_t)(arow * 72 + acol) * 2);
                }
        }

        uint32_t sK = sb + AT_SOFF + (kt & 1) * AT_STG;
        uint32_t sV = sK + 2 * KVTILE;

        float sacc[8][4];
        #pragma unroll
        for (int j = 0; j < 8; j++)
            #pragma unroll
            for (int q = 0; q < 4; q++) sacc[j][q] = 0.f;

        // ---- S = Q K^T, ntp processed in pairs with product-grouped MMAs ----
        #pragma unroll
        for (int ks = 0; ks < 4; ks++) {
            #pragma unroll
            for (int np = 0; np < 2; np++) {     // ntp pair {2np, 2np+1}
                int g = lane >> 3;
                int r0 = (2*np) * 16 + ((g & 2) << 2) + (lane & 7);
                int r1 = (2*np+1) * 16 + ((g & 2) << 2) + (lane & 7);
                int bcol = ks * 16 + ((g & 1) << 3);
                uint32_t o0 = (uint32_t)(r0 * 72 + bcol) * 2;
                uint32_t o1 = (uint32_t)(r1 * 72 + bcol) * 2;
                uint32_t k0a, k0b, k0c, k0d, k0e, k0f, k0g2, k0h;
                uint32_t k1a, k1b, k1c, k1d, k1e, k1f, k1g2, k1h;
                LDSM4(k0a, k0b, k0c, k0d, sK + 0 * KVTILE + o0);   // K0 @ ntp
                LDSM4(k0e, k0f, k0g2, k0h, sK + 0 * KVTILE + o1);  // K0 @ ntp+1
                LDSM4(k1a, k1b, k1c, k1d, sK + 1 * KVTILE + o0);   // K1 @ ntp
                LDSM4(k1e, k1f, k1g2, k1h, sK + 1 * KVTILE + o1);  // K1 @ ntp+1
                int t0 = 4*np, t1 = 4*np + 2;
                // Q0*K0 (4 MMAs)
                MMA16816(sacc[t0],   qf[0][ks][0],qf[0][ks][1],qf[0][ks][2],qf[0][ks][3], k0a,k0b);
                MMA16816(sacc[t0+1], qf[0][ks][0],qf[0][ks][1],qf[0][ks][2],qf[0][ks][3], k0c,k0d);
                MMA16816(sacc[t1],   qf[0][ks][0],qf[0][ks][1],qf[0][ks][2],qf[0][ks][3], k0e,k0f);
                MMA16816(sacc[t1+1], qf[0][ks][0],qf[0][ks][1],qf[0][ks][2],qf[0][ks][3], k0g2,k0h);
                // Q1*K0 (4 MMAs)
                MMA16816(sacc[t0],   qf[1][ks][0],qf[1][ks][1],qf[1][ks][2],qf[1][ks][3], k0a,k0b);
                MMA16816(sacc[t0+1], qf[1][ks][0],qf[1][ks][1],qf[1][ks][2],qf[1][ks][3], k0c,k0d);
                MMA16816(sacc[t1],   qf[1][ks][0],qf[1][ks][1],qf[1][ks][2],qf[1][ks][3], k0e,k0f);
                MMA16816(sacc[t1+1], qf[1][ks][0],qf[1][ks][1],qf[1][ks][2],qf[1][ks][3], k0g2,k0h);
                // Q0*K1 (4 MMAs)
                MMA16816(sacc[t0],   qf[0][ks][0],qf[0][ks][1],qf[0][ks][2],qf[0][ks][3], k1a,k1b);
                MMA16816(sacc[t0+1], qf[0][ks][0],qf[0][ks][1],qf[0][ks][2],qf[0][ks][3], k1c,k1d);
                MMA16816(sacc[t1],   qf[0][ks][0],qf[0][ks][1],qf[0][ks][2],qf[0][ks][3], k1e,k1f);
                MMA16816(sacc[t1+1], qf[0][ks][0],qf[0][ks][1],qf[0][ks][2],qf[0][ks][3], k1g2,k1h);
            }
        }

        float tm0 = -1e30f, tm1 = -1e30f;
        #pragma unroll
        for (int j = 0; j < 8; j++) {
            tm0 = fmaxf(tm0, fmaxf(sacc[j][0], sacc[j][1]));
            tm1 = fmaxf(tm1, fmaxf(sacc[j][2], sacc[j][3]));
        }
        tm0 = fmaxf(tm0, __shfl_xor_sync(0xffffffffu, tm0, 1));
        tm0 = fmaxf(tm0, __shfl_xor_sync(0xffffffffu, tm0, 2));
        tm1 = fmaxf(tm1, __shfl_xor_sync(0xffffffffu, tm1, 1));
        tm1 = fmaxf(tm1, __shfl_xor_sync(0xffffffffu, tm1, 2));
        tm0 *= 0.125f; tm1 *= 0.125f;
        float mn0 = fmaxf(m0, tm0), mn1 = fmaxf(m1, tm1);
        float al0 = __expf(m0 - mn0), al1 = __expf(m1 - mn1);
        m0 = mn0; m1 = mn1;

        float rs0 = 0.f, rs1 = 0.f;
        uint32_t pf[2][4][4];
        #pragma unroll
        for (int j = 0; j < 8; j++) {
            float p0 = __expf(sacc[j][0] * 0.125f - mn0);
            float p1 = __expf(sacc[j][1] * 0.125f - mn0);
            float p2 = __expf(sacc[j][2] * 0.125f - mn1);
            float p3 = __expf(sacc[j][3] * 0.125f - mn1);
            rs0 += p0 + p1; rs1 += p2 + p3;
            __half a0, a1, b0v, b1v, c0, c1, d0, d1;
            split2r(p0, a0, a1);
            split2r(p1, b0v, b1v);
            split2r(p2, c0, c1);
            split2r(p3, d0, d1);
            int ks = j >> 1, ri = (j & 1) * 2;
            pf[0][ks][ri]     = pkh(a0, b0v);
            pf[0][ks][ri + 1] = pkh(c0, d0);
            pf[1][ks][ri]     = pkh(a1, b1v);
            pf[1][ks][ri + 1] = pkh(c1, d1);
        }
        rs0 += __shfl_xor_sync(0xffffffffu, rs0, 1);
        rs0 += __shfl_xor_sync(0xffffffffu, rs0, 2);
        rs1 += __shfl_xor_sync(0xffffffffu, rs1, 1);
        rs1 += __shfl_xor_sync(0xffffffffu, rs1, 2);
        l0 = l0 * al0 + rs0;
        l1 = l1 * al1 + rs1;
        #pragma unroll
        for (int j = 0; j < 8; j++) {
            pv[j][0] *= al0; pv[j][1] *= al0;
            pv[j][2] *= al1; pv[j][3] *= al1;
        }

        // ---- PV, ntp processed in pairs with product-grouped MMAs ----
        #pragma unroll
        for (int ks = 0; ks < 4; ks++) {
            #pragma unroll
            for (int np = 0; np < 2; np++) {
                int g = lane >> 3;
                int vrow = ks * 16 + ((g & 1) << 3) + (lane & 7);
                int c0p = (2*np) * 16 + ((g >> 1) << 3);
                int c1p = (2*np+1) * 16 + ((g >> 1) << 3);
                uint32_t o0 = (uint32_t)(vrow * 72 + c0p) * 2;
                uint32_t o1 = (uint32_t)(vrow * 72 + c1p) * 2;
                uint32_t v0a, v0b, v0c, v0d, v0e, v0f, v0g2, v0h;
                uint32_t v1a, v1b, v1c, v1d, v1e, v1f, v1g2, v1h;
                LDSM4T(v0a, v0b, v0c, v0d, sV + 0 * KVTILE + o0);   // V0 @ ntp
                LDSM4T(v0e, v0f, v0g2, v0h, sV + 0 * KVTILE + o1);  // V0 @ ntp+1
                LDSM4T(v1a, v1b, v1c, v1d, sV + 1 * KVTILE + o0);   // V1 @ ntp
                LDSM4T(v1e, v1f, v1g2, v1h, sV + 1 * KVTILE + o1);  // V1 @ ntp+1
                int t0 = 4*np, t1 = 4*np + 2;
                // P0*V0 (4 MMAs)
                MMA16816(pv[t0],   pf[0][ks][0],pf[0][ks][1],pf[0][ks][2],pf[0][ks][3], v0a,v0b);
                MMA16816(pv[t0+1], pf[0][ks][0],pf[0][ks][1],pf[0][ks][2],pf[0][ks][3], v0c,v0d);
                MMA16816(pv[t1],   pf[0][ks][0],pf[0][ks][1],pf[0][ks][2],pf[0][ks][3], v0e,v0f);
                MMA16816(pv[t1+1], pf[0][ks][0],pf[0][ks][1],pf[0][ks][2],pf[0][ks][3], v0g2,v0h);
                // P1*V0 (4 MMAs)
                MMA16816(pv[t0],   pf[1][ks][0],pf[1][ks][1],pf[1][ks][2],pf[1][ks][3], v0a,v0b);
                MMA16816(pv[t0+1], pf[1][ks][0],pf[1][ks][1],pf[1][ks][2],pf[1][ks][3], v0c,v0d);
                MMA16816(pv[t1],   pf[1][ks][0],pf[1][ks][1],pf[1][ks][2],pf[1][ks][3], v0e,v0f);
                MMA16816(pv[t1+1], pf[1][ks][0],pf[1][ks][1],pf[1][ks][2],pf[1][ks][3], v0g2,v0h);
                // P0*V1 (4 MMAs)
                MMA16816(pv[t0],   pf[0][ks][0],pf[0][ks][1],pf[0][ks][2],pf[0][ks][3], v1a,v1b);
                MMA16816(pv[t0+1], pf[0][ks][0],pf[0][ks][1],pf[0][ks][2],pf[0][ks][3], v1c,v1d);
                MMA16816(pv[t1],   pf[0][ks][0],pf[0][ks][1],pf[0][ks][2],pf[0][ks][3], v1e,v1f);
                MMA16816(pv[t1+1], pf[0][ks][0],pf[0][ks][1],pf[0][ks][2],pf[0][ks][3], v1g2,v1h);
            }
        }

        __syncthreads();
        if (kt + 2 < LL / 64) KV_LOAD(kt & 1, kt + 2);
        CP_COMMIT();
    }

    float inv0 = 1.f / l0, inv1 = 1.f / l1;
    int gr0 = b * LL + q0 + wid * 16 + (lane >> 2);
    #pragma unroll
    for (int j = 0; j < 8; j++) {
        int col = hh * 64 + j * 8 + ((lane & 3) << 1);
        store_split_pair(Z0, Z1, (size_t)gr0 * CC + col,
                         pv[j][0] * inv0, pv[j][1] * inv0);
        store_split_pair(Z0, Z1, (size_t)(gr0 + 8) * CC + col,
                         pv[j][2] * inv1, pv[j][3] * inv1);
    }
    #undef KV_LOAD
}

// ---------------- block reduce helper ----------------
__device__ __forceinline__ float blockReduceSum256(float v, float* red)
{
    int lane = threadIdx.x & 31, warp = threadIdx.x >> 5;
    #pragma unroll
    for (int o = 16; o; o >>= 1) v += __shfl_xor_sync(0xffffffffu, v, o);
    if (lane == 0) red[warp] = v;
    __syncthreads();
    if (warp == 0) {
        v = (lane < 8) ? red[lane] : 0.f;
        #pragma unroll
        for (int o = 4; o; o >>= 1) v += __shfl_xor_sync(0xffffffffu, v, o);
        if (lane == 0) red[0] = v;
    }
    __syncthreads();
    float r = red[0];
    __syncthreads();
    return r;
}

// ---------------- fused residual add + LayerNorm + router argmax ----------------
__global__ void __launch_bounds__(256)
add_ln_router_kernel(const float* __restrict__ qx, const float* __restrict__ att,
                     const float* __restrict__ w, const float* __restrict__ bb,
                     const float* __restrict__ Wsw, const float* __restrict__ bsw,
                     float* __restrict__ zn, int* __restrict__ route)
{
    __shared__ float red[8];
    __shared__ float esum[8][EE];
    int row = blockIdx.x, tid = threadIdx.x;
    int lane = tid & 31, warp = tid >> 5;
    const float4* xq = (const float4*)(qx  + (size_t)row * CC);
    const float4* aq = (const float4*)(att + (size_t)row * CC);
    float4 x = xq[tid], a = aq[tid];
    float4 v; v.x = x.x + a.x; v.y = x.y + a.y; v.z = x.z + a.z; v.w = x.w + a.w;
    float mean = blockReduceSum256(v.x + v.y + v.z + v.w, red) * (1.f/1024.f);
    float dx = v.x - mean, dy = v.y - mean, dz = v.z - mean, dw = v.w - mean;
    float var = blockReduceSum256(dx*dx + dy*dy + dz*dz + dw*dw, red) * (1.f/1024.f);
    float rs = rsqrtf(var + 1e-5f);
    float4 wv = ((const float4*)w)[tid];
    float4 bv = ((const float4*)bb)[tid];
    float4 o;
    o.x = dx*rs*wv.x + bv.x; o.y = dy*rs*wv.y + bv.y;
    o.z = dz*rs*wv.z + bv.z; o.w = dw*rs*wv.w + bv.w;
    ((float4*)(zn + (size_t)row * CC))[tid] = o;

    int c = tid * 4;
    #pragma unroll
    for (int e = 0; e < EE; e++) {
        float4 we = *(const float4*)(Wsw + (size_t)e * CC + c);
        float p = o.x*we.x + o.y*we.y + o.z*we.z + o.w*we.w;
        #pragma unroll
        for (int of = 16; of; of >>= 1) p += __shfl_xor_sync(0xffffffffu, p, of);
        if (lane == 0) esum[warp][e] = p;
    }
    __syncthreads();
    if (tid == 0) {
        float best = -1e30f; int bi = 0;
        #pragma unroll
        for (int e = 0; e < EE; e++) {
            float lg = esum[0][e] + esum[1][e] + esum[2][e] + esum[3][e]
                     + esum[4][e] + esum[5][e] + esum[6][e] + esum[7][e] + bsw[e];
            if (lg > best) { best = lg; bi = e; }
        }
        route[row] = bi;
    }
}

// ---------------- deterministic per-expert prefix positions ----------------
__global__ void __launch_bounds__(256)
scanpos_kernel(const int* __restrict__ route, int* __restrict__ pos)
{
    int e = blockIdx.x;
    int tid = threadIdx.x;
    int lane = tid & 31, warp = tid >> 5;
    __shared__ int wtot[8];
    __shared__ int running;
    if (tid == 0) running = 0;
    __syncthreads();
    for (int base = 0; base < NTOK; base += 256) {
        int tok = base + tid;
        int flag = (route[tok] == e);
        unsigned m = __ballot_sync(0xffffffffu, flag);
        int rank = __popc(m & ((1u << lane) - 1u));
        if (lane == 31) wtot[warp] = __popc(m);
        __syncthreads();
        int prefix = 0;
        for (int w = 0; w < warp; w++) prefix += wtot[w];
        if (flag) pos[tok] = running + prefix + rank;
        __syncthreads();
        if (tid == 0) {
            int t = 0;
            for (int w = 0; w < 8; w++) t += wtot[w];
            running += t;
        }
        __syncthreads();
    }
}

// ---------------- gather kept tokens into expert buffers ----------------
__global__ void __launch_bounds__(256)
gather_kernel(const float* __restrict__ zn, const int* __restrict__ route,
              const int* __restrict__ pos, float* __restrict__ eb)
{
    int tok = blockIdx.x;
    int p = pos[tok];
    if (p >= CAPP) return;
    size_t slot = (size_t)route[tok] * CAPP + p;
    ((float4*)(eb + slot * CC))[threadIdx.x] =
        ((const float4*)(zn + (size_t)tok * CC))[threadIdx.x];
}

// ---------------- expert FFN layer 1 ----------------
__global__ void __launch_bounds__(256)
ffn1_kernel(const float* __restrict__ eb, const float* __restrict__ W1,
            const float* __restrict__ b1, float* __restrict__ h)
{
    int blk = blockIdx.x;
    int e  = blk >> 6;
    int r0 = (blk & 63) * 4;
    __shared__ float xs[4][CC];
    __shared__ float red[4][4][HIDD];
    int tid = threadIdx.x;
    const float4* src = (const float4*)(eb + ((size_t)e*CAPP + r0) * CC);
    for (int i = tid; i < 4 * (CC/4); i += 256)
        ((float4*)xs)[i] = src[i];
    __syncthreads();
    int kp = tid >> 6;
    int n  = tid & 63;
    float acc[4] = {};
    const float* w = W1 + (size_t)e * CC * HIDD + n;
    #pragma unroll 4
    for (int k = kp; k < CC; k += 4) {
        float wv = w[(size_t)k * HIDD];
        #pragma unroll
        for (int r = 0; r < 4; r++) acc[r] += xs[r][k] * wv;
    }
    #pragma unroll
    for (int r = 0; r < 4; r++) red[kp][r][n] = acc[r];
    __syncthreads();
    {
        int r = tid >> 6, n2 = tid & 63;
        float s = red[0][r][n2] + red[1][r][n2] + red[2][r][n2] + red[3][r][n2]
                + b1[e*HIDD + n2];
        h[((size_t)e*CAPP + r0 + r) * HIDD + n2] = fmaxf(s, 0.f);
    }
}

// ---------------- expert FFN layer 2 ----------------
__global__ void __launch_bounds__(256)
ffn2_kernel(const float* __restrict__ h, const float* __restrict__ W2,
            const float* __restrict__ b2, float* __restrict__ y)
{
    int blk = blockIdx.x;
    int e  = blk >> 6;
    int r0 = (blk & 63) * 4;
    __shared__ float hs[4][HIDD];
    int tid = threadIdx.x;
    hs[tid >> 6][tid & 63] = h[((size_t)e*CAPP + r0 + (tid >> 6)) * HIDD + (tid & 63)];
    __syncthreads();
    int c = tid * 4;
    float4 acc[4];
    #pragma unroll
    for (int r = 0; r < 4; r++) { acc[r].x=0.f; acc[r].y=0.f; acc[r].z=0.f; acc[r].w=0.f; }
    const float* w = W2 + (size_t)e * HIDD * CC + c;
    #pragma unroll 8
    for (int k = 0; k < HIDD; k++) {
        float4 wv = *(const float4*)(w + (size_t)k * CC);
        #pragma unroll
        for (int r = 0; r < 4; r++) {
            float hv = hs[r][k];
            acc[r].x += hv*wv.x; acc[r].y += hv*wv.y;
            acc[r].z += hv*wv.z; acc[r].w += hv*wv.w;
        }
    }
    float4 bb = *(const float4*)(b2 + (size_t)e * CC + c);
    #pragma unroll
    for (int r = 0; r < 4; r++) {
        float4 o;
        o.x = acc[r].x + bb.x; o.y = acc[r].y + bb.y;
        o.z = acc[r].z + bb.z; o.w = acc[r].w + bb.w;
        *(float4*)(y + ((size_t)e*CAPP + r0 + r) * CC + c) = o;
    }
}

// ---------------- final: out = zn + (kept ? y[slot] : zn) ----------------
__global__ void __launch_bounds__(256)
finalize_kernel(const float* __restrict__ zn, const float* __restrict__ y,
                const int* __restrict__ route, const int* __restrict__ pos,
                float* __restrict__ out)
{
    int tok = blockIdx.x, tid = threadIdx.x;
    int p = pos[tok];
    float4 z = ((const float4*)(zn + (size_t)tok * CC))[tid];
    float4 o;
    if (p < CAPP) {
        float4 yv = ((const float4*)(y + ((size_t)route[tok]*CAPP + p) * CC))[tid];
        o.x = z.x + yv.x; o.y = z.y + yv.y; o.z = z.z + yv.z; o.w = z.w + yv.w;
    } else {
        o.x = 2.f*z.x; o.y = 2.f*z.y; o.z = 2.f*z.z; o.w = 2.f*z.w;
    }
    ((float4*)(out + (size_t)tok * CC))[tid] = o;
}

__global__ void fill_ones_kernel(float* __restrict__ p, int n)
{
    int i = blockIdx.x * 256 + threadIdx.x;
    if (i < n) p[i] = 1.0f;
}

// ---------------- launch ----------------
extern "C" void kernel_launch(void* const* d_in, const int* in_sizes, int n_in,
                              void* d_out, int out_size)
{
    const float* qx  = (const float*)d_in[0];
    const float* kx  = (const float*)d_in[1];
    const float* vx  = (const float*)d_in[2];
    const float* WQ  = (const float*)d_in[4];
    const float* bQ  = (const float*)d_in[5];
    const float* WK  = (const float*)d_in[6];
    const float* bK  = (const float*)d_in[7];
    const float* WV  = (const float*)d_in[8];
    const float* bV  = (const float*)d_in[9];
    const float* WO  = (const float*)d_in[10];
    const float* bO  = (const float*)d_in[11];
    const float* ln1w= (const float*)d_in[12];
    const float* ln1b= (const float*)d_in[13];
    const float* Wsw = (const float*)d_in[14];
    const float* bsw = (const float*)d_in[15];
    const float* W1  = (const float*)d_in[16];
    const float* b1  = (const float*)d_in[17];
    const float* W2  = (const float*)d_in[18];
    const float* b2  = (const float*)d_in[19];
    float* out = (float*)d_out;

    float *pA, *pzn, *peb, *ph, *py;
    int *proute, *ppos;
    cudaGetSymbolAddress((void**)&pA,  g_A);
    cudaGetSymbolAddress((void**)&pzn, g_zn);
    cudaGetSymbolAddress((void**)&peb, g_eb);
    cudaGetSymbolAddress((void**)&ph,  g_h);
    cudaGetSymbolAddress((void**)&py,  g_y);
    cudaGetSymbolAddress((void**)&proute, g_route);
    cudaGetSymbolAddress((void**)&ppos,   g_pos);

    __half *xq[2], *xk[2], *xv[2];
    __half *wq[2], *wk[2], *wv[2], *wo[2];
    __half *oq[2], *ok[2], *ov[2];
    cudaGetSymbolAddress((void**)&xq[0], g_xq0); cudaGetSymbolAddress((void**)&xq[1], g_xq1);
    cudaGetSymbolAddress((void**)&xk[0], g_xk0); cudaGetSymbolAddress((void**)&xk[1], g_xk1);
    cudaGetSymbolAddress((void**)&xv[0], g_xv0); cudaGetSymbolAddress((void**)&xv[1], g_xv1);
    cudaGetSymbolAddress((void**)&wq[0], g_wq0); cudaGetSymbolAddress((void**)&wq[1], g_wq1);
    cudaGetSymbolAddress((void**)&wk[0], g_wk0); cudaGetSymbolAddress((void**)&wk[1], g_wk1);
    cudaGetSymbolAddress((void**)&wv[0], g_wv0); cudaGetSymbolAddress((void**)&wv[1], g_wv1);
    cudaGetSymbolAddress((void**)&wo[0], g_wo0); cudaGetSymbolAddress((void**)&wo[1], g_wo1);
    cudaGetSymbolAddress((void**)&oq[0], g_q0);  cudaGetSymbolAddress((void**)&oq[1], g_q1);
    cudaGetSymbolAddress((void**)&ok[0], g_k0);  cudaGetSymbolAddress((void**)&ok[1], g_k1);
    cudaGetSymbolAddress((void**)&ov[0], g_v0);  cudaGetSymbolAddress((void**)&ov[1], g_v1);

    cudaFuncSetAttribute(mma_gemm,   cudaFuncAttributeMaxDynamicSharedMemorySize, GEMM_SMEM);
    cudaFuncSetAttribute(mma_gemm_s, cudaFuncAttributeMaxDynamicSharedMemorySize, GEMM_SMEM);
    cudaFuncSetAttribute(attn_mma,   cudaFuncAttributeMaxDynamicSharedMemorySize, ATTN_SMEM);

    const int NX4 = NTOK * CC / 4;
    const int NW4 = CC * CC / 4;
    dim3 gemmGrid(CC/128, NTOK/128);

    split2_kernel<<<NX4/256, 256>>>(qx, xq[0], xq[1], NX4);
    split2_kernel<<<NW4/256, 256>>>(WQ, wq[0], wq[1], NW4);
    split2_kernel<<<NX4/256, 256>>>(kx, xk[0], xk[1], NX4);
    split2_kernel<<<NW4/256, 256>>>(WK, wk[0], wk[1], NW4);
    split2_kernel<<<NX4/256, 256>>>(vx, xv[0], xv[1], NX4);

    mma_gemm_s<<<gemmGrid, 256, GEMM_SMEM>>>(
        xq[0], xq[1], wq[0], wq[1], bQ, oq[0], oq[1]);

    split2_kernel<<<NW4/256, 256>>>(WV, wv[0], wv[1], NW4);
    mma_gemm_s<<<gemmGrid, 256, GEMM_SMEM>>>(
        xk[0], xk[1], wk[0], wk[1], bK, ok[0], ok[1]);
    mma_gemm_s<<<gemmGrid, 256, GEMM_SMEM>>>(
        xv[0], xv[1], wv[0], wv[1], bV, ov[0], ov[1]);

    split2_kernel<<<NW4/256, 256>>>(WO, wo[0], wo[1], NW4);

    attn_mma<<<dim3(LL/128, BB*HH), 256, ATTN_SMEM>>>(
        oq[0], oq[1], ok[0], ok[1], ov[0], ov[1], xq[0], xq[1]);

    mma_gemm<<<gemmGrid, 256, GEMM_SMEM>>>(
        xq[0], xq[1], wo[0], wo[1], bO, pA);

    add_ln_router_kernel<<<NTOK, 256>>>(qx, pA, ln1w, ln1b, Wsw, bsw, pzn, proute);
    scanpos_kernel<<<EE, 256>>>(proute, ppos);
    gather_kernel<<<NTOK, 256>>>(pzn, proute, ppos, peb);
    ffn1_kernel<<<EE * (CAPP/4), 256>>>(peb, W1, b1, ph);
    ffn2_kernel<<<EE * (CAPP/4), 256>>>(ph, W2, b2, py);
    finalize_kernel<<<NTOK, 256>>>(pzn, py, proute, ppos, out);

    long long os = (long long)out_size;
    if (os >= (long long)(2 * NCE)) {
        cudaMemcpyAsync(out + NCE, kx, NCE * sizeof(float),
                        cudaMemcpyDeviceToDevice, 0);
    }
    if (os >= (long long)(3 * NCE)) {
        cudaMemcpyAsync(out + 2 * NCE, vx, NCE * sizeof(float),
                        cudaMemcpyDeviceToDevice, 0);
    }
    long long rem = os - (long long)(3 * NCE);
    if (rem > 0) {
        fill_ones_kernel<<<(int)((rem + 255) / 256), 256>>>(out + 3 * NCE, (int)rem);
    }
}

// round 12
// speedup vs baseline: 1.5205x; 1.5205x over previous
#include <cuda_runtime.h>
#include <cuda_fp16.h>
#include <math.h>
#include <stdint.h>

// ---------------- problem constants ----------------
#define BB 8
#define LL 1024
#define CC 1024
#define HH 16
#define DKK 64
#define NTOK (BB*LL)            // 8192
#define EE 16
#define HIDD 64
#define CAPP 256
#define NCE ((size_t)NTOK * CC)

// ---------------- baseline-PTX tensor-core helpers (sm_80+) ----------------
__device__ __forceinline__ uint32_t smem_u32(const void* p) {
    uint32_t a;
    asm("{ .reg .u64 t; cvta.to.shared.u64 t, %1; cvt.u32.u64 %0, t; }" : "=r"(a) : "l"(p));
    return a;
}
#define LDSM4(d0, d1, d2, d3, a) \
    asm volatile("ldmatrix.sync.aligned.m8n8.x4.shared.b16 {%0,%1,%2,%3}, [%4];" \
        : "=r"(d0), "=r"(d1), "=r"(d2), "=r"(d3) : "r"(a))
#define LDSM4T(d0, d1, d2, d3, a) \
    asm volatile("ldmatrix.sync.aligned.m8n8.x4.trans.shared.b16 {%0,%1,%2,%3}, [%4];" \
        : "=r"(d0), "=r"(d1), "=r"(d2), "=r"(d3) : "r"(a))
#define MMA16816(c, a0, a1, a2, a3, b0, b1) \
    asm volatile("mma.sync.aligned.m16n8k16.row.col.f32.f16.f16.f32 " \
        "{%0,%1,%2,%3}, {%4,%5,%6,%7}, {%8,%9}, {%0,%1,%2,%3};" \
        : "+f"((c)[0]), "+f"((c)[1]), "+f"((c)[2]), "+f"((c)[3]) \
        : "r"(a0), "r"(a1), "r"(a2), "r"(a3), "r"(b0), "r"(b1))
#define CP_ASYNC16(dst, src) \
    asm volatile("cp.async.cg.shared.global [%0], [%1], 16;" :: "r"(dst), "l"(src))
#define CP_COMMIT() asm volatile("cp.async.commit_group;" ::: "memory")
#define CP_WAIT1()  asm volatile("cp.async.wait_group 1;" ::: "memory")

// ---------------- fp16 2-term split helpers ----------------
__device__ __forceinline__ void split2r(float a, __half& h0, __half& h1)
{
    h0 = __float2half_rn(a);
    h1 = __float2half_rn(a - __half2float(h0));
}
__device__ __forceinline__ uint32_t pkh(__half lo, __half hi)
{
    __half2 t = __halves2half2(lo, hi);
    return *reinterpret_cast<uint32_t*>(&t);
}
__device__ __forceinline__ void store_split_pair(
    __half* Y0, __half* Y1, size_t off, float e0, float e1)
{
    __half a0, a1, b0, b1;
    split2r(e0, a0, a1);
    split2r(e1, b0, b1);
    *(uint32_t*)(Y0 + off) = pkh(a0, b0);
    *(uint32_t*)(Y1 + off) = pkh(a1, b1);
}

// ---------------- scratch ----------------
__device__ float g_A [NTOK * CC];
__device__ float g_zn[NTOK * CC];
__device__ float g_eb[EE * CAPP * CC];
__device__ float g_h [EE * CAPP * HIDD];
__device__ int   g_route[NTOK];
__device__ int   g_pos  [NTOK];
__device__ int   g_slot2tok[EE * CAPP];
__device__ __half g_xq0[NTOK*CC], g_xq1[NTOK*CC];
__device__ __half g_xk0[NTOK*CC], g_xk1[NTOK*CC];
__device__ __half g_xv0[NTOK*CC], g_xv1[NTOK*CC];
__device__ __half g_wq0[CC*CC], g_wq1[CC*CC];
__device__ __half g_wk0[CC*CC], g_wk1[CC*CC];
__device__ __half g_wv0[CC*CC], g_wv1[CC*CC];
__device__ __half g_wo0[CC*CC], g_wo1[CC*CC];
__device__ __half g_q0[NTOK*CC], g_q1[NTOK*CC];
__device__ __half g_k0[NTOK*CC], g_k1[NTOK*CC];
__device__ __half g_v0[NTOK*CC], g_v1[NTOK*CC];

// ---------------- fp32 -> 2x fp16 split ----------------
__global__ void __launch_bounds__(256)
split2_kernel(const float* __restrict__ in, __half* __restrict__ o0,
              __half* __restrict__ o1, int n4)
{
    int i = blockIdx.x * 256 + threadIdx.x;
    if (i >= n4) return;
    float4 v = ((const float4*)in)[i];
    float a[4] = {v.x, v.y, v.z, v.w};
    union { __half b[4]; uint2 u; } s0, s1;
    #pragma unroll
    for (int j = 0; j < 4; j++) split2r(a[j], s0.b[j], s1.b[j]);
    ((uint2*)o0)[i] = s0.u;
    ((uint2*)o1)[i] = s1.u;
}

// ---------------- HMMA GEMM core (fp16x3), 2-stage, 2 CTAs/SM (R10) -----------
#define APAD 40
#define TILE_B (128 * APAD * 2)     // 10240
#define STAGE4 (4 * TILE_B)         // 40960
#define GEMM_SMEM (2 * STAGE4)      // 81920
#define NCHUNK 32

template <int OutMode>
__device__ __forceinline__ void gemm_core(
    const __half* __restrict__ X0, const __half* __restrict__ X1,
    const __half* __restrict__ W0, const __half* __restrict__ W1,
    const float* __restrict__ bias,
    float* __restrict__ Yf,
    __half* __restrict__ Y0, __half* __restrict__ Y1,
    char* smem)
{
    const uint32_t sb = smem_u32(smem);
    const int tid = threadIdx.x, wid = tid >> 5, lane = tid & 31;
    const int bm = blockIdx.y * 128, bn = blockIdx.x * 128;
    const int wm = (wid >> 2) * 64, wn = (wid & 3) * 32;

    const __half* TS[4] = {X0, X1, W0, W1};

    #define G_LOAD(buf, ch) do { \
        int ko_ = (ch) * 32; \
        _Pragma("unroll") \
        for (int j_ = 0; j_ < 8; j_++) { \
            int e_ = j_ * 256 + tid; \
            int t_ = e_ >> 9; \
            int w_ = e_ & 511; \
            int r_ = w_ >> 2, c8_ = (w_ & 3) * 8; \
            int rowb_ = ((t_ < 2) ? bm : bn) + r_; \
            CP_ASYNC16(sb + (buf) * STAGE4 + t_ * TILE_B + (r_ * APAD + c8_) * 2, \
                       TS[t_] + (size_t)rowb_ * CC + ko_ + c8_); \
        } \
    } while (0)

    float acc[4][4][4];
    #pragma unroll
    for (int i = 0; i < 4; i++)
        #pragma unroll
        for (int j = 0; j < 4; j++)
            #pragma unroll
            for (int q = 0; q < 4; q++) acc[i][j][q] = 0.f;

    G_LOAD(0, 0); CP_COMMIT();
    G_LOAD(1, 1); CP_COMMIT();

    for (int c = 0; c < NCHUNK; c++) {
        int buf = c & 1;
        CP_WAIT1();
        __syncthreads();

        uint32_t stage = sb + buf * STAGE4;
        #pragma unroll
        for (int kk = 0; kk < 2; kk++) {
            uint32_t a[2][4][4];
            #pragma unroll
            for (int s = 0; s < 2; s++)
                #pragma unroll
                for (int i = 0; i < 4; i++) {
                    int arow = wm + i * 16 + (lane & 15);
                    int acol = kk * 16 + ((lane >> 4) << 3);
                    LDSM4(a[s][i][0], a[s][i][1], a[s][i][2], a[s][i][3],
                          stage + s * TILE_B + (uint32_t)(arow * APAD + acol) * 2);
                }
            #pragma unroll
            for (int jp = 0; jp < 2; jp++) {
                int g = lane >> 3;
                int brow = wn + jp * 16 + ((g & 2) << 2) + (lane & 7);
                int bcol = kk * 16 + ((g & 1) << 3);
                uint32_t boff = (uint32_t)(brow * APAD + bcol) * 2;
                uint32_t b0, b1, b2, b3;
                LDSM4(b0, b1, b2, b3, stage + 2 * TILE_B + boff);
                #pragma unroll
                for (int i = 0; i < 4; i++) {
                    MMA16816(acc[i][2*jp],   a[0][i][0],a[0][i][1],a[0][i][2],a[0][i][3], b0,b1);
                    MMA16816(acc[i][2*jp+1], a[0][i][0],a[0][i][1],a[0][i][2],a[0][i][3], b2,b3);
                    MMA16816(acc[i][2*jp],   a[1][i][0],a[1][i][1],a[1][i][2],a[1][i][3], b0,b1);
                    MMA16816(acc[i][2*jp+1], a[1][i][0],a[1][i][1],a[1][i][2],a[1][i][3], b2,b3);
                }
                LDSM4(b0, b1, b2, b3, stage + 3 * TILE_B + boff);
                #pragma unroll
                for (int i = 0; i < 4; i++) {
                    MMA16816(acc[i][2*jp],   a[0][i][0],a[0][i][1],a[0][i][2],a[0][i][3], b0,b1);
                    MMA16816(acc[i][2*jp+1], a[0][i][0],a[0][i][1],a[0][i][2],a[0][i][3], b2,b3);
                }
            }
        }
        __syncthreads();
        if (c + 2 < NCHUNK) {
            G_LOAD(buf, c + 2);
        }
        CP_COMMIT();
    }

    #pragma unroll
    for (int i = 0; i < 4; i++) {
        int row = bm + wm + i * 16 + (lane >> 2);
        #pragma unroll
        for (int j = 0; j < 4; j++) {
            int col = bn + wn + j * 8 + ((lane & 3) << 1);
            float bx = bias[col], by = bias[col + 1];
            float e0 = acc[i][j][0] + bx, e1 = acc[i][j][1] + by;
            float e2 = acc[i][j][2] + bx, e3 = acc[i][j][3] + by;
            if (OutMode == 0) {
                float2 v0 = {e0, e1};
                float2 v1 = {e2, e3};
                *(float2*)(Yf + (size_t)row * CC + col) = v0;
                *(float2*)(Yf + (size_t)(row + 8) * CC + col) = v1;
            } else {
                store_split_pair(Y0, Y1, (size_t)row * CC + col, e0, e1);
                store_split_pair(Y0, Y1, (size_t)(row + 8) * CC + col, e2, e3);
            }
        }
    }
    #undef G_LOAD
}

__global__ void __launch_bounds__(256, 2)
mma_gemm(const __half* __restrict__ X0, const __half* __restrict__ X1,
         const __half* __restrict__ W0, const __half* __restrict__ W1,
         const float* __restrict__ bias, float* __restrict__ Y)
{
    extern __shared__ char smem[];
    gemm_core<0>(X0, X1, W0, W1, bias, Y, nullptr, nullptr, smem);
}

__global__ void __launch_bounds__(256, 2)
mma_gemm_s(const __half* __restrict__ X0, const __half* __restrict__ X1,
           const __half* __restrict__ W0, const __half* __restrict__ W1,
           const float* __restrict__ bias,
           __half* __restrict__ Y0, __half* __restrict__ Y1)
{
    extern __shared__ char smem[];
    gemm_core<1>(X0, X1, W0, W1, bias, nullptr, Y0, Y1, smem);
}

// ---------------- flash attention on HMMA (fp16x3, R10-verbatim) -------------
#define QTILE (128 * 72 * 2)      // 18432
#define KVTILE (64 * 72 * 2)      // 9216
#define AT_SOFF (2 * QTILE)       // 36864
#define AT_STG (4 * KVTILE)       // 36864
#define ATTN_SMEM (AT_SOFF + 2 * AT_STG)   // 110592

__global__ void __launch_bounds__(256)
attn_mma(const __half* __restrict__ Q0, const __half* __restrict__ Q1,
         const __half* __restrict__ K0, const __half* __restrict__ K1,
         const __half* __restrict__ V0, const __half* __restrict__ V1,
         __half* __restrict__ Z0, __half* __restrict__ Z1)
{
    extern __shared__ char smem[];
    const uint32_t sb = smem_u32(smem);
    const int tid = threadIdx.x, wid = tid >> 5, lane = tid & 31;
    const int bh = blockIdx.y;
    const int b = bh >> 4, hh = bh & 15;
    const int q0 = blockIdx.x * 128;

    const __half* QS[2] = {Q0, Q1};
    const __half* KS[2] = {K0, K1};
    const __half* VS[2] = {V0, V1};

    #pragma unroll
    for (int j = 0; j < 8; j++) {
        int e = j * 256 + tid;
        int t = e >> 10;
        int w = e & 1023;
        int r = w >> 3, c = w & 7;
        CP_ASYNC16(sb + t * QTILE + (uint32_t)(r * 72 + c * 8) * 2,
                   QS[t] + (size_t)(b * LL + q0 + r) * CC + hh * 64 + c * 8);
    }

    #define KV_LOAD(buf, kt) do { \
        _Pragma("unroll") \
        for (int j_ = 0; j_ < 8; j_++) { \
            int e_ = j_ * 256 + tid; \
            int t_ = e_ >> 9; \
            int w_ = e_ & 511; \
            int r_ = w_ >> 3, c_ = w_ & 7; \
            const __half* src_ = (t_ < 2) ? KS[t_] : VS[t_ - 2]; \
            CP_ASYNC16(sb + AT_SOFF + (buf) * AT_STG + t_ * KVTILE + \
                       (uint32_t)(r_ * 72 + c_ * 8) * 2, \
                       src_ + (size_t)(b * LL + (kt) * 64 + r_) * CC + hh * 64 + c_ * 8); \
        } \
    } while (0)

    KV_LOAD(0, 0); CP_COMMIT();
    KV_LOAD(1, 1); CP_COMMIT();

    float pv[8][4];
    #pragma unroll
    for (int j = 0; j < 8; j++)
        #pragma unroll
        for (int q = 0; q < 4; q++) pv[j][q] = 0.f;
    float m0 = -1e30f, m1 = -1e30f, l0 = 0.f, l1 = 0.f;
    uint32_t qf[2][4][4];

    for (int kt = 0; kt < LL / 64; kt++) {
        CP_WAIT1();
        __syncthreads();
        if (kt == 0) {
            #pragma unroll
            for (int s = 0; s < 2; s++)
                #pragma unroll
                for (int ks = 0; ks < 4; ks++) {
                    int arow = wid * 16 + (lane & 15);
                    int acol = ks * 16 + ((lane >> 4) << 3);
                    LDSM4(qf[s][ks][0], qf[s][ks][1], qf[s][ks][2], qf[s][ks][3],
                          sb + s * QTILE + (uint32_t)(arow * 72 + acol) * 2);
                }
        }

        uint32_t sK = sb + AT_SOFF + (kt & 1) * AT_STG;
        uint32_t sV = sK + 2 * KVTILE;

        float sacc[8][4];
        #pragma unroll
        for (int j = 0; j < 8; j++)
            #pragma unroll
            for (int q = 0; q < 4; q++) sacc[j][q] = 0.f;

        #pragma unroll
        for (int ks = 0; ks < 4; ks++) {
            #pragma unroll
            for (int ntp = 0; ntp < 4; ntp++) {
                int g = lane >> 3;
                int brow = ntp * 16 + ((g & 2) << 2) + (lane & 7);
                int bcol = ks * 16 + ((g & 1) << 3);
                uint32_t boff = (uint32_t)(brow * 72 + bcol) * 2;
                uint32_t b0, b1, b2, b3;
                LDSM4(b0, b1, b2, b3, sK + 0 * KVTILE + boff);
                MMA16816(sacc[2*ntp],   qf[0][ks][0],qf[0][ks][1],qf[0][ks][2],qf[0][ks][3], b0,b1);
                MMA16816(sacc[2*ntp+1], qf[0][ks][0],qf[0][ks][1],qf[0][ks][2],qf[0][ks][3], b2,b3);
                MMA16816(sacc[2*ntp],   qf[1][ks][0],qf[1][ks][1],qf[1][ks][2],qf[1][ks][3], b0,b1);
                MMA16816(sacc[2*ntp+1], qf[1][ks][0],qf[1][ks][1],qf[1][ks][2],qf[1][ks][3], b2,b3);
                LDSM4(b0, b1, b2, b3, sK + 1 * KVTILE + boff);
                MMA16816(sacc[2*ntp],   qf[0][ks][0],qf[0][ks][1],qf[0][ks][2],qf[0][ks][3], b0,b1);
                MMA16816(sacc[2*ntp+1], qf[0][ks][0],qf[0][ks][1],qf[0][ks][2],qf[0][ks][3], b2,b3);
            }
        }

        float tm0 = -1e30f, tm1 = -1e30f;
        #pragma unroll
        for (int j = 0; j < 8; j++) {
            tm0 = fmaxf(tm0, fmaxf(sacc[j][0], sacc[j][1]));
            tm1 = fmaxf(tm1, fmaxf(sacc[j][2], sacc[j][3]));
        }
        tm0 = fmaxf(tm0, __shfl_xor_sync(0xffffffffu, tm0, 1));
        tm0 = fmaxf(tm0, __shfl_xor_sync(0xffffffffu, tm0, 2));
        tm1 = fmaxf(tm1, __shfl_xor_sync(0xffffffffu, tm1, 1));
        tm1 = fmaxf(tm1, __shfl_xor_sync(0xffffffffu, tm1, 2));
        tm0 *= 0.125f; tm1 *= 0.125f;
        float mn0 = fmaxf(m0, tm0), mn1 = fmaxf(m1, tm1);
        float al0 = __expf(m0 - mn0), al1 = __expf(m1 - mn1);
        m0 = mn0; m1 = mn1;

        float rs0 = 0.f, rs1 = 0.f;
        uint32_t pf[2][4][4];
        #pragma unroll
        for (int j = 0; j < 8; j++) {
            float p0 = __expf(sacc[j][0] * 0.125f - mn0);
            float p1 = __expf(sacc[j][1] * 0.125f - mn0);
            float p2 = __expf(sacc[j][2] * 0.125f - mn1);
            float p3 = __expf(sacc[j][3] * 0.125f - mn1);
            rs0 += p0 + p1; rs1 += p2 + p3;
            __half a0, a1, b0v, b1v, c0, c1, d0, d1;
            split2r(p0, a0, a1);
            split2r(p1, b0v, b1v);
            split2r(p2, c0, c1);
            split2r(p3, d0, d1);
            int ks = j >> 1, ri = (j & 1) * 2;
            pf[0][ks][ri]     = pkh(a0, b0v);
            pf[0][ks][ri + 1] = pkh(c0, d0);
            pf[1][ks][ri]     = pkh(a1, b1v);
            pf[1][ks][ri + 1] = pkh(c1, d1);
        }
        rs0 += __shfl_xor_sync(0xffffffffu, rs0, 1);
        rs0 += __shfl_xor_sync(0xffffffffu, rs0, 2);
        rs1 += __shfl_xor_sync(0xffffffffu, rs1, 1);
        rs1 += __shfl_xor_sync(0xffffffffu, rs1, 2);
        l0 = l0 * al0 + rs0;
        l1 = l1 * al1 + rs1;
        #pragma unroll
        for (int j = 0; j < 8; j++) {
            pv[j][0] *= al0; pv[j][1] *= al0;
            pv[j][2] *= al1; pv[j][3] *= al1;
        }

        #pragma unroll
        for (int ks = 0; ks < 4; ks++) {
            #pragma unroll
            for (int ntp = 0; ntp < 4; ntp++) {
                int g = lane >> 3;
                int vrow = ks * 16 + ((g & 1) << 3) + (lane & 7);
                int vcol = ntp * 16 + ((g >> 1) << 3);
                uint32_t voff = (uint32_t)(vrow * 72 + vcol) * 2;
                uint32_t v0, v1, v2, v3;
                LDSM4T(v0, v1, v2, v3, sV + 0 * KVTILE + voff);
                MMA16816(pv[2*ntp],   pf[0][ks][0],pf[0][ks][1],pf[0][ks][2],pf[0][ks][3], v0,v1);
                MMA16816(pv[2*ntp+1], pf[0][ks][0],pf[0][ks][1],pf[0][ks][2],pf[0][ks][3], v2,v3);
                MMA16816(pv[2*ntp],   pf[1][ks][0],pf[1][ks][1],pf[1][ks][2],pf[1][ks][3], v0,v1);
                MMA16816(pv[2*ntp+1], pf[1][ks][0],pf[1][ks][1],pf[1][ks][2],pf[1][ks][3], v2,v3);
                LDSM4T(v0, v1, v2, v3, sV + 1 * KVTILE + voff);
                MMA16816(pv[2*ntp],   pf[0][ks][0],pf[0][ks][1],pf[0][ks][2],pf[0][ks][3], v0,v1);
                MMA16816(pv[2*ntp+1], pf[0][ks][0],pf[0][ks][1],pf[0][ks][2],pf[0][ks][3], v2,v3);
            }
        }

        __syncthreads();
        if (kt + 2 < LL / 64) KV_LOAD(kt & 1, kt + 2);
        CP_COMMIT();
    }

    float inv0 = 1.f / l0, inv1 = 1.f / l1;
    int gr0 = b * LL + q0 + wid * 16 + (lane >> 2);
    #pragma unroll
    for (int j = 0; j < 8; j++) {
        int col = hh * 64 + j * 8 + ((lane & 3) << 1);
        store_split_pair(Z0, Z1, (size_t)gr0 * CC + col,
                         pv[j][0] * inv0, pv[j][1] * inv0);
        store_split_pair(Z0, Z1, (size_t)(gr0 + 8) * CC + col,
                         pv[j][2] * inv1, pv[j][3] * inv1);
    }
    #undef KV_LOAD
}

// ---------------- block reduce helper ----------------
__device__ __forceinline__ float blockReduceSum256(float v, float* red)
{
    int lane = threadIdx.x & 31, warp = threadIdx.x >> 5;
    #pragma unroll
    for (int o = 16; o; o >>= 1) v += __shfl_xor_sync(0xffffffffu, v, o);
    if (lane == 0) red[warp] = v;
    __syncthreads();
    if (warp == 0) {
        v = (lane < 8) ? red[lane] : 0.f;
        #pragma unroll
        for (int o = 4; o; o >>= 1) v += __shfl_xor_sync(0xffffffffu, v, o);
        if (lane == 0) red[0] = v;
    }
    __syncthreads();
    float r = red[0];
    __syncthreads();
    return r;
}

// ---------------- fused residual add + LayerNorm + router argmax ----------------
__global__ void __launch_bounds__(256)
add_ln_router_kernel(const float* __restrict__ qx, const float* __restrict__ att,
                     const float* __restrict__ w, const float* __restrict__ bb,
                     const float* __restrict__ Wsw, const float* __restrict__ bsw,
                     float* __restrict__ zn, int* __restrict__ route)
{
    __shared__ float red[8];
    __shared__ float esum[8][EE];
    int row = blockIdx.x, tid = threadIdx.x;
    int lane = tid & 31, warp = tid >> 5;
    const float4* xq = (const float4*)(qx  + (size_t)row * CC);
    const float4* aq = (const float4*)(att + (size_t)row * CC);
    float4 x = xq[tid], a = aq[tid];
    float4 v; v.x = x.x + a.x; v.y = x.y + a.y; v.z = x.z + a.z; v.w = x.w + a.w;
    float mean = blockReduceSum256(v.x + v.y + v.z + v.w, red) * (1.f/1024.f);
    float dx = v.x - mean, dy = v.y - mean, dz = v.z - mean, dw = v.w - mean;
    float var = blockReduceSum256(dx*dx + dy*dy + dz*dz + dw*dw, red) * (1.f/1024.f);
    float rs = rsqrtf(var + 1e-5f);
    float4 wv = ((const float4*)w)[tid];
    float4 bv = ((const float4*)bb)[tid];
    float4 o;
    o.x = dx*rs*wv.x + bv.x; o.y = dy*rs*wv.y + bv.y;
    o.z = dz*rs*wv.z + bv.z; o.w = dw*rs*wv.w + bv.w;
    ((float4*)(zn + (size_t)row * CC))[tid] = o;

    int c = tid * 4;
    #pragma unroll
    for (int e = 0; e < EE; e++) {
        float4 we = *(const float4*)(Wsw + (size_t)e * CC + c);
        float p = o.x*we.x + o.y*we.y + o.z*we.z + o.w*we.w;
        #pragma unroll
        for (int of = 16; of; of >>= 1) p += __shfl_xor_sync(0xffffffffu, p, of);
        if (lane == 0) esum[warp][e] = p;
    }
    __syncthreads();
    if (tid == 0) {
        float best = -1e30f; int bi = 0;
        #pragma unroll
        for (int e = 0; e < EE; e++) {
            float lg = esum[0][e] + esum[1][e] + esum[2][e] + esum[3][e]
                     + esum[4][e] + esum[5][e] + esum[6][e] + esum[7][e] + bsw[e];
            if (lg > best) { best = lg; bi = e; }
        }
        route[row] = bi;
    }
}

// ---------------- deterministic per-expert prefix positions + inverse map ----
__global__ void __launch_bounds__(256)
scanpos_kernel(const int* __restrict__ route, int* __restrict__ pos,
               int* __restrict__ slot2tok)
{
    int e = blockIdx.x;
    int tid = threadIdx.x;
    int lane = tid & 31, warp = tid >> 5;
    __shared__ int wtot[8];
    __shared__ int running;
    if (tid == 0) running = 0;
    if (tid < CAPP) {
        // init this expert's slot map (CAPP == 256 == blockDim)
        slot2tok[e * CAPP + tid] = -1;
    }
    __syncthreads();
    for (int base = 0; base < NTOK; base += 256) {
        int tok = base + tid;
        int flag = (route[tok] == e);
        unsigned m = __ballot_sync(0xffffffffu, flag);
        int rank = __popc(m & ((1u << lane) - 1u));
        if (lane == 31) wtot[warp] = __popc(m);
        __syncthreads();
        int prefix = 0;
        for (int w = 0; w < warp; w++) prefix += wtot[w];
        if (flag) {
            int p = running + prefix + rank;
            pos[tok] = p;
            if (p < CAPP) slot2tok[e * CAPP + p] = tok;
        }
        __syncthreads();
        if (tid == 0) {
            int t = 0;
            for (int w = 0; w < 8; w++) t += wtot[w];
            running += t;
        }
        __syncthreads();
    }
}

// ---------------- gather kept tokens into expert buffers ----------------
__global__ void __launch_bounds__(256)
gather_kernel(const float* __restrict__ zn, const int* __restrict__ route,
              const int* __restrict__ pos, float* __restrict__ eb)
{
    int tok = blockIdx.x;
    int p = pos[tok];
    if (p >= CAPP) return;
    size_t slot = (size_t)route[tok] * CAPP + p;
    ((float4*)(eb + slot * CC))[threadIdx.x] =
        ((const float4*)(zn + (size_t)tok * CC))[threadIdx.x];
}

// ---------------- expert FFN layer 1 ----------------
__global__ void __launch_bounds__(256)
ffn1_kernel(const float* __restrict__ eb, const float* __restrict__ W1,
            const float* __restrict__ b1, float* __restrict__ h)
{
    int blk = blockIdx.x;
    int e  = blk >> 6;
    int r0 = (blk & 63) * 4;
    __shared__ float xs[4][CC];
    __shared__ float red[4][4][HIDD];
    int tid = threadIdx.x;
    const float4* src = (const float4*)(eb + ((size_t)e*CAPP + r0) * CC);
    for (int i = tid; i < 4 * (CC/4); i += 256)
        ((float4*)xs)[i] = src[i];
    __syncthreads();
    int kp = tid >> 6;
    int n  = tid & 63;
    float acc[4] = {};
    const float* w = W1 + (size_t)e * CC * HIDD + n;
    #pragma unroll 4
    for (int k = kp; k < CC; k += 4) {
        float wv = w[(size_t)k * HIDD];
        #pragma unroll
        for (int r = 0; r < 4; r++) acc[r] += xs[r][k] * wv;
    }
    #pragma unroll
    for (int r = 0; r < 4; r++) red[kp][r][n] = acc[r];
    __syncthreads();
    {
        int r = tid >> 6, n2 = tid & 63;
        float s = red[0][r][n2] + red[1][r][n2] + red[2][r][n2] + red[3][r][n2]
                + b1[e*HIDD + n2];
        h[((size_t)e*CAPP + r0 + r) * HIDD + n2] = fmaxf(s, 0.f);
    }
}

// ---------------- expert FFN layer 2 fused with finalize (kept tokens) -------
__global__ void __launch_bounds__(256)
ffn2_out_kernel(const float* __restrict__ h, const float* __restrict__ W2,
                const float* __restrict__ b2, const int* __restrict__ slot2tok,
                const float* __restrict__ zn, float* __restrict__ out)
{
    int blk = blockIdx.x;
    int e  = blk >> 6;
    int r0 = (blk & 63) * 4;
    __shared__ float hs[4][HIDD];
    __shared__ int toks[4];
    int tid = threadIdx.x;
    hs[tid >> 6][tid & 63] = h[((size_t)e*CAPP + r0 + (tid >> 6)) * HIDD + (tid & 63)];
    if (tid < 4) toks[tid] = slot2tok[e * CAPP + r0 + tid];
    __syncthreads();
    int c = tid * 4;
    float4 acc[4];
    #pragma unroll
    for (int r = 0; r < 4; r++) { acc[r].x=0.f; acc[r].y=0.f; acc[r].z=0.f; acc[r].w=0.f; }
    const float* w = W2 + (size_t)e * HIDD * CC + c;
    #pragma unroll 8
    for (int k = 0; k < HIDD; k++) {
        float4 wv = *(const float4*)(w + (size_t)k * CC);
        #pragma unroll
        for (int r = 0; r < 4; r++) {
            float hv = hs[r][k];
            acc[r].x += hv*wv.x; acc[r].y += hv*wv.y;
            acc[r].z += hv*wv.z; acc[r].w += hv*wv.w;
        }
    }
    float4 bb = *(const float4*)(b2 + (size_t)e * CC + c);
    #pragma unroll
    for (int r = 0; r < 4; r++) {
        int tok = toks[r];
        if (tok < 0) continue;          // unfilled slot: no token
        float4 z = *(const float4*)(zn + (size_t)tok * CC + c);
        float4 o;
        o.x = z.x + acc[r].x + bb.x; o.y = z.y + acc[r].y + bb.y;
        o.z = z.z + acc[r].z + bb.z; o.w = z.w + acc[r].w + bb.w;
        *(float4*)(out + (size_t)tok * CC + c) = o;
    }
}

// ---------------- dropped tokens: out = 2*zn ----------------
__global__ void __launch_bounds__(256)
finalize_dropped_kernel(const float* __restrict__ zn, const int* __restrict__ pos,
                        float* __restrict__ out)
{
    int tok = blockIdx.x, tid = threadIdx.x;
    if (pos[tok] < CAPP) return;        // kept: written by ffn2_out
    float4 z = ((const float4*)(zn + (size_t)tok * CC))[tid];
    float4 o = {2.f*z.x, 2.f*z.y, 2.f*z.z, 2.f*z.w};
    ((float4*)(out + (size_t)tok * CC))[tid] = o;
}

__global__ void fill_ones_kernel(float* __restrict__ p, int n)
{
    int i = blockIdx.x * 256 + threadIdx.x;
    if (i < n) p[i] = 1.0f;
}

// ---------------- launch ----------------
extern "C" void kernel_launch(void* const* d_in, const int* in_sizes, int n_in,
                              void* d_out, int out_size)
{
    const float* qx  = (const float*)d_in[0];
    const float* kx  = (const float*)d_in[1];
    const float* vx  = (const float*)d_in[2];
    const float* WQ  = (const float*)d_in[4];
    const float* bQ  = (const float*)d_in[5];
    const float* WK  = (const float*)d_in[6];
    const float* bK  = (const float*)d_in[7];
    const float* WV  = (const float*)d_in[8];
    const float* bV  = (const float*)d_in[9];
    const float* WO  = (const float*)d_in[10];
    const float* bO  = (const float*)d_in[11];
    const float* ln1w= (const float*)d_in[12];
    const float* ln1b= (const float*)d_in[13];
    const float* Wsw = (const float*)d_in[14];
    const float* bsw = (const float*)d_in[15];
    const float* W1  = (const float*)d_in[16];
    const float* b1  = (const float*)d_in[17];
    const float* W2  = (const float*)d_in[18];
    const float* b2  = (const float*)d_in[19];
    float* out = (float*)d_out;

    float *pA, *pzn, *peb, *ph;
    int *proute, *ppos, *ps2t;
    cudaGetSymbolAddress((void**)&pA,  g_A);
    cudaGetSymbolAddress((void**)&pzn, g_zn);
    cudaGetSymbolAddress((void**)&peb, g_eb);
    cudaGetSymbolAddress((void**)&ph,  g_h);
    cudaGetSymbolAddress((void**)&proute, g_route);
    cudaGetSymbolAddress((void**)&ppos,   g_pos);
    cudaGetSymbolAddress((void**)&ps2t,   g_slot2tok);

    __half *xq[2], *xk[2], *xv[2];
    __half *wq[2], *wk[2], *wv[2], *wo[2];
    __half *oq[2], *ok[2], *ov[2];
    cudaGetSymbolAddress((void**)&xq[0], g_xq0); cudaGetSymbolAddress((void**)&xq[1], g_xq1);
    cudaGetSymbolAddress((void**)&xk[0], g_xk0); cudaGetSymbolAddress((void**)&xk[1], g_xk1);
    cudaGetSymbolAddress((void**)&xv[0], g_xv0); cudaGetSymbolAddress((void**)&xv[1], g_xv1);
    cudaGetSymbolAddress((void**)&wq[0], g_wq0); cudaGetSymbolAddress((void**)&wq[1], g_wq1);
    cudaGetSymbolAddress((void**)&wk[0], g_wk0); cudaGetSymbolAddress((void**)&wk[1], g_wk1);
    cudaGetSymbolAddress((void**)&wv[0], g_wv0); cudaGetSymbolAddress((void**)&wv[1], g_wv1);
    cudaGetSymbolAddress((void**)&wo[0], g_wo0); cudaGetSymbolAddress((void**)&wo[1], g_wo1);
    cudaGetSymbolAddress((void**)&oq[0], g_q0);  cudaGetSymbolAddress((void**)&oq[1], g_q1);
    cudaGetSymbolAddress((void**)&ok[0], g_k0);  cudaGetSymbolAddress((void**)&ok[1], g_k1);
    cudaGetSymbolAddress((void**)&ov[0], g_v0);  cudaGetSymbolAddress((void**)&ov[1], g_v1);

    cudaFuncSetAttribute(mma_gemm,   cudaFuncAttributeMaxDynamicSharedMemorySize, GEMM_SMEM);
    cudaFuncSetAttribute(mma_gemm_s, cudaFuncAttributeMaxDynamicSharedMemorySize, GEMM_SMEM);
    cudaFuncSetAttribute(attn_mma,   cudaFuncAttributeMaxDynamicSharedMemorySize, ATTN_SMEM);

    const int NX4 = NTOK * CC / 4;
    const int NW4 = CC * CC / 4;
    dim3 gemmGrid(CC/128, NTOK/128);

    split2_kernel<<<NX4/256, 256>>>(qx, xq[0], xq[1], NX4);
    split2_kernel<<<NW4/256, 256>>>(WQ, wq[0], wq[1], NW4);
    split2_kernel<<<NX4/256, 256>>>(kx, xk[0], xk[1], NX4);
    split2_kernel<<<NW4/256, 256>>>(WK, wk[0], wk[1], NW4);
    split2_kernel<<<NX4/256, 256>>>(vx, xv[0], xv[1], NX4);

    mma_gemm_s<<<gemmGrid, 256, GEMM_SMEM>>>(
        xq[0], xq[1], wq[0], wq[1], bQ, oq[0], oq[1]);

    split2_kernel<<<NW4/256, 256>>>(WV, wv[0], wv[1], NW4);
    mma_gemm_s<<<gemmGrid, 256, GEMM_SMEM>>>(
        xk[0], xk[1], wk[0], wk[1], bK, ok[0], ok[1]);
    mma_gemm_s<<<gemmGrid, 256, GEMM_SMEM>>>(
        xv[0], xv[1], wv[0], wv[1], bV, ov[0], ov[1]);

    split2_kernel<<<NW4/256, 256>>>(WO, wo[0], wo[1], NW4);

    attn_mma<<<dim3(LL/128, BB*HH), 256, ATTN_SMEM>>>(
        oq[0], oq[1], ok[0], ok[1], ov[0], ov[1], xq[0], xq[1]);

    mma_gemm<<<gemmGrid, 256, GEMM_SMEM>>>(
        xq[0], xq[1], wo[0], wo[1], bO, pA);

    add_ln_router_kernel<<<NTOK, 256>>>(qx, pA, ln1w, ln1b, Wsw, bsw, pzn, proute);
    scanpos_kernel<<<EE, 256>>>(proute, ppos, ps2t);
    gather_kernel<<<NTOK, 256>>>(pzn, proute, ppos, peb);
    ffn1_kernel<<<EE * (CAPP/4), 256>>>(peb, W1, b1, ph);
    ffn2_out_kernel<<<EE * (CAPP/4), 256>>>(ph, W2, b2, ps2t, pzn, out);
    finalize_dropped_kernel<<<NTOK, 256>>>(pzn, ppos, out);

    long long os = (long long)out_size;
    if (os >= (long long)(2 * NCE)) {
        cudaMemcpyAsync(out + NCE, kx, NCE * sizeof(float),
                        cudaMemcpyDeviceToDevice, 0);
    }
    if (os >= (long long)(3 * NCE)) {
        cudaMemcpyAsync(out + 2 * NCE, vx, NCE * sizeof(float),
                        cudaMemcpyDeviceToDevice, 0);
    }
    long long rem = os - (long long)(3 * NCE);
    if (rem > 0) {
        fill_ones_kernel<<<(int)((rem + 255) / 256), 256>>>(out + 3 * NCE, (int)rem);
    }
}

// round 13
// speedup vs baseline: 1.6299x; 1.0719x over previous
#include <cuda_runtime.h>
#include <cuda_fp16.h>
#include <math.h>
#include <stdint.h>

// ---------------- problem constants ----------------
#define BB 8
#define LL 1024
#define CC 1024
#define HH 16
#define DKK 64
#define NTOK (BB*LL)            // 8192
#define EE 16
#define HIDD 64
#define CAPP 256
#define NCE ((size_t)NTOK * CC)

// ---------------- baseline-PTX tensor-core helpers (sm_80+) ----------------
__device__ __forceinline__ uint32_t smem_u32(const void* p) {
    uint32_t a;
    asm("{ .reg .u64 t; cvta.to.shared.u64 t, %1; cvt.u32.u64 %0, t; }" : "=r"(a) : "l"(p));
    return a;
}
#define LDSM4(d0, d1, d2, d3, a) \
    asm volatile("ldmatrix.sync.aligned.m8n8.x4.shared.b16 {%0,%1,%2,%3}, [%4];" \
        : "=r"(d0), "=r"(d1), "=r"(d2), "=r"(d3) : "r"(a))
#define LDSM4T(d0, d1, d2, d3, a) \
    asm volatile("ldmatrix.sync.aligned.m8n8.x4.trans.shared.b16 {%0,%1,%2,%3}, [%4];" \
        : "=r"(d0), "=r"(d1), "=r"(d2), "=r"(d3) : "r"(a))
#define MMA16816(c, a0, a1, a2, a3, b0, b1) \
    asm volatile("mma.sync.aligned.m16n8k16.row.col.f32.f16.f16.f32 " \
        "{%0,%1,%2,%3}, {%4,%5,%6,%7}, {%8,%9}, {%0,%1,%2,%3};" \
        : "+f"((c)[0]), "+f"((c)[1]), "+f"((c)[2]), "+f"((c)[3]) \
        : "r"(a0), "r"(a1), "r"(a2), "r"(a3), "r"(b0), "r"(b1))
#define CP_ASYNC16(dst, src) \
    asm volatile("cp.async.cg.shared.global [%0], [%1], 16;" :: "r"(dst), "l"(src))
#define CP_COMMIT() asm volatile("cp.async.commit_group;" ::: "memory")
#define CP_WAIT1()  asm volatile("cp.async.wait_group 1;" ::: "memory")

// ---------------- fp16 2-term split helpers ----------------
__device__ __forceinline__ void split2r(float a, __half& h0, __half& h1)
{
    h0 = __float2half_rn(a);
    h1 = __float2half_rn(a - __half2float(h0));
}
__device__ __forceinline__ uint32_t pkh(__half lo, __half hi)
{
    __half2 t = __halves2half2(lo, hi);
    return *reinterpret_cast<uint32_t*>(&t);
}
__device__ __forceinline__ void store_split_pair(
    __half* Y0, __half* Y1, size_t off, float e0, float e1)
{
    __half a0, a1, b0, b1;
    split2r(e0, a0, a1);
    split2r(e1, b0, b1);
    *(uint32_t*)(Y0 + off) = pkh(a0, b0);
    *(uint32_t*)(Y1 + off) = pkh(a1, b1);
}

// ---------------- scratch ----------------
__device__ float g_A [NTOK * CC];
__device__ float g_zn[NTOK * CC];
__device__ float g_eb[EE * CAPP * CC];
__device__ float g_h [EE * CAPP * HIDD];
__device__ int   g_route[NTOK];
__device__ int   g_pos  [NTOK];
__device__ int   g_slot2tok[EE * CAPP];
__device__ __half g_xq0[NTOK*CC], g_xq1[NTOK*CC];
__device__ __half g_xk0[NTOK*CC], g_xk1[NTOK*CC];
__device__ __half g_xv0[NTOK*CC], g_xv1[NTOK*CC];
__device__ __half g_wq0[CC*CC], g_wq1[CC*CC];
__device__ __half g_wk0[CC*CC], g_wk1[CC*CC];
__device__ __half g_wv0[CC*CC], g_wv1[CC*CC];
__device__ __half g_wo0[CC*CC], g_wo1[CC*CC];
__device__ __half g_q0[NTOK*CC], g_q1[NTOK*CC];
__device__ __half g_k0[NTOK*CC], g_k1[NTOK*CC];
__device__ __half g_v0[NTOK*CC], g_v1[NTOK*CC];

// ---------------- fp32 -> 2x fp16 split ----------------
__global__ void __launch_bounds__(256)
split2_kernel(const float* __restrict__ in, __half* __restrict__ o0,
              __half* __restrict__ o1, int n4)
{
    int i = blockIdx.x * 256 + threadIdx.x;
    if (i >= n4) return;
    float4 v = ((const float4*)in)[i];
    float a[4] = {v.x, v.y, v.z, v.w};
    union { __half b[4]; uint2 u; } s0, s1;
    #pragma unroll
    for (int j = 0; j < 4; j++) split2r(a[j], s0.b[j], s1.b[j]);
    ((uint2*)o0)[i] = s0.u;
    ((uint2*)o1)[i] = s1.u;
}

// ---------------- HMMA GEMM core (fp16x3), 2-stage, 2 CTAs/SM ----------------
#define APAD 40
#define TILE_B (128 * APAD * 2)     // 10240
#define STAGE4 (4 * TILE_B)         // 40960
#define GEMM_SMEM (2 * STAGE4)      // 81920
#define NCHUNK 32

template <int OutMode>
__device__ __forceinline__ void gemm_core(
    const __half* __restrict__ X0, const __half* __restrict__ X1,
    const __half* __restrict__ W0, const __half* __restrict__ W1,
    const float* __restrict__ bias,
    float* __restrict__ Yf,
    __half* __restrict__ Y0, __half* __restrict__ Y1,
    char* smem)
{
    const uint32_t sb = smem_u32(smem);
    const int tid = threadIdx.x, wid = tid >> 5, lane = tid & 31;
    const int bm = blockIdx.y * 128, bn = blockIdx.x * 128;
    const int wm = (wid >> 2) * 64, wn = (wid & 3) * 32;

    const __half* TS[4] = {X0, X1, W0, W1};

    #define G_LOAD(buf, ch) do { \
        int ko_ = (ch) * 32; \
        _Pragma("unroll") \
        for (int j_ = 0; j_ < 8; j_++) { \
            int e_ = j_ * 256 + tid; \
            int t_ = e_ >> 9; \
            int w_ = e_ & 511; \
            int r_ = w_ >> 2, c8_ = (w_ & 3) * 8; \
            int rowb_ = ((t_ < 2) ? bm : bn) + r_; \
            CP_ASYNC16(sb + (buf) * STAGE4 + t_ * TILE_B + (r_ * APAD + c8_) * 2, \
                       TS[t_] + (size_t)rowb_ * CC + ko_ + c8_); \
        } \
    } while (0)

    float acc[4][4][4];
    #pragma unroll
    for (int i = 0; i < 4; i++)
        #pragma unroll
        for (int j = 0; j < 4; j++)
            #pragma unroll
            for (int q = 0; q < 4; q++) acc[i][j][q] = 0.f;

    G_LOAD(0, 0); CP_COMMIT();
    G_LOAD(1, 1); CP_COMMIT();

    for (int c = 0; c < NCHUNK; c++) {
        int buf = c & 1;
        CP_WAIT1();
        __syncthreads();

        uint32_t stage = sb + buf * STAGE4;
        #pragma unroll
        for (int kk = 0; kk < 2; kk++) {
            uint32_t a[2][4][4];
            #pragma unroll
            for (int s = 0; s < 2; s++)
                #pragma unroll
                for (int i = 0; i < 4; i++) {
                    int arow = wm + i * 16 + (lane & 15);
                    int acol = kk * 16 + ((lane >> 4) << 3);
                    LDSM4(a[s][i][0], a[s][i][1], a[s][i][2], a[s][i][3],
                          stage + s * TILE_B + (uint32_t)(arow * APAD + acol) * 2);
                }
            #pragma unroll
            for (int jp = 0; jp < 2; jp++) {
                int g = lane >> 3;
                int brow = wn + jp * 16 + ((g & 2) << 2) + (lane & 7);
                int bcol = kk * 16 + ((g & 1) << 3);
                uint32_t boff = (uint32_t)(brow * APAD + bcol) * 2;
                uint32_t b0, b1, b2, b3;
                LDSM4(b0, b1, b2, b3, stage + 2 * TILE_B + boff);
                #pragma unroll
                for (int i = 0; i < 4; i++) {
                    MMA16816(acc[i][2*jp],   a[0][i][0],a[0][i][1],a[0][i][2],a[0][i][3], b0,b1);
                    MMA16816(acc[i][2*jp+1], a[0][i][0],a[0][i][1],a[0][i][2],a[0][i][3], b2,b3);
                    MMA16816(acc[i][2*jp],   a[1][i][0],a[1][i][1],a[1][i][2],a[1][i][3], b0,b1);
                    MMA16816(acc[i][2*jp+1], a[1][i][0],a[1][i][1],a[1][i][2],a[1][i][3], b2,b3);
                }
                LDSM4(b0, b1, b2, b3, stage + 3 * TILE_B + boff);
                #pragma unroll
                for (int i = 0; i < 4; i++) {
                    MMA16816(acc[i][2*jp],   a[0][i][0],a[0][i][1],a[0][i][2],a[0][i][3], b0,b1);
                    MMA16816(acc[i][2*jp+1], a[0][i][0],a[0][i][1],a[0][i][2],a[0][i][3], b2,b3);
                }
            }
        }
        __syncthreads();
        if (c + 2 < NCHUNK) {
            G_LOAD(buf, c + 2);
        }
        CP_COMMIT();
    }

    #pragma unroll
    for (int i = 0; i < 4; i++) {
        int row = bm + wm + i * 16 + (lane >> 2);
        #pragma unroll
        for (int j = 0; j < 4; j++) {
            int col = bn + wn + j * 8 + ((lane & 3) << 1);
            float bx = bias[col], by = bias[col + 1];
            float e0 = acc[i][j][0] + bx, e1 = acc[i][j][1] + by;
            float e2 = acc[i][j][2] + bx, e3 = acc[i][j][3] + by;
            if (OutMode == 0) {
                float2 v0 = {e0, e1};
                float2 v1 = {e2, e3};
                *(float2*)(Yf + (size_t)row * CC + col) = v0;
                *(float2*)(Yf + (size_t)(row + 8) * CC + col) = v1;
            } else {
                store_split_pair(Y0, Y1, (size_t)row * CC + col, e0, e1);
                store_split_pair(Y0, Y1, (size_t)(row + 8) * CC + col, e2, e3);
            }
        }
    }
    #undef G_LOAD
}

__global__ void __launch_bounds__(256, 2)
mma_gemm(const __half* __restrict__ X0, const __half* __restrict__ X1,
         const __half* __restrict__ W0, const __half* __restrict__ W1,
         const float* __restrict__ bias, float* __restrict__ Y)
{
    extern __shared__ char smem[];
    gemm_core<0>(X0, X1, W0, W1, bias, Y, nullptr, nullptr, smem);
}

__global__ void __launch_bounds__(256, 2)
mma_gemm_s(const __half* __restrict__ X0, const __half* __restrict__ X1,
           const __half* __restrict__ W0, const __half* __restrict__ W1,
           const float* __restrict__ bias,
           __half* __restrict__ Y0, __half* __restrict__ Y1)
{
    extern __shared__ char smem[];
    gemm_core<1>(X0, X1, W0, W1, bias, nullptr, Y0, Y1, smem);
}

// ---------------- flash attention on HMMA (fp16x3, R10-verbatim) -------------
#define QTILE (128 * 72 * 2)      // 18432
#define KVTILE (64 * 72 * 2)      // 9216
#define AT_SOFF (2 * QTILE)       // 36864
#define AT_STG (4 * KVTILE)       // 36864
#define ATTN_SMEM (AT_SOFF + 2 * AT_STG)   // 110592

__global__ void __launch_bounds__(256)
attn_mma(const __half* __restrict__ Q0, const __half* __restrict__ Q1,
         const __half* __restrict__ K0, const __half* __restrict__ K1,
         const __half* __restrict__ V0, const __half* __restrict__ V1,
         __half* __restrict__ Z0, __half* __restrict__ Z1)
{
    extern __shared__ char smem[];
    const uint32_t sb = smem_u32(smem);
    const int tid = threadIdx.x, wid = tid >> 5, lane = tid & 31;
    const int bh = blockIdx.y;
    const int b = bh >> 4, hh = bh & 15;
    const int q0 = blockIdx.x * 128;

    const __half* QS[2] = {Q0, Q1};
    const __half* KS[2] = {K0, K1};
    const __half* VS[2] = {V0, V1};

    #pragma unroll
    for (int j = 0; j < 8; j++) {
        int e = j * 256 + tid;
        int t = e >> 10;
        int w = e & 1023;
        int r = w >> 3, c = w & 7;
        CP_ASYNC16(sb + t * QTILE + (uint32_t)(r * 72 + c * 8) * 2,
                   QS[t] + (size_t)(b * LL + q0 + r) * CC + hh * 64 + c * 8);
    }

    #define KV_LOAD(buf, kt) do { \
        _Pragma("unroll") \
        for (int j_ = 0; j_ < 8; j_++) { \
            int e_ = j_ * 256 + tid; \
            int t_ = e_ >> 9; \
            int w_ = e_ & 511; \
            int r_ = w_ >> 3, c_ = w_ & 7; \
            const __half* src_ = (t_ < 2) ? KS[t_] : VS[t_ - 2]; \
            CP_ASYNC16(sb + AT_SOFF + (buf) * AT_STG + t_ * KVTILE + \
                       (uint32_t)(r_ * 72 + c_ * 8) * 2, \
                       src_ + (size_t)(b * LL + (kt) * 64 + r_) * CC + hh * 64 + c_ * 8); \
        } \
    } while (0)

    KV_LOAD(0, 0); CP_COMMIT();
    KV_LOAD(1, 1); CP_COMMIT();

    float pv[8][4];
    #pragma unroll
    for (int j = 0; j < 8; j++)
        #pragma unroll
        for (int q = 0; q < 4; q++) pv[j][q] = 0.f;
    float m0 = -1e30f, m1 = -1e30f, l0 = 0.f, l1 = 0.f;
    uint32_t qf[2][4][4];

    for (int kt = 0; kt < LL / 64; kt++) {
        CP_WAIT1();
        __syncthreads();
        if (kt == 0) {
            #pragma unroll
            for (int s = 0; s < 2; s++)
                #pragma unroll
                for (int ks = 0; ks < 4; ks++) {
                    int arow = wid * 16 + (lane & 15);
                    int acol = ks * 16 + ((lane >> 4) << 3);
                    LDSM4(qf[s][ks][0], qf[s][ks][1], qf[s][ks][2], qf[s][ks][3],
                          sb + s * QTILE + (uint32_t)(arow * 72 + acol) * 2);
                }
        }

        uint32_t sK = sb + AT_SOFF + (kt & 1) * AT_STG;
        uint32_t sV = sK + 2 * KVTILE;

        float sacc[8][4];
        #pragma unroll
        for (int j = 0; j < 8; j++)
            #pragma unroll
            for (int q = 0; q < 4; q++) sacc[j][q] = 0.f;

        #pragma unroll
        for (int ks = 0; ks < 4; ks++) {
            #pragma unroll
            for (int ntp = 0; ntp < 4; ntp++) {
                int g = lane >> 3;
                int brow = ntp * 16 + ((g & 2) << 2) + (lane & 7);
                int bcol = ks * 16 + ((g & 1) << 3);
                uint32_t boff = (uint32_t)(brow * 72 + bcol) * 2;
                uint32_t b0, b1, b2, b3;
                LDSM4(b0, b1, b2, b3, sK + 0 * KVTILE + boff);
                MMA16816(sacc[2*ntp],   qf[0][ks][0],qf[0][ks][1],qf[0][ks][2],qf[0][ks][3], b0,b1);
                MMA16816(sacc[2*ntp+1], qf[0][ks][0],qf[0][ks][1],qf[0][ks][2],qf[0][ks][3], b2,b3);
                MMA16816(sacc[2*ntp],   qf[1][ks][0],qf[1][ks][1],qf[1][ks][2],qf[1][ks][3], b0,b1);
                MMA16816(sacc[2*ntp+1], qf[1][ks][0],qf[1][ks][1],qf[1][ks][2],qf[1][ks][3], b2,b3);
                LDSM4(b0, b1, b2, b3, sK + 1 * KVTILE + boff);
                MMA16816(sacc[2*ntp],   qf[0][ks][0],qf[0][ks][1],qf[0][ks][2],qf[0][ks][3], b0,b1);
                MMA16816(sacc[2*ntp+1], qf[0][ks][0],qf[0][ks][1],qf[0][ks][2],qf[0][ks][3], b2,b3);
            }
        }

        float tm0 = -1e30f, tm1 = -1e30f;
        #pragma unroll
        for (int j = 0; j < 8; j++) {
            tm0 = fmaxf(tm0, fmaxf(sacc[j][0], sacc[j][1]));
            tm1 = fmaxf(tm1, fmaxf(sacc[j][2], sacc[j][3]));
        }
        tm0 = fmaxf(tm0, __shfl_xor_sync(0xffffffffu, tm0, 1));
        tm0 = fmaxf(tm0, __shfl_xor_sync(0xffffffffu, tm0, 2));
        tm1 = fmaxf(tm1, __shfl_xor_sync(0xffffffffu, tm1, 1));
        tm1 = fmaxf(tm1, __shfl_xor_sync(0xffffffffu, tm1, 2));
        tm0 *= 0.125f; tm1 *= 0.125f;
        float mn0 = fmaxf(m0, tm0), mn1 = fmaxf(m1, tm1);
        float al0 = __expf(m0 - mn0), al1 = __expf(m1 - mn1);
        m0 = mn0; m1 = mn1;

        float rs0 = 0.f, rs1 = 0.f;
        uint32_t pf[2][4][4];
        #pragma unroll
        for (int j = 0; j < 8; j++) {
            float p0 = __expf(sacc[j][0] * 0.125f - mn0);
            float p1 = __expf(sacc[j][1] * 0.125f - mn0);
            float p2 = __expf(sacc[j][2] * 0.125f - mn1);
            float p3 = __expf(sacc[j][3] * 0.125f - mn1);
            rs0 += p0 + p1; rs1 += p2 + p3;
            __half a0, a1, b0v, b1v, c0, c1, d0, d1;
            split2r(p0, a0, a1);
            split2r(p1, b0v, b1v);
            split2r(p2, c0, c1);
            split2r(p3, d0, d1);
            int ks = j >> 1, ri = (j & 1) * 2;
            pf[0][ks][ri]     = pkh(a0, b0v);
            pf[0][ks][ri + 1] = pkh(c0, d0);
            pf[1][ks][ri]     = pkh(a1, b1v);
            pf[1][ks][ri + 1] = pkh(c1, d1);
        }
        rs0 += __shfl_xor_sync(0xffffffffu, rs0, 1);
        rs0 += __shfl_xor_sync(0xffffffffu, rs0, 2);
        rs1 += __shfl_xor_sync(0xffffffffu, rs1, 1);
        rs1 += __shfl_xor_sync(0xffffffffu, rs1, 2);
        l0 = l0 * al0 + rs0;
        l1 = l1 * al1 + rs1;
        #pragma unroll
        for (int j = 0; j < 8; j++) {
            pv[j][0] *= al0; pv[j][1] *= al0;
            pv[j][2] *= al1; pv[j][3] *= al1;
        }

        #pragma unroll
        for (int ks = 0; ks < 4; ks++) {
            #pragma unroll
            for (int ntp = 0; ntp < 4; ntp++) {
                int g = lane >> 3;
                int vrow = ks * 16 + ((g & 1) << 3) + (lane & 7);
                int vcol = ntp * 16 + ((g >> 1) << 3);
                uint32_t voff = (uint32_t)(vrow * 72 + vcol) * 2;
                uint32_t v0, v1, v2, v3;
                LDSM4T(v0, v1, v2, v3, sV + 0 * KVTILE + voff);
                MMA16816(pv[2*ntp],   pf[0][ks][0],pf[0][ks][1],pf[0][ks][2],pf[0][ks][3], v0,v1);
                MMA16816(pv[2*ntp+1], pf[0][ks][0],pf[0][ks][1],pf[0][ks][2],pf[0][ks][3], v2,v3);
                MMA16816(pv[2*ntp],   pf[1][ks][0],pf[1][ks][1],pf[1][ks][2],pf[1][ks][3], v0,v1);
                MMA16816(pv[2*ntp+1], pf[1][ks][1],pf[1][ks][1],pf[1][ks][2],pf[1][ks][3], v2,v3);
                LDSM4T(v0, v1, v2, v3, sV + 1 * KVTILE + voff);
                MMA16816(pv[2*ntp],   pf[0][ks][0],pf[0][ks][1],pf[0][ks][2],pf[0][ks][3], v0,v1);
                MMA16816(pv[2*ntp+1], pf[0][ks][0],pf[0][ks][1],pf[0][ks][2],pf[0][ks][3], v2,v3);
            }
        }

        __syncthreads();
        if (kt + 2 < LL / 64) KV_LOAD(kt & 1, kt + 2);
        CP_COMMIT();
    }

    float inv0 = 1.f / l0, inv1 = 1.f / l1;
    int gr0 = b * LL + q0 + wid * 16 + (lane >> 2);
    #pragma unroll
    for (int j = 0; j < 8; j++) {
        int col = hh * 64 + j * 8 + ((lane & 3) << 1);
        store_split_pair(Z0, Z1, (size_t)gr0 * CC + col,
                         pv[j][0] * inv0, pv[j][1] * inv0);
        store_split_pair(Z0, Z1, (size_t)(gr0 + 8) * CC + col,
                         pv[j][2] * inv1, pv[j][3] * inv1);
    }
    #undef KV_LOAD
}

// ---------------- block reduce helper ----------------
__device__ __forceinline__ float blockReduceSum256(float v, float* red)
{
    int lane = threadIdx.x & 31, warp = threadIdx.x >> 5;
    #pragma unroll
    for (int o = 16; o; o >>= 1) v += __shfl_xor_sync(0xffffffffu, v, o);
    if (lane == 0) red[warp] = v;
    __syncthreads();
    if (warp == 0) {
        v = (lane < 8) ? red[lane] : 0.f;
        #pragma unroll
        for (int o = 4; o; o >>= 1) v += __shfl_xor_sync(0xffffffffu, v, o);
        if (lane == 0) red[0] = v;
    }
    __syncthreads();
    float r = red[0];
    __syncthreads();
    return r;
}

// ---------------- fused residual add + LayerNorm + router argmax ----------------
__global__ void __launch_bounds__(256)
add_ln_router_kernel(const float* __restrict__ qx, const float* __restrict__ att,
                     const float* __restrict__ w, const float* __restrict__ bb,
                     const float* __restrict__ Wsw, const float* __restrict__ bsw,
                     float* __restrict__ zn, int* __restrict__ route)
{
    __shared__ float red[8];
    __shared__ float esum[8][EE];
    int row = blockIdx.x, tid = threadIdx.x;
    int lane = tid & 31, warp = tid >> 5;
    const float4* xq = (const float4*)(qx  + (size_t)row * CC);
    const float4* aq = (const float4*)(att + (size_t)row * CC);
    float4 x = xq[tid], a = aq[tid];
    float4 v; v.x = x.x + a.x; v.y = x.y + a.y; v.z = x.z + a.z; v.w = x.w + a.w;
    float mean = blockReduceSum256(v.x + v.y + v.z + v.w, red) * (1.f/1024.f);
    float dx = v.x - mean, dy = v.y - mean, dz = v.z - mean, dw = v.w - mean;
    float var = blockReduceSum256(dx*dx + dy*dy + dz*dz + dw*dw, red) * (1.f/1024.f);
    float rs = rsqrtf(var + 1e-5f);
    float4 wv = ((const float4*)w)[tid];
    float4 bv = ((const float4*)bb)[tid];
    float4 o;
    o.x = dx*rs*wv.x + bv.x; o.y = dy*rs*wv.y + bv.y;
    o.z = dz*rs*wv.z + bv.z; o.w = dw*rs*wv.w + bv.w;
    ((float4*)(zn + (size_t)row * CC))[tid] = o;

    int c = tid * 4;
    #pragma unroll
    for (int e = 0; e < EE; e++) {
        float4 we = *(const float4*)(Wsw + (size_t)e * CC + c);
        float p = o.x*we.x + o.y*we.y + o.z*we.z + o.w*we.w;
        #pragma unroll
        for (int of = 16; of; of >>= 1) p += __shfl_xor_sync(0xffffffffu, p, of);
        if (lane == 0) esum[warp][e] = p;
    }
    __syncthreads();
    if (tid == 0) {
        float best = -1e30f; int bi = 0;
        #pragma unroll
        for (int e = 0; e < EE; e++) {
            float lg = esum[0][e] + esum[1][e] + esum[2][e] + esum[3][e]
                     + esum[4][e] + esum[5][e] + esum[6][e] + esum[7][e] + bsw[e];
            if (lg > best) { best = lg; bi = e; }
        }
        route[row] = bi;
    }
}

// ---------------- deterministic per-expert prefix positions + inverse map ----
__global__ void __launch_bounds__(256)
scanpos_kernel(const int* __restrict__ route, int* __restrict__ pos,
               int* __restrict__ slot2tok)
{
    int e = blockIdx.x;
    int tid = threadIdx.x;
    int lane = tid & 31, warp = tid >> 5;
    __shared__ int wtot[8];
    __shared__ int running;
    if (tid == 0) running = 0;
    if (tid < CAPP) {
        slot2tok[e * CAPP + tid] = -1;
    }
    __syncthreads();
    for (int base = 0; base < NTOK; base += 256) {
        int tok = base + tid;
        int flag = (route[tok] == e);
        unsigned m = __ballot_sync(0xffffffffu, flag);
        int rank = __popc(m & ((1u << lane) - 1u));
        if (lane == 31) wtot[warp] = __popc(m);
        __syncthreads();
        int prefix = 0;
        for (int w = 0; w < warp; w++) prefix += wtot[w];
        if (flag) {
            int p = running + prefix + rank;
            pos[tok] = p;
            if (p < CAPP) slot2tok[e * CAPP + p] = tok;
        }
        __syncthreads();
        if (tid == 0) {
            int t = 0;
            for (int w = 0; w < 8; w++) t += wtot[w];
            running += t;
        }
        __syncthreads();
    }
}

// ---------------- gather kept tokens into expert buffers ----------------
__global__ void __launch_bounds__(256)
gather_kernel(const float* __restrict__ zn, const int* __restrict__ route,
              const int* __restrict__ pos, float* __restrict__ eb)
{
    int tok = blockIdx.x;
    int p = pos[tok];
    if (p >= CAPP) return;
    size_t slot = (size_t)route[tok] * CAPP + p;
    ((float4*)(eb + slot * CC))[threadIdx.x] =
        ((const float4*)(zn + (size_t)tok * CC))[threadIdx.x];
}

// ---------------- expert FFN layer 1 ----------------
__global__ void __launch_bounds__(256)
ffn1_kernel(const float* __restrict__ eb, const float* __restrict__ W1,
            const float* __restrict__ b1, float* __restrict__ h)
{
    int blk = blockIdx.x;
    int e  = blk >> 6;
    int r0 = (blk & 63) * 4;
    __shared__ float xs[4][CC];
    __shared__ float red[4][4][HIDD];
    int tid = threadIdx.x;
    const float4* src = (const float4*)(eb + ((size_t)e*CAPP + r0) * CC);
    for (int i = tid; i < 4 * (CC/4); i += 256)
        ((float4*)xs)[i] = src[i];
    __syncthreads();
    int kp = tid >> 6;
    int n  = tid & 63;
    float acc[4] = {};
    const float* w = W1 + (size_t)e * CC * HIDD + n;
    #pragma unroll 4
    for (int k = kp; k < CC; k += 4) {
        float wv = w[(size_t)k * HIDD];
        #pragma unroll
        for (int r = 0; r < 4; r++) acc[r] += xs[r][k] * wv;
    }
    #pragma unroll
    for (int r = 0; r < 4; r++) red[kp][r][n] = acc[r];
    __syncthreads();
    {
        int r = tid >> 6, n2 = tid & 63;
        float s = red[0][r][n2] + red[1][r][n2] + red[2][r][n2] + red[3][r][n2]
                + b1[e*HIDD + n2];
        h[((size_t)e*CAPP + r0 + r) * HIDD + n2] = fmaxf(s, 0.f);
    }
}

// ---------------- expert FFN layer 2 fused with finalize (kept tokens) -------
__global__ void __launch_bounds__(256)
ffn2_out_kernel(const float* __restrict__ h, const float* __restrict__ W2,
                const float* __restrict__ b2, const int* __restrict__ slot2tok,
                const float* __restrict__ zn, float* __restrict__ out)
{
    int blk = blockIdx.x;
    int e  = blk >> 6;
    int r0 = (blk & 63) * 4;
    __shared__ float hs[4][HIDD];
    __shared__ int toks[4];
    int tid = threadIdx.x;
    hs[tid >> 6][tid & 63] = h[((size_t)e*CAPP + r0 + (tid >> 6)) * HIDD + (tid & 63)];
    if (tid < 4) toks[tid] = slot2tok[e * CAPP + r0 + tid];
    __syncthreads();
    int c = tid * 4;
    float4 acc[4];
    #pragma unroll
    for (int r = 0; r < 4; r++) { acc[r].x=0.f; acc[r].y=0.f; acc[r].z=0.f; acc[r].w=0.f; }
    const float* w = W2 + (size_t)e * HIDD * CC + c;
    #pragma unroll 8
    for (int k = 0; k < HIDD; k++) {
        float4 wv = *(const float4*)(w + (size_t)k * CC);
        #pragma unroll
        for (int r = 0; r < 4; r++) {
            float hv = hs[r][k];
            acc[r].x += hv*wv.x; acc[r].y += hv*wv.y;
            acc[r].z += hv*wv.z; acc[r].w += hv*wv.w;
        }
    }
    float4 bb = *(const float4*)(b2 + (size_t)e * CC + c);
    #pragma unroll
    for (int r = 0; r < 4; r++) {
        int tok = toks[r];
        if (tok < 0) continue;
        float4 z = *(const float4*)(zn + (size_t)tok * CC + c);
        float4 o;
        o.x = z.x + acc[r].x + bb.x; o.y = z.y + acc[r].y + bb.y;
        o.z = z.z + acc[r].z + bb.z; o.w = z.w + acc[r].w + bb.w;
        *(float4*)(out + (size_t)tok * CC + c) = o;
    }
}

// ---------------- dropped tokens: out = 2*zn ----------------
__global__ void __launch_bounds__(256)
finalize_dropped_kernel(const float* __restrict__ zn, const int* __restrict__ pos,
                        float* __restrict__ out)
{
    int tok = blockIdx.x, tid = threadIdx.x;
    if (pos[tok] < CAPP) return;
    float4 z = ((const float4*)(zn + (size_t)tok * CC))[tid];
    float4 o = {2.f*z.x, 2.f*z.y, 2.f*z.z, 2.f*z.w};
    ((float4*)(out + (size_t)tok * CC))[tid] = o;
}

__global__ void fill_ones_kernel(float* __restrict__ p, int n)
{
    int i = blockIdx.x * 256 + threadIdx.x;
    if (i < n) p[i] = 1.0f;
}

// ---------------- launch (multi-stream DAG) ----------------
extern "C" void kernel_launch(void* const* d_in, const int* in_sizes, int n_in,
                              void* d_out, int out_size)
{
    const float* qx  = (const float*)d_in[0];
    const float* kx  = (const float*)d_in[1];
    const float* vx  = (const float*)d_in[2];
    const float* WQ  = (const float*)d_in[4];
    const float* bQ  = (const float*)d_in[5];
    const float* WK  = (const float*)d_in[6];
    const float* bK  = (const float*)d_in[7];
    const float* WV  = (const float*)d_in[8];
    const float* bV  = (const float*)d_in[9];
    const float* WO  = (const float*)d_in[10];
    const float* bO  = (const float*)d_in[11];
    const float* ln1w= (const float*)d_in[12];
    const float* ln1b= (const float*)d_in[13];
    const float* Wsw = (const float*)d_in[14];
    const float* bsw = (const float*)d_in[15];
    const float* W1  = (const float*)d_in[16];
    const float* b1  = (const float*)d_in[17];
    const float* W2  = (const float*)d_in[18];
    const float* b2  = (const float*)d_in[19];
    float* out = (float*)d_out;

    float *pA, *pzn, *peb, *ph;
    int *proute, *ppos, *ps2t;
    cudaGetSymbolAddress((void**)&pA,  g_A);
    cudaGetSymbolAddress((void**)&pzn, g_zn);
    cudaGetSymbolAddress((void**)&peb, g_eb);
    cudaGetSymbolAddress((void**)&ph,  g_h);
    cudaGetSymbolAddress((void**)&proute, g_route);
    cudaGetSymbolAddress((void**)&ppos,   g_pos);
    cudaGetSymbolAddress((void**)&ps2t,   g_slot2tok);

    __half *xq[2], *xk[2], *xv[2];
    __half *wq[2], *wk[2], *wv[2], *wo[2];
    __half *oq[2], *ok[2], *ov[2];
    cudaGetSymbolAddress((void**)&xq[0], g_xq0); cudaGetSymbolAddress((void**)&xq[1], g_xq1);
    cudaGetSymbolAddress((void**)&xk[0], g_xk0); cudaGetSymbolAddress((void**)&xk[1], g_xk1);
    cudaGetSymbolAddress((void**)&xv[0], g_xv0); cudaGetSymbolAddress((void**)&xv[1], g_xv1);
    cudaGetSymbolAddress((void**)&wq[0], g_wq0); cudaGetSymbolAddress((void**)&wq[1], g_wq1);
    cudaGetSymbolAddress((void**)&wk[0], g_wk0); cudaGetSymbolAddress((void**)&wk[1], g_wk1);
    cudaGetSymbolAddress((void**)&wv[0], g_wv0); cudaGetSymbolAddress((void**)&wv[1], g_wv1);
    cudaGetSymbolAddress((void**)&wo[0], g_wo0); cudaGetSymbolAddress((void**)&wo[1], g_wo1);
    cudaGetSymbolAddress((void**)&oq[0], g_q0);  cudaGetSymbolAddress((void**)&oq[1], g_q1);
    cudaGetSymbolAddress((void**)&ok[0], g_k0);  cudaGetSymbolAddress((void**)&ok[1], g_k1);
    cudaGetSymbolAddress((void**)&ov[0], g_v0);  cudaGetSymbolAddress((void**)&ov[1], g_v1);

    cudaFuncSetAttribute(mma_gemm,   cudaFuncAttributeMaxDynamicSharedMemorySize, GEMM_SMEM);
    cudaFuncSetAttribute(mma_gemm_s, cudaFuncAttributeMaxDynamicSharedMemorySize, GEMM_SMEM);
    cudaFuncSetAttribute(attn_mma,   cudaFuncAttributeMaxDynamicSharedMemorySize, ATTN_SMEM);

    const int NX4 = NTOK * CC / 4;
    const int NW4 = CC * CC / 4;
    dim3 gemmGrid(CC/128, NTOK/128);

    cudaStream_t s1, s2;
    cudaStreamCreateWithFlags(&s1, cudaStreamNonBlocking);
    cudaStreamCreateWithFlags(&s2, cudaStreamNonBlocking);
    cudaEvent_t evFork, evK, evV, evWO, evJ1, evJ2;
    cudaEventCreateWithFlags(&evFork, cudaEventDisableTiming);
    cudaEventCreateWithFlags(&evK,    cudaEventDisableTiming);
    cudaEventCreateWithFlags(&evV,    cudaEventDisableTiming);
    cudaEventCreateWithFlags(&evWO,   cudaEventDisableTiming);
    cudaEventCreateWithFlags(&evJ1,   cudaEventDisableTiming);
    cudaEventCreateWithFlags(&evJ2,   cudaEventDisableTiming);

    // fork
    cudaEventRecord(evFork, 0);
    cudaStreamWaitEvent(s1, evFork, 0);
    cudaStreamWaitEvent(s2, evFork, 0);

    // s0: Q pipeline
    split2_kernel<<<NX4/256, 256>>>(qx, xq[0], xq[1], NX4);
    split2_kernel<<<NW4/256, 256>>>(WQ, wq[0], wq[1], NW4);
    mma_gemm_s<<<gemmGrid, 256, GEMM_SMEM, 0>>>(
        xq[0], xq[1], wq[0], wq[1], bQ, oq[0], oq[1]);

    // s1: K pipeline, then WO split
    split2_kernel<<<NX4/256, 256, 0, s1>>>(kx, xk[0], xk[1], NX4);
    split2_kernel<<<NW4/256, 256, 0, s1>>>(WK, wk[0], wk[1], NW4);
    mma_gemm_s<<<gemmGrid, 256, GEMM_SMEM, s1>>>(
        xk[0], xk[1], wk[0], wk[1], bK, ok[0], ok[1]);
    cudaEventRecord(evK, s1);
    split2_kernel<<<NW4/256, 256, 0, s1>>>(WO, wo[0], wo[1], NW4);
    cudaEventRecord(evWO, s1);

    // s2: tuple memcpys (independent) then V pipeline
    long long os = (long long)out_size;
    if (os >= (long long)(2 * NCE)) {
        cudaMemcpyAsync(out + NCE, kx, NCE * sizeof(float),
                        cudaMemcpyDeviceToDevice, s2);
    }
    if (os >= (long long)(3 * NCE)) {
        cudaMemcpyAsync(out + 2 * NCE, vx, NCE * sizeof(float),
                        cudaMemcpyDeviceToDevice, s2);
    }
    long long rem = os - (long long)(3 * NCE);
    if (rem > 0) {
        fill_ones_kernel<<<(int)((rem + 255) / 256), 256, 0, s2>>>(
            out + 3 * NCE, (int)rem);
    }
    split2_kernel<<<NX4/256, 256, 0, s2>>>(vx, xv[0], xv[1], NX4);
    split2_kernel<<<NW4/256, 256, 0, s2>>>(WV, wv[0], wv[1], NW4);
    mma_gemm_s<<<gemmGrid, 256, GEMM_SMEM, s2>>>(
        xv[0], xv[1], wv[0], wv[1], bV, ov[0], ov[1]);
    cudaEventRecord(evV, s2);

    // s0: attention waits on K and V
    cudaStreamWaitEvent(0, evK, 0);
    cudaStreamWaitEvent(0, evV, 0);
    attn_mma<<<dim3(LL/128, BB*HH), 256, ATTN_SMEM, 0>>>(
        oq[0], oq[1], ok[0], ok[1], ov[0], ov[1], xq[0], xq[1]);

    // s0: WO GEMM waits on WO split
    cudaStreamWaitEvent(0, evWO, 0);
    mma_gemm<<<gemmGrid, 256, GEMM_SMEM, 0>>>(
        xq[0], xq[1], wo[0], wo[1], bO, pA);

    add_ln_router_kernel<<<NTOK, 256>>>(qx, pA, ln1w, ln1b, Wsw, bsw, pzn, proute);
    scanpos_kernel<<<EE, 256>>>(proute, ppos, ps2t);
    gather_kernel<<<NTOK, 256>>>(pzn, proute, ppos, peb);
    ffn1_kernel<<<EE * (CAPP/4), 256>>>(peb, W1, b1, ph);
    ffn2_out_kernel<<<EE * (CAPP/4), 256>>>(ph, W2, b2, ps2t, pzn, out);
    finalize_dropped_kernel<<<NTOK, 256>>>(pzn, ppos, out);

    // join side streams back into s0 before returning
    cudaEventRecord(evJ1, s1);
    cudaEventRecord(evJ2, s2);
    cudaStreamWaitEvent(0, evJ1, 0);
    cudaStreamWaitEvent(0, evJ2, 0);

    cudaEventDestroy(evFork);
    cudaEventDestroy(evK);
    cudaEventDestroy(evV);
    cudaEventDestroy(evWO);
    cudaEventDestroy(evJ1);
    cudaEventDestroy(evJ2);
    cudaStreamDestroy(s1);
    cudaStreamDestroy(s2);
}

// round 14
// speedup vs baseline: 1.6300x; 1.0001x over previous
#include <cuda_runtime.h>
#include <cuda_fp16.h>
#include <math.h>
#include <stdint.h>

// ---------------- problem constants ----------------
#define BB 8
#define LL 1024
#define CC 1024
#define HH 16
#define DKK 64
#define NTOK (BB*LL)            // 8192
#define EE 16
#define HIDD 64
#define CAPP 256
#define NCE ((size_t)NTOK * CC)

// ---------------- baseline-PTX tensor-core helpers (sm_80+) ----------------
__device__ __forceinline__ uint32_t smem_u32(const void* p) {
    uint32_t a;
    asm("{ .reg .u64 t; cvta.to.shared.u64 t, %1; cvt.u32.u64 %0, t; }" : "=r"(a) : "l"(p));
    return a;
}
#define LDSM4(d0, d1, d2, d3, a) \
    asm volatile("ldmatrix.sync.aligned.m8n8.x4.shared.b16 {%0,%1,%2,%3}, [%4];" \
        : "=r"(d0), "=r"(d1), "=r"(d2), "=r"(d3) : "r"(a))
#define LDSM4T(d0, d1, d2, d3, a) \
    asm volatile("ldmatrix.sync.aligned.m8n8.x4.trans.shared.b16 {%0,%1,%2,%3}, [%4];" \
        : "=r"(d0), "=r"(d1), "=r"(d2), "=r"(d3) : "r"(a))
#define MMA16816(c, a0, a1, a2, a3, b0, b1) \
    asm volatile("mma.sync.aligned.m16n8k16.row.col.f32.f16.f16.f32 " \
        "{%0,%1,%2,%3}, {%4,%5,%6,%7}, {%8,%9}, {%0,%1,%2,%3};" \
        : "+f"((c)[0]), "+f"((c)[1]), "+f"((c)[2]), "+f"((c)[3]) \
        : "r"(a0), "r"(a1), "r"(a2), "r"(a3), "r"(b0), "r"(b1))
#define CP_ASYNC16(dst, src) \
    asm volatile("cp.async.cg.shared.global [%0], [%1], 16;" :: "r"(dst), "l"(src))
#define CP_COMMIT() asm volatile("cp.async.commit_group;" ::: "memory")
#define CP_WAIT1()  asm volatile("cp.async.wait_group 1;" ::: "memory")

// ---------------- fp16 2-term split helpers ----------------
__device__ __forceinline__ void split2r(float a, __half& h0, __half& h1)
{
    h0 = __float2half_rn(a);
    h1 = __float2half_rn(a - __half2float(h0));
}
__device__ __forceinline__ uint32_t pkh(__half lo, __half hi)
{
    __half2 t = __halves2half2(lo, hi);
    return *reinterpret_cast<uint32_t*>(&t);
}
__device__ __forceinline__ void store_split_pair(
    __half* Y0, __half* Y1, size_t off, float e0, float e1)
{
    __half a0, a1, b0, b1;
    split2r(e0, a0, a1);
    split2r(e1, b0, b1);
    *(uint32_t*)(Y0 + off) = pkh(a0, b0);
    *(uint32_t*)(Y1 + off) = pkh(a1, b1);
}

// ---------------- scratch ----------------
__device__ float g_A [NTOK * CC];
__device__ float g_zn[NTOK * CC];
__device__ float g_eb[EE * CAPP * CC];
__device__ float g_h [EE * CAPP * HIDD];
__device__ int   g_route[NTOK];
__device__ int   g_pos  [NTOK];
__device__ int   g_slot2tok[EE * CAPP];
__device__ __half g_xq0[NTOK*CC], g_xq1[NTOK*CC];
__device__ __half g_xk0[NTOK*CC], g_xk1[NTOK*CC];
__device__ __half g_xv0[NTOK*CC], g_xv1[NTOK*CC];
__device__ __half g_wq0[CC*CC], g_wq1[CC*CC];
__device__ __half g_wk0[CC*CC], g_wk1[CC*CC];
__device__ __half g_wv0[CC*CC], g_wv1[CC*CC];
__device__ __half g_wo0[CC*CC], g_wo1[CC*CC];
__device__ __half g_q0[NTOK*CC], g_q1[NTOK*CC];
__device__ __half g_k0[NTOK*CC], g_k1[NTOK*CC];
__device__ __half g_v0[NTOK*CC], g_v1[NTOK*CC];

// ---------------- fp32 -> 2x fp16 split ----------------
__global__ void __launch_bounds__(256)
split2_kernel(const float* __restrict__ in, __half* __restrict__ o0,
              __half* __restrict__ o1, int n4)
{
    int i = blockIdx.x * 256 + threadIdx.x;
    if (i >= n4) return;
    float4 v = ((const float4*)in)[i];
    float a[4] = {v.x, v.y, v.z, v.w};
    union { __half b[4]; uint2 u; } s0, s1;
    #pragma unroll
    for (int j = 0; j < 4; j++) split2r(a[j], s0.b[j], s1.b[j]);
    ((uint2*)o0)[i] = s0.u;
    ((uint2*)o1)[i] = s1.u;
}

// ---------------- HMMA GEMM core (fp16x3), 2-stage, 2 CTAs/SM ----------------
#define APAD 40
#define TILE_B (128 * APAD * 2)     // 10240
#define STAGE4 (4 * TILE_B)         // 40960
#define GEMM_SMEM (2 * STAGE4)      // 81920
#define NCHUNK 32

template <int OutMode>
__device__ __forceinline__ void gemm_core(
    const __half* __restrict__ X0, const __half* __restrict__ X1,
    const __half* __restrict__ W0, const __half* __restrict__ W1,
    const float* __restrict__ bias,
    float* __restrict__ Yf,
    __half* __restrict__ Y0, __half* __restrict__ Y1,
    char* smem)
{
    const uint32_t sb = smem_u32(smem);
    const int tid = threadIdx.x, wid = tid >> 5, lane = tid & 31;
    const int bm = blockIdx.y * 128, bn = blockIdx.x * 128;
    const int wm = (wid >> 2) * 64, wn = (wid & 3) * 32;

    const __half* TS[4] = {X0, X1, W0, W1};

    #define G_LOAD(buf, ch) do { \
        int ko_ = (ch) * 32; \
        _Pragma("unroll") \
        for (int j_ = 0; j_ < 8; j_++) { \
            int e_ = j_ * 256 + tid; \
            int t_ = e_ >> 9; \
            int w_ = e_ & 511; \
            int r_ = w_ >> 2, c8_ = (w_ & 3) * 8; \
            int rowb_ = ((t_ < 2) ? bm : bn) + r_; \
            CP_ASYNC16(sb + (buf) * STAGE4 + t_ * TILE_B + (r_ * APAD + c8_) * 2, \
                       TS[t_] + (size_t)rowb_ * CC + ko_ + c8_); \
        } \
    } while (0)

    float acc[4][4][4];
    #pragma unroll
    for (int i = 0; i < 4; i++)
        #pragma unroll
        for (int j = 0; j < 4; j++)
            #pragma unroll
            for (int q = 0; q < 4; q++) acc[i][j][q] = 0.f;

    G_LOAD(0, 0); CP_COMMIT();
    G_LOAD(1, 1); CP_COMMIT();

    for (int c = 0; c < NCHUNK; c++) {
        int buf = c & 1;
        CP_WAIT1();
        __syncthreads();

        uint32_t stage = sb + buf * STAGE4;
        #pragma unroll
        for (int kk = 0; kk < 2; kk++) {
            uint32_t a[2][4][4];
            #pragma unroll
            for (int s = 0; s < 2; s++)
                #pragma unroll
                for (int i = 0; i < 4; i++) {
                    int arow = wm + i * 16 + (lane & 15);
                    int acol = kk * 16 + ((lane >> 4) << 3);
                    LDSM4(a[s][i][0], a[s][i][1], a[s][i][2], a[s][i][3],
                          stage + s * TILE_B + (uint32_t)(arow * APAD + acol) * 2);
                }
            #pragma unroll
            for (int jp = 0; jp < 2; jp++) {
                int g = lane >> 3;
                int brow = wn + jp * 16 + ((g & 2) << 2) + (lane & 7);
                int bcol = kk * 16 + ((g & 1) << 3);
                uint32_t boff = (uint32_t)(brow * APAD + bcol) * 2;
                uint32_t b0, b1, b2, b3;
                LDSM4(b0, b1, b2, b3, stage + 2 * TILE_B + boff);
                #pragma unroll
                for (int i = 0; i < 4; i++) {
                    MMA16816(acc[i][2*jp],   a[0][i][0],a[0][i][1],a[0][i][2],a[0][i][3], b0,b1);
                    MMA16816(acc[i][2*jp+1], a[0][i][0],a[0][i][1],a[0][i][2],a[0][i][3], b2,b3);
                    MMA16816(acc[i][2*jp],   a[1][i][0],a[1][i][1],a[1][i][2],a[1][i][3], b0,b1);
                    MMA16816(acc[i][2*jp+1], a[1][i][0],a[1][i][1],a[1][i][2],a[1][i][3], b2,b3);
                }
                LDSM4(b0, b1, b2, b3, stage + 3 * TILE_B + boff);
                #pragma unroll
                for (int i = 0; i < 4; i++) {
                    MMA16816(acc[i][2*jp],   a[0][i][0],a[0][i][1],a[0][i][2],a[0][i][3], b0,b1);
                    MMA16816(acc[i][2*jp+1], a[0][i][0],a[0][i][1],a[0][i][2],a[0][i][3], b2,b3);
                }
            }
        }
        __syncthreads();
        if (c + 2 < NCHUNK) {
            G_LOAD(buf, c + 2);
        }
        CP_COMMIT();
    }

    #pragma unroll
    for (int i = 0; i < 4; i++) {
        int row = bm + wm + i * 16 + (lane >> 2);
        #pragma unroll
        for (int j = 0; j < 4; j++) {
            int col = bn + wn + j * 8 + ((lane & 3) << 1);
            float bx = bias[col], by = bias[col + 1];
            float e0 = acc[i][j][0] + bx, e1 = acc[i][j][1] + by;
            float e2 = acc[i][j][2] + bx, e3 = acc[i][j][3] + by;
            if (OutMode == 0) {
                float2 v0 = {e0, e1};
                float2 v1 = {e2, e3};
                *(float2*)(Yf + (size_t)row * CC + col) = v0;
                *(float2*)(Yf + (size_t)(row + 8) * CC + col) = v1;
            } else {
                store_split_pair(Y0, Y1, (size_t)row * CC + col, e0, e1);
                store_split_pair(Y0, Y1, (size_t)(row + 8) * CC + col, e2, e3);
            }
        }
    }
    #undef G_LOAD
}

__global__ void __launch_bounds__(256, 2)
mma_gemm(const __half* __restrict__ X0, const __half* __restrict__ X1,
         const __half* __restrict__ W0, const __half* __restrict__ W1,
         const float* __restrict__ bias, float* __restrict__ Y)
{
    extern __shared__ char smem[];
    gemm_core<0>(X0, X1, W0, W1, bias, Y, nullptr, nullptr, smem);
}

__global__ void __launch_bounds__(256, 2)
mma_gemm_s(const __half* __restrict__ X0, const __half* __restrict__ X1,
           const __half* __restrict__ W0, const __half* __restrict__ W1,
           const float* __restrict__ bias,
           __half* __restrict__ Y0, __half* __restrict__ Y1)
{
    extern __shared__ char smem[];
    gemm_core<1>(X0, X1, W0, W1, bias, nullptr, Y0, Y1, smem);
}

// ---------------- flash attention on HMMA (fp16x3) ----------------
#define QTILE (128 * 72 * 2)      // 18432
#define KVTILE (64 * 72 * 2)      // 9216
#define AT_SOFF (2 * QTILE)       // 36864
#define AT_STG (4 * KVTILE)       // 36864
#define ATTN_SMEM (AT_SOFF + 2 * AT_STG)   // 110592

__global__ void __launch_bounds__(256)
attn_mma(const __half* __restrict__ Q0, const __half* __restrict__ Q1,
         const __half* __restrict__ K0, const __half* __restrict__ K1,
         const __half* __restrict__ V0, const __half* __restrict__ V1,
         __half* __restrict__ Z0, __half* __restrict__ Z1)
{
    extern __shared__ char smem[];
    const uint32_t sb = smem_u32(smem);
    const int tid = threadIdx.x, wid = tid >> 5, lane = tid & 31;
    const int bh = blockIdx.y;
    const int b = bh >> 4, hh = bh & 15;
    const int q0 = blockIdx.x * 128;

    const __half* QS[2] = {Q0, Q1};
    const __half* KS[2] = {K0, K1};
    const __half* VS[2] = {V0, V1};

    #pragma unroll
    for (int j = 0; j < 8; j++) {
        int e = j * 256 + tid;
        int t = e >> 10;
        int w = e & 1023;
        int r = w >> 3, c = w & 7;
        CP_ASYNC16(sb + t * QTILE + (uint32_t)(r * 72 + c * 8) * 2,
                   QS[t] + (size_t)(b * LL + q0 + r) * CC + hh * 64 + c * 8);
    }

    #define KV_LOAD(buf, kt) do { \
        _Pragma("unroll") \
        for (int j_ = 0; j_ < 8; j_++) { \
            int e_ = j_ * 256 + tid; \
            int t_ = e_ >> 9; \
            int w_ = e_ & 511; \
            int r_ = w_ >> 3, c_ = w_ & 7; \
            const __half* src_ = (t_ < 2) ? KS[t_] : VS[t_ - 2]; \
            CP_ASYNC16(sb + AT_SOFF + (buf) * AT_STG + t_ * KVTILE + \
                       (uint32_t)(r_ * 72 + c_ * 8) * 2, \
                       src_ + (size_t)(b * LL + (kt) * 64 + r_) * CC + hh * 64 + c_ * 8); \
        } \
    } while (0)

    KV_LOAD(0, 0); CP_COMMIT();
    KV_LOAD(1, 1); CP_COMMIT();

    float pv[8][4];
    #pragma unroll
    for (int j = 0; j < 8; j++)
        #pragma unroll
        for (int q = 0; q < 4; q++) pv[j][q] = 0.f;
    float m0 = -1e30f, m1 = -1e30f, l0 = 0.f, l1 = 0.f;
    uint32_t qf[2][4][4];

    for (int kt = 0; kt < LL / 64; kt++) {
        CP_WAIT1();
        __syncthreads();
        if (kt == 0) {
            #pragma unroll
            for (int s = 0; s < 2; s++)
                #pragma unroll
                for (int ks = 0; ks < 4; ks++) {
                    int arow = wid * 16 + (lane & 15);
                    int acol = ks * 16 + ((lane >> 4) << 3);
                    LDSM4(qf[s][ks][0], qf[s][ks][1], qf[s][ks][2], qf[s][ks][3],
                          sb + s * QTILE + (uint32_t)(arow * 72 + acol) * 2);
                }
        }

        uint32_t sK = sb + AT_SOFF + (kt & 1) * AT_STG;
        uint32_t sV = sK + 2 * KVTILE;

        float sacc[8][4];
        #pragma unroll
        for (int j = 0; j < 8; j++)
            #pragma unroll
            for (int q = 0; q < 4; q++) sacc[j][q] = 0.f;

        #pragma unroll
        for (int ks = 0; ks < 4; ks++) {
            #pragma unroll
            for (int ntp = 0; ntp < 4; ntp++) {
                int g = lane >> 3;
                int brow = ntp * 16 + ((g & 2) << 2) + (lane & 7);
                int bcol = ks * 16 + ((g & 1) << 3);
                uint32_t boff = (uint32_t)(brow * 72 + bcol) * 2;
                uint32_t b0, b1, b2, b3;
                LDSM4(b0, b1, b2, b3, sK + 0 * KVTILE + boff);
                MMA16816(sacc[2*ntp],   qf[0][ks][0],qf[0][ks][1],qf[0][ks][2],qf[0][ks][3], b0,b1);
                MMA16816(sacc[2*ntp+1], qf[0][ks][0],qf[0][ks][1],qf[0][ks][2],qf[0][ks][3], b2,b3);
                MMA16816(sacc[2*ntp],   qf[1][ks][0],qf[1][ks][1],qf[1][ks][2],qf[1][ks][3], b0,b1);
                MMA16816(sacc[2*ntp+1], qf[1][ks][0],qf[1][ks][1],qf[1][ks][2],qf[1][ks][3], b2,b3);
                LDSM4(b0, b1, b2, b3, sK + 1 * KVTILE + boff);
                MMA16816(sacc[2*ntp],   qf[0][ks][0],qf[0][ks][1],qf[0][ks][2],qf[0][ks][3], b0,b1);
                MMA16816(sacc[2*ntp+1], qf[0][ks][0],qf[0][ks][1],qf[0][ks][2],qf[0][ks][3], b2,b3);
            }
        }

        float tm0 = -1e30f, tm1 = -1e30f;
        #pragma unroll
        for (int j = 0; j < 8; j++) {
            tm0 = fmaxf(tm0, fmaxf(sacc[j][0], sacc[j][1]));
            tm1 = fmaxf(tm1, fmaxf(sacc[j][2], sacc[j][3]));
        }
        tm0 = fmaxf(tm0, __shfl_xor_sync(0xffffffffu, tm0, 1));
        tm0 = fmaxf(tm0, __shfl_xor_sync(0xffffffffu, tm0, 2));
        tm1 = fmaxf(tm1, __shfl_xor_sync(0xffffffffu, tm1, 1));
        tm1 = fmaxf(tm1, __shfl_xor_sync(0xffffffffu, tm1, 2));
        tm0 *= 0.125f; tm1 *= 0.125f;
        float mn0 = fmaxf(m0, tm0), mn1 = fmaxf(m1, tm1);
        float al0 = __expf(m0 - mn0), al1 = __expf(m1 - mn1);
        m0 = mn0; m1 = mn1;

        float rs0 = 0.f, rs1 = 0.f;
        uint32_t pf[2][4][4];
        #pragma unroll
        for (int j = 0; j < 8; j++) {
            float p0 = __expf(sacc[j][0] * 0.125f - mn0);
            float p1 = __expf(sacc[j][1] * 0.125f - mn0);
            float p2 = __expf(sacc[j][2] * 0.125f - mn1);
            float p3 = __expf(sacc[j][3] * 0.125f - mn1);
            rs0 += p0 + p1; rs1 += p2 + p3;
            __half a0, a1, b0v, b1v, c0, c1, d0, d1;
            split2r(p0, a0, a1);
            split2r(p1, b0v, b1v);
            split2r(p2, c0, c1);
            split2r(p3, d0, d1);
            int ks = j >> 1, ri = (j & 1) * 2;
            pf[0][ks][ri]     = pkh(a0, b0v);
            pf[0][ks][ri + 1] = pkh(c0, d0);
            pf[1][ks][ri]     = pkh(a1, b1v);
            pf[1][ks][ri + 1] = pkh(c1, d1);
        }
        rs0 += __shfl_xor_sync(0xffffffffu, rs0, 1);
        rs0 += __shfl_xor_sync(0xffffffffu, rs0, 2);
        rs1 += __shfl_xor_sync(0xffffffffu, rs1, 1);
        rs1 += __shfl_xor_sync(0xffffffffu, rs1, 2);
        l0 = l0 * al0 + rs0;
        l1 = l1 * al1 + rs1;
        #pragma unroll
        for (int j = 0; j < 8; j++) {
            pv[j][0] *= al0; pv[j][1] *= al0;
            pv[j][2] *= al1; pv[j][3] *= al1;
        }

        #pragma unroll
        for (int ks = 0; ks < 4; ks++) {
            #pragma unroll
            for (int ntp = 0; ntp < 4; ntp++) {
                int g = lane >> 3;
                int vrow = ks * 16 + ((g & 1) << 3) + (lane & 7);
                int vcol = ntp * 16 + ((g >> 1) << 3);
                uint32_t voff = (uint32_t)(vrow * 72 + vcol) * 2;
                uint32_t v0, v1, v2, v3;
                LDSM4T(v0, v1, v2, v3, sV + 0 * KVTILE + voff);
                MMA16816(pv[2*ntp],   pf[0][ks][0],pf[0][ks][1],pf[0][ks][2],pf[0][ks][3], v0,v1);
                MMA16816(pv[2*ntp+1], pf[0][ks][0],pf[0][ks][1],pf[0][ks][2],pf[0][ks][3], v2,v3);
                MMA16816(pv[2*ntp],   pf[1][ks][0],pf[1][ks][1],pf[1][ks][2],pf[1][ks][3], v0,v1);
                MMA16816(pv[2*ntp+1], pf[1][ks][0],pf[1][ks][1],pf[1][ks][2],pf[1][ks][3], v2,v3);
                LDSM4T(v0, v1, v2, v3, sV + 1 * KVTILE + voff);
                MMA16816(pv[2*ntp],   pf[0][ks][0],pf[0][ks][1],pf[0][ks][2],pf[0][ks][3], v0,v1);
                MMA16816(pv[2*ntp+1], pf[0][ks][0],pf[0][ks][1],pf[0][ks][2],pf[0][ks][3], v2,v3);
            }
        }

        __syncthreads();
        if (kt + 2 < LL / 64) KV_LOAD(kt & 1, kt + 2);
        CP_COMMIT();
    }

    float inv0 = 1.f / l0, inv1 = 1.f / l1;
    int gr0 = b * LL + q0 + wid * 16 + (lane >> 2);
    #pragma unroll
    for (int j = 0; j < 8; j++) {
        int col = hh * 64 + j * 8 + ((lane & 3) << 1);
        store_split_pair(Z0, Z1, (size_t)gr0 * CC + col,
                         pv[j][0] * inv0, pv[j][1] * inv0);
        store_split_pair(Z0, Z1, (size_t)(gr0 + 8) * CC + col,
                         pv[j][2] * inv1, pv[j][3] * inv1);
    }
    #undef KV_LOAD
}

// ---------------- block reduce helper ----------------
__device__ __forceinline__ float blockReduceSum256(float v, float* red)
{
    int lane = threadIdx.x & 31, warp = threadIdx.x >> 5;
    #pragma unroll
    for (int o = 16; o; o >>= 1) v += __shfl_xor_sync(0xffffffffu, v, o);
    if (lane == 0) red[warp] = v;
    __syncthreads();
    if (warp == 0) {
        v = (lane < 8) ? red[lane] : 0.f;
        #pragma unroll
        for (int o = 4; o; o >>= 1) v += __shfl_xor_sync(0xffffffffu, v, o);
        if (lane == 0) red[0] = v;
    }
    __syncthreads();
    float r = red[0];
    __syncthreads();
    return r;
}

// ---------------- fused residual add + LayerNorm + router argmax ----------------
__global__ void __launch_bounds__(256)
add_ln_router_kernel(const float* __restrict__ qx, const float* __restrict__ att,
                     const float* __restrict__ w, const float* __restrict__ bb,
                     const float* __restrict__ Wsw, const float* __restrict__ bsw,
                     float* __restrict__ zn, int* __restrict__ route)
{
    __shared__ float red[8];
    __shared__ float esum[8][EE];
    int row = blockIdx.x, tid = threadIdx.x;
    int lane = tid & 31, warp = tid >> 5;
    const float4* xq = (const float4*)(qx  + (size_t)row * CC);
    const float4* aq = (const float4*)(att + (size_t)row * CC);
    float4 x = xq[tid], a = aq[tid];
    float4 v; v.x = x.x + a.x; v.y = x.y + a.y; v.z = x.z + a.z; v.w = x.w + a.w;
    float mean = blockReduceSum256(v.x + v.y + v.z + v.w, red) * (1.f/1024.f);
    float dx = v.x - mean, dy = v.y - mean, dz = v.z - mean, dw = v.w - mean;
    float var = blockReduceSum256(dx*dx + dy*dy + dz*dz + dw*dw, red) * (1.f/1024.f);
    float rs = rsqrtf(var + 1e-5f);
    float4 wv = ((const float4*)w)[tid];
    float4 bv = ((const float4*)bb)[tid];
    float4 o;
    o.x = dx*rs*wv.x + bv.x; o.y = dy*rs*wv.y + bv.y;
    o.z = dz*rs*wv.z + bv.z; o.w = dw*rs*wv.w + bv.w;
    ((float4*)(zn + (size_t)row * CC))[tid] = o;

    int c = tid * 4;
    #pragma unroll
    for (int e = 0; e < EE; e++) {
        float4 we = *(const float4*)(Wsw + (size_t)e * CC + c);
        float p = o.x*we.x + o.y*we.y + o.z*we.z + o.w*we.w;
        #pragma unroll
        for (int of = 16; of; of >>= 1) p += __shfl_xor_sync(0xffffffffu, p, of);
        if (lane == 0) esum[warp][e] = p;
    }
    __syncthreads();
    if (tid == 0) {
        float best = -1e30f; int bi = 0;
        #pragma unroll
        for (int e = 0; e < EE; e++) {
            float lg = esum[0][e] + esum[1][e] + esum[2][e] + esum[3][e]
                     + esum[4][e] + esum[5][e] + esum[6][e] + esum[7][e] + bsw[e];
            if (lg > best) { best = lg; bi = e; }
        }
        route[row] = bi;
    }
}

// ---------------- deterministic per-expert prefix positions + inverse map ----
__global__ void __launch_bounds__(256)
scanpos_kernel(const int* __restrict__ route, int* __restrict__ pos,
               int* __restrict__ slot2tok)
{
    int e = blockIdx.x;
    int tid = threadIdx.x;
    int lane = tid & 31, warp = tid >> 5;
    __shared__ int wtot[8];
    __shared__ int running;
    if (tid == 0) running = 0;
    if (tid < CAPP) {
        slot2tok[e * CAPP + tid] = -1;
    }
    __syncthreads();
    for (int base = 0; base < NTOK; base += 256) {
        int tok = base + tid;
        int flag = (route[tok] == e);
        unsigned m = __ballot_sync(0xffffffffu, flag);
        int rank = __popc(m & ((1u << lane) - 1u));
        if (lane == 31) wtot[warp] = __popc(m);
        __syncthreads();
        int prefix = 0;
        for (int w = 0; w < warp; w++) prefix += wtot[w];
        if (flag) {
            int p = running + prefix + rank;
            pos[tok] = p;
            if (p < CAPP) slot2tok[e * CAPP + p] = tok;
        }
        __syncthreads();
        if (tid == 0) {
            int t = 0;
            for (int w = 0; w < 8; w++) t += wtot[w];
            running += t;
        }
        __syncthreads();
    }
}

// ---------------- gather kept tokens into expert buffers ----------------
__global__ void __launch_bounds__(256)
gather_kernel(const float* __restrict__ zn, const int* __restrict__ route,
              const int* __restrict__ pos, float* __restrict__ eb)
{
    int tok = blockIdx.x;
    int p = pos[tok];
    if (p >= CAPP) return;
    size_t slot = (size_t)route[tok] * CAPP + p;
    ((float4*)(eb + slot * CC))[threadIdx.x] =
        ((const float4*)(zn + (size_t)tok * CC))[threadIdx.x];
}

// ---------------- expert FFN layer 1 ----------------
__global__ void __launch_bounds__(256)
ffn1_kernel(const float* __restrict__ eb, const float* __restrict__ W1,
            const float* __restrict__ b1, float* __restrict__ h)
{
    int blk = blockIdx.x;
    int e  = blk >> 6;
    int r0 = (blk & 63) * 4;
    __shared__ float xs[4][CC];
    __shared__ float red[4][4][HIDD];
    int tid = threadIdx.x;
    const float4* src = (const float4*)(eb + ((size_t)e*CAPP + r0) * CC);
    for (int i = tid; i < 4 * (CC/4); i += 256)
        ((float4*)xs)[i] = src[i];
    __syncthreads();
    int kp = tid >> 6;
    int n  = tid & 63;
    float acc[4] = {};
    const float* w = W1 + (size_t)e * CC * HIDD + n;
    #pragma unroll 4
    for (int k = kp; k < CC; k += 4) {
        float wv = w[(size_t)k * HIDD];
        #pragma unroll
        for (int r = 0; r < 4; r++) acc[r] += xs[r][k] * wv;
    }
    #pragma unroll
    for (int r = 0; r < 4; r++) red[kp][r][n] = acc[r];
    __syncthreads();
    {
        int r = tid >> 6, n2 = tid & 63;
        float s = red[0][r][n2] + red[1][r][n2] + red[2][r][n2] + red[3][r][n2]
                + b1[e*HIDD + n2];
        h[((size_t)e*CAPP + r0 + r) * HIDD + n2] = fmaxf(s, 0.f);
    }
}

// ---------------- expert FFN layer 2 fused with finalize (kept tokens) -------
__global__ void __launch_bounds__(256)
ffn2_out_kernel(const float* __restrict__ h, const float* __restrict__ W2,
                const float* __restrict__ b2, const int* __restrict__ slot2tok,
                const float* __restrict__ zn, float* __restrict__ out)
{
    int blk = blockIdx.x;
    int e  = blk >> 6;
    int r0 = (blk & 63) * 4;
    __shared__ float hs[4][HIDD];
    __shared__ int toks[4];
    int tid = threadIdx.x;
    hs[tid >> 6][tid & 63] = h[((size_t)e*CAPP + r0 + (tid >> 6)) * HIDD + (tid & 63)];
    if (tid < 4) toks[tid] = slot2tok[e * CAPP + r0 + tid];
    __syncthreads();
    int c = tid * 4;
    float4 acc[4];
    #pragma unroll
    for (int r = 0; r < 4; r++) { acc[r].x=0.f; acc[r].y=0.f; acc[r].z=0.f; acc[r].w=0.f; }
    const float* w = W2 + (size_t)e * HIDD * CC + c;
    #pragma unroll 8
    for (int k = 0; k < HIDD; k++) {
        float4 wv = *(const float4*)(w + (size_t)k * CC);
        #pragma unroll
        for (int r = 0; r < 4; r++) {
            float hv = hs[r][k];
            acc[r].x += hv*wv.x; acc[r].y += hv*wv.y;
            acc[r].z += hv*wv.z; acc[r].w += hv*wv.w;
        }
    }
    float4 bb = *(const float4*)(b2 + (size_t)e * CC + c);
    #pragma unroll
    for (int r = 0; r < 4; r++) {
        int tok = toks[r];
        if (tok < 0) continue;
        float4 z = *(const float4*)(zn + (size_t)tok * CC + c);
        float4 o;
        o.x = z.x + acc[r].x + bb.x; o.y = z.y + acc[r].y + bb.y;
        o.z = z.z + acc[r].z + bb.z; o.w = z.w + acc[r].w + bb.w;
        *(float4*)(out + (size_t)tok * CC + c) = o;
    }
}

// ---------------- dropped tokens: out = 2*zn ----------------
__global__ void __launch_bounds__(256)
finalize_dropped_kernel(const float* __restrict__ zn, const int* __restrict__ pos,
                        float* __restrict__ out)
{
    int tok = blockIdx.x, tid = threadIdx.x;
    if (pos[tok] < CAPP) return;
    float4 z = ((const float4*)(zn + (size_t)tok * CC))[tid];
    float4 o = {2.f*z.x, 2.f*z.y, 2.f*z.z, 2.f*z.w};
    ((float4*)(out + (size_t)tok * CC))[tid] = o;
}

__global__ void fill_ones_kernel(float* __restrict__ p, int n)
{
    int i = blockIdx.x * 256 + threadIdx.x;
    if (i < n) p[i] = 1.0f;
}

// ---------------- launch (multi-stream DAG) ----------------
extern "C" void kernel_launch(void* const* d_in, const int* in_sizes, int n_in,
                              void* d_out, int out_size)
{
    const float* qx  = (const float*)d_in[0];
    const float* kx  = (const float*)d_in[1];
    const float* vx  = (const float*)d_in[2];
    const float* WQ  = (const float*)d_in[4];
    const float* bQ  = (const float*)d_in[5];
    const float* WK  = (const float*)d_in[6];
    const float* bK  = (const float*)d_in[7];
    const float* WV  = (const float*)d_in[8];
    const float* bV  = (const float*)d_in[9];
    const float* WO  = (const float*)d_in[10];
    const float* bO  = (const float*)d_in[11];
    const float* ln1w= (const float*)d_in[12];
    const float* ln1b= (const float*)d_in[13];
    const float* Wsw = (const float*)d_in[14];
    const float* bsw = (const float*)d_in[15];
    const float* W1  = (const float*)d_in[16];
    const float* b1  = (const float*)d_in[17];
    const float* W2  = (const float*)d_in[18];
    const float* b2  = (const float*)d_in[19];
    float* out = (float*)d_out;

    float *pA, *pzn, *peb, *ph;
    int *proute, *ppos, *ps2t;
    cudaGetSymbolAddress((void**)&pA,  g_A);
    cudaGetSymbolAddress((void**)&pzn, g_zn);
    cudaGetSymbolAddress((void**)&peb, g_eb);
    cudaGetSymbolAddress((void**)&ph,  g_h);
    cudaGetSymbolAddress((void**)&proute, g_route);
    cudaGetSymbolAddress((void**)&ppos,   g_pos);
    cudaGetSymbolAddress((void**)&ps2t,   g_slot2tok);

    __half *xq[2], *xk[2], *xv[2];
    __half *wq[2], *wk[2], *wv[2], *wo[2];
    __half *oq[2], *ok[2], *ov[2];
    cudaGetSymbolAddress((void**)&xq[0], g_xq0); cudaGetSymbolAddress((void**)&xq[1], g_xq1);
    cudaGetSymbolAddress((void**)&xk[0], g_xk0); cudaGetSymbolAddress((void**)&xk[1], g_xk1);
    cudaGetSymbolAddress((void**)&xv[0], g_xv0); cudaGetSymbolAddress((void**)&xv[1], g_xv1);
    cudaGetSymbolAddress((void**)&wq[0], g_wq0); cudaGetSymbolAddress((void**)&wq[1], g_wq1);
    cudaGetSymbolAddress((void**)&wk[0], g_wk0); cudaGetSymbolAddress((void**)&wk[1], g_wk1);
    cudaGetSymbolAddress((void**)&wv[0], g_wv0); cudaGetSymbolAddress((void**)&wv[1], g_wv1);
    cudaGetSymbolAddress((void**)&wo[0], g_wo0); cudaGetSymbolAddress((void**)&wo[1], g_wo1);
    cudaGetSymbolAddress((void**)&oq[0], g_q0);  cudaGetSymbolAddress((void**)&oq[1], g_q1);
    cudaGetSymbolAddress((void**)&ok[0], g_k0);  cudaGetSymbolAddress((void**)&ok[1], g_k1);
    cudaGetSymbolAddress((void**)&ov[0], g_v0);  cudaGetSymbolAddress((void**)&ov[1], g_v1);

    cudaFuncSetAttribute(mma_gemm,   cudaFuncAttributeMaxDynamicSharedMemorySize, GEMM_SMEM);
    cudaFuncSetAttribute(mma_gemm_s, cudaFuncAttributeMaxDynamicSharedMemorySize, GEMM_SMEM);
    cudaFuncSetAttribute(attn_mma,   cudaFuncAttributeMaxDynamicSharedMemorySize, ATTN_SMEM);

    const int NX4 = NTOK * CC / 4;
    const int NW4 = CC * CC / 4;
    dim3 gemmGrid(CC/128, NTOK/128);

    cudaStream_t s1, s2;
    cudaStreamCreateWithFlags(&s1, cudaStreamNonBlocking);
    cudaStreamCreateWithFlags(&s2, cudaStreamNonBlocking);
    cudaEvent_t evFork, evK, evV, evWO, evJ1, evJ2;
    cudaEventCreateWithFlags(&evFork, cudaEventDisableTiming);
    cudaEventCreateWithFlags(&evK,    cudaEventDisableTiming);
    cudaEventCreateWithFlags(&evV,    cudaEventDisableTiming);
    cudaEventCreateWithFlags(&evWO,   cudaEventDisableTiming);
    cudaEventCreateWithFlags(&evJ1,   cudaEventDisableTiming);
    cudaEventCreateWithFlags(&evJ2,   cudaEventDisableTiming);

    // fork
    cudaEventRecord(evFork, 0);
    cudaStreamWaitEvent(s1, evFork, 0);
    cudaStreamWaitEvent(s2, evFork, 0);

    // s0: Q pipeline
    split2_kernel<<<NX4/256, 256>>>(qx, xq[0], xq[1], NX4);
    split2_kernel<<<NW4/256, 256>>>(WQ, wq[0], wq[1], NW4);
    mma_gemm_s<<<gemmGrid, 256, GEMM_SMEM, 0>>>(
        xq[0], xq[1], wq[0], wq[1], bQ, oq[0], oq[1]);

    // s1: K pipeline, then WO split
    split2_kernel<<<NX4/256, 256, 0, s1>>>(kx, xk[0], xk[1], NX4);
    split2_kernel<<<NW4/256, 256, 0, s1>>>(WK, wk[0], wk[1], NW4);
    mma_gemm_s<<<gemmGrid, 256, GEMM_SMEM, s1>>>(
        xk[0], xk[1], wk[0], wk[1], bK, ok[0], ok[1]);
    cudaEventRecord(evK, s1);
    split2_kernel<<<NW4/256, 256, 0, s1>>>(WO, wo[0], wo[1], NW4);
    cudaEventRecord(evWO, s1);

    // s2: tuple memcpys (independent) then V pipeline
    long long os = (long long)out_size;
    if (os >= (long long)(2 * NCE)) {
        cudaMemcpyAsync(out + NCE, kx, NCE * sizeof(float),
                        cudaMemcpyDeviceToDevice, s2);
    }
    if (os >= (long long)(3 * NCE)) {
        cudaMemcpyAsync(out + 2 * NCE, vx, NCE * sizeof(float),
                        cudaMemcpyDeviceToDevice, s2);
    }
    long long rem = os - (long long)(3 * NCE);
    if (rem > 0) {
        fill_ones_kernel<<<(int)((rem + 255) / 256), 256, 0, s2>>>(
            out + 3 * NCE, (int)rem);
    }
    split2_kernel<<<NX4/256, 256, 0, s2>>>(vx, xv[0], xv[1], NX4);
    split2_kernel<<<NW4/256, 256, 0, s2>>>(WV, wv[0], wv[1], NW4);
    mma_gemm_s<<<gemmGrid, 256, GEMM_SMEM, s2>>>(
        xv[0], xv[1], wv[0], wv[1], bV, ov[0], ov[1]);
    cudaEventRecord(evV, s2);

    // s0: attention waits on K and V
    cudaStreamWaitEvent(0, evK, 0);
    cudaStreamWaitEvent(0, evV, 0);
    attn_mma<<<dim3(LL/128, BB*HH), 256, ATTN_SMEM, 0>>>(
        oq[0], oq[1], ok[0], ok[1], ov[0], ov[1], xq[0], xq[1]);

    // s0: WO GEMM waits on WO split
    cudaStreamWaitEvent(0, evWO, 0);
    mma_gemm<<<gemmGrid, 256, GEMM_SMEM, 0>>>(
        xq[0], xq[1], wo[0], wo[1], bO, pA);

    add_ln_router_kernel<<<NTOK, 256>>>(qx, pA, ln1w, ln1b, Wsw, bsw, pzn, proute);
    scanpos_kernel<<<EE, 256>>>(proute, ppos, ps2t);
    gather_kernel<<<NTOK, 256>>>(pzn, proute, ppos, peb);
    ffn1_kernel<<<EE * (CAPP/4), 256>>>(peb, W1, b1, ph);
    ffn2_out_kernel<<<EE * (CAPP/4), 256>>>(ph, W2, b2, ps2t, pzn, out);
    finalize_dropped_kernel<<<NTOK, 256>>>(pzn, ppos, out);

    // join side streams back into s0 before returning
    cudaEventRecord(evJ1, s1);
    cudaEventRecord(evJ2, s2);
    cudaStreamWaitEvent(0, evJ1, 0);
    cudaStreamWaitEvent(0, evJ2, 0);

    cudaEventDestroy(evFork);
    cudaEventDestroy(evK);
    cudaEventDestroy(evV);
    cudaEventDestroy(evWO);
    cudaEventDestroy(evJ1);
    cudaEventDestroy(evJ2);
    cudaStreamDestroy(s1);
    cudaStreamDestroy(s2);
}

// round 15
// speedup vs baseline: 1.6450x; 1.0092x over previous
#include <cuda_runtime.h>
#include <cuda_fp16.h>
#include <math.h>
#include <stdint.h>

// ---------------- problem constants ----------------
#define BB 8
#define LL 1024
#define CC 1024
#define HH 16
#define DKK 64
#define NTOK (BB*LL)            // 8192
#define EE 16
#define HIDD 64
#define CAPP 256
#define NCE ((size_t)NTOK * CC)

// ---------------- baseline-PTX tensor-core helpers (sm_80+) ----------------
__device__ __forceinline__ uint32_t smem_u32(const void* p) {
    uint32_t a;
    asm("{ .reg .u64 t; cvta.to.shared.u64 t, %1; cvt.u32.u64 %0, t; }" : "=r"(a) : "l"(p));
    return a;
}
#define LDSM4(d0, d1, d2, d3, a) \
    asm volatile("ldmatrix.sync.aligned.m8n8.x4.shared.b16 {%0,%1,%2,%3}, [%4];" \
        : "=r"(d0), "=r"(d1), "=r"(d2), "=r"(d3) : "r"(a))
#define LDSM4T(d0, d1, d2, d3, a) \
    asm volatile("ldmatrix.sync.aligned.m8n8.x4.trans.shared.b16 {%0,%1,%2,%3}, [%4];" \
        : "=r"(d0), "=r"(d1), "=r"(d2), "=r"(d3) : "r"(a))
#define MMA16816(c, a0, a1, a2, a3, b0, b1) \
    asm volatile("mma.sync.aligned.m16n8k16.row.col.f32.f16.f16.f32 " \
        "{%0,%1,%2,%3}, {%4,%5,%6,%7}, {%8,%9}, {%0,%1,%2,%3};" \
        : "+f"((c)[0]), "+f"((c)[1]), "+f"((c)[2]), "+f"((c)[3]) \
        : "r"(a0), "r"(a1), "r"(a2), "r"(a3), "r"(b0), "r"(b1))
#define CP_ASYNC16(dst, src) \
    asm volatile("cp.async.cg.shared.global [%0], [%1], 16;" :: "r"(dst), "l"(src))
#define CP_COMMIT() asm volatile("cp.async.commit_group;" ::: "memory")
#define CP_WAIT1()  asm volatile("cp.async.wait_group 1;" ::: "memory")

// ---------------- fp16 2-term split helpers ----------------
__device__ __forceinline__ void split2r(float a, __half& h0, __half& h1)
{
    h0 = __float2half_rn(a);
    h1 = __float2half_rn(a - __half2float(h0));
}
__device__ __forceinline__ uint32_t pkh(__half lo, __half hi)
{
    __half2 t = __halves2half2(lo, hi);
    return *reinterpret_cast<uint32_t*>(&t);
}
__device__ __forceinline__ void store_split_pair(
    __half* Y0, __half* Y1, size_t off, float e0, float e1)
{
    __half a0, a1, b0, b1;
    split2r(e0, a0, a1);
    split2r(e1, b0, b1);
    *(uint32_t*)(Y0 + off) = pkh(a0, b0);
    *(uint32_t*)(Y1 + off) = pkh(a1, b1);
}

// ---------------- scratch ----------------
__device__ float g_A [NTOK * CC];
__device__ float g_zn[NTOK * CC];
__device__ float g_h [EE * CAPP * HIDD];
__device__ int   g_route[NTOK];
__device__ int   g_pos  [NTOK];
__device__ int   g_slot2tok[EE * CAPP];
__device__ __half g_xq0[NTOK*CC], g_xq1[NTOK*CC];
__device__ __half g_xk0[NTOK*CC], g_xk1[NTOK*CC];
__device__ __half g_xv0[NTOK*CC], g_xv1[NTOK*CC];
__device__ __half g_wq0[CC*CC], g_wq1[CC*CC];
__device__ __half g_wk0[CC*CC], g_wk1[CC*CC];
__device__ __half g_wv0[CC*CC], g_wv1[CC*CC];
__device__ __half g_wo0[CC*CC], g_wo1[CC*CC];
__device__ __half g_q0[NTOK*CC], g_q1[NTOK*CC];
__device__ __half g_k0[NTOK*CC], g_k1[NTOK*CC];
__device__ __half g_v0[NTOK*CC], g_v1[NTOK*CC];

// ---------------- fp32 -> 2x fp16 split ----------------
__global__ void __launch_bounds__(256)
split2_kernel(const float* __restrict__ in, __half* __restrict__ o0,
              __half* __restrict__ o1, int n4)
{
    int i = blockIdx.x * 256 + threadIdx.x;
    if (i >= n4) return;
    float4 v = ((const float4*)in)[i];
    float a[4] = {v.x, v.y, v.z, v.w};
    union { __half b[4]; uint2 u; } s0, s1;
    #pragma unroll
    for (int j = 0; j < 4; j++) split2r(a[j], s0.b[j], s1.b[j]);
    ((uint2*)o0)[i] = s0.u;
    ((uint2*)o1)[i] = s1.u;
}

// ---------------- HMMA GEMM core (fp16x3), 2-stage, 2 CTAs/SM ----------------
#define APAD 40
#define TILE_B (128 * APAD * 2)     // 10240
#define STAGE4 (4 * TILE_B)         // 40960
#define GEMM_SMEM (2 * STAGE4)      // 81920
#define NCHUNK 32

template <int OutMode>
__device__ __forceinline__ void gemm_core(
    const __half* __restrict__ X0, const __half* __restrict__ X1,
    const __half* __restrict__ W0, const __half* __restrict__ W1,
    const float* __restrict__ bias,
    float* __restrict__ Yf,
    __half* __restrict__ Y0, __half* __restrict__ Y1,
    char* smem)
{
    const uint32_t sb = smem_u32(smem);
    const int tid = threadIdx.x, wid = tid >> 5, lane = tid & 31;
    const int bm = blockIdx.y * 128, bn = blockIdx.x * 128;
    const int wm = (wid >> 2) * 64, wn = (wid & 3) * 32;

    const __half* TS[4] = {X0, X1, W0, W1};

    #define G_LOAD(buf, ch) do { \
        int ko_ = (ch) * 32; \
        _Pragma("unroll") \
        for (int j_ = 0; j_ < 8; j_++) { \
            int e_ = j_ * 256 + tid; \
            int t_ = e_ >> 9; \
            int w_ = e_ & 511; \
            int r_ = w_ >> 2, c8_ = (w_ & 3) * 8; \
            int rowb_ = ((t_ < 2) ? bm : bn) + r_; \
            CP_ASYNC16(sb + (buf) * STAGE4 + t_ * TILE_B + (r_ * APAD + c8_) * 2, \
                       TS[t_] + (size_t)rowb_ * CC + ko_ + c8_); \
        } \
    } while (0)

    float acc[4][4][4];
    #pragma unroll
    for (int i = 0; i < 4; i++)
        #pragma unroll
        for (int j = 0; j < 4; j++)
            #pragma unroll
            for (int q = 0; q < 4; q++) acc[i][j][q] = 0.f;

    G_LOAD(0, 0); CP_COMMIT();
    G_LOAD(1, 1); CP_COMMIT();

    for (int c = 0; c < NCHUNK; c++) {
        int buf = c & 1;
        CP_WAIT1();
        __syncthreads();

        uint32_t stage = sb + buf * STAGE4;
        #pragma unroll
        for (int kk = 0; kk < 2; kk++) {
            uint32_t a[2][4][4];
            #pragma unroll
            for (int s = 0; s < 2; s++)
                #pragma unroll
                for (int i = 0; i < 4; i++) {
                    int arow = wm + i * 16 + (lane & 15);
                    int acol = kk * 16 + ((lane >> 4) << 3);
                    LDSM4(a[s][i][0], a[s][i][1], a[s][i][2], a[s][i][3],
                          stage + s * TILE_B + (uint32_t)(arow * APAD + acol) * 2);
                }
            #pragma unroll
            for (int jp = 0; jp < 2; jp++) {
                int g = lane >> 3;
                int brow = wn + jp * 16 + ((g & 2) << 2) + (lane & 7);
                int bcol = kk * 16 + ((g & 1) << 3);
                uint32_t boff = (uint32_t)(brow * APAD + bcol) * 2;
                uint32_t b0, b1, b2, b3;
                LDSM4(b0, b1, b2, b3, stage + 2 * TILE_B + boff);
                #pragma unroll
                for (int i = 0; i < 4; i++) {
                    MMA16816(acc[i][2*jp],   a[0][i][0],a[0][i][1],a[0][i][2],a[0][i][3], b0,b1);
                    MMA16816(acc[i][2*jp+1], a[0][i][0],a[0][i][1],a[0][i][2],a[0][i][3], b2,b3);
                    MMA16816(acc[i][2*jp],   a[1][i][0],a[1][i][1],a[1][i][2],a[1][i][3], b0,b1);
                    MMA16816(acc[i][2*jp+1], a[1][i][0],a[1][i][1],a[1][i][2],a[1][i][3], b2,b3);
                }
                LDSM4(b0, b1, b2, b3, stage + 3 * TILE_B + boff);
                #pragma unroll
                for (int i = 0; i < 4; i++) {
                    MMA16816(acc[i][2*jp],   a[0][i][0],a[0][i][1],a[0][i][2],a[0][i][3], b0,b1);
                    MMA16816(acc[i][2*jp+1], a[0][i][0],a[0][i][1],a[0][i][2],a[0][i][3], b2,b3);
                }
            }
        }
        __syncthreads();
        if (c + 2 < NCHUNK) {
            G_LOAD(buf, c + 2);
        }
        CP_COMMIT();
    }

    #pragma unroll
    for (int i = 0; i < 4; i++) {
        int row = bm + wm + i * 16 + (lane >> 2);
        #pragma unroll
        for (int j = 0; j < 4; j++) {
            int col = bn + wn + j * 8 + ((lane & 3) << 1);
            float bx = bias[col], by = bias[col + 1];
            float e0 = acc[i][j][0] + bx, e1 = acc[i][j][1] + by;
            float e2 = acc[i][j][2] + bx, e3 = acc[i][j][3] + by;
            if (OutMode == 0) {
                float2 v0 = {e0, e1};
                float2 v1 = {e2, e3};
                *(float2*)(Yf + (size_t)row * CC + col) = v0;
                *(float2*)(Yf + (size_t)(row + 8) * CC + col) = v1;
            } else {
                store_split_pair(Y0, Y1, (size_t)row * CC + col, e0, e1);
                store_split_pair(Y0, Y1, (size_t)(row + 8) * CC + col, e2, e3);
            }
        }
    }
    #undef G_LOAD
}

__global__ void __launch_bounds__(256, 2)
mma_gemm(const __half* __restrict__ X0, const __half* __restrict__ X1,
         const __half* __restrict__ W0, const __half* __restrict__ W1,
         const float* __restrict__ bias, float* __restrict__ Y)
{
    extern __shared__ char smem[];
    gemm_core<0>(X0, X1, W0, W1, bias, Y, nullptr, nullptr, smem);
}

__global__ void __launch_bounds__(256, 2)
mma_gemm_s(const __half* __restrict__ X0, const __half* __restrict__ X1,
           const __half* __restrict__ W0, const __half* __restrict__ W1,
           const float* __restrict__ bias,
           __half* __restrict__ Y0, __half* __restrict__ Y1)
{
    extern __shared__ char smem[];
    gemm_core<1>(X0, X1, W0, W1, bias, nullptr, Y0, Y1, smem);
}

// ---------------- flash attention on HMMA (fp16x3) ----------------
#define QTILE (128 * 72 * 2)      // 18432
#define KVTILE (64 * 72 * 2)      // 9216
#define AT_SOFF (2 * QTILE)       // 36864
#define AT_STG (4 * KVTILE)       // 36864
#define ATTN_SMEM (AT_SOFF + 2 * AT_STG)   // 110592

__global__ void __launch_bounds__(256)
attn_mma(const __half* __restrict__ Q0, const __half* __restrict__ Q1,
         const __half* __restrict__ K0, const __half* __restrict__ K1,
         const __half* __restrict__ V0, const __half* __restrict__ V1,
         __half* __restrict__ Z0, __half* __restrict__ Z1)
{
    extern __shared__ char smem[];
    const uint32_t sb = smem_u32(smem);
    const int tid = threadIdx.x, wid = tid >> 5, lane = tid & 31;
    const int bh = blockIdx.y;
    const int b = bh >> 4, hh = bh & 15;
    const int q0 = blockIdx.x * 128;

    const __half* QS[2] = {Q0, Q1};
    const __half* KS[2] = {K0, K1};
    const __half* VS[2] = {V0, V1};

    #pragma unroll
    for (int j = 0; j < 8; j++) {
        int e = j * 256 + tid;
        int t = e >> 10;
        int w = e & 1023;
        int r = w >> 3, c = w & 7;
        CP_ASYNC16(sb + t * QTILE + (uint32_t)(r * 72 + c * 8) * 2,
                   QS[t] + (size_t)(b * LL + q0 + r) * CC + hh * 64 + c * 8);
    }

    #define KV_LOAD(buf, kt) do { \
        _Pragma("unroll") \
        for (int j_ = 0; j_ < 8; j_++) { \
            int e_ = j_ * 256 + tid; \
            int t_ = e_ >> 9; \
            int w_ = e_ & 511; \
            int r_ = w_ >> 3, c_ = w_ & 7; \
            const __half* src_ = (t_ < 2) ? KS[t_] : VS[t_ - 2]; \
            CP_ASYNC16(sb + AT_SOFF + (buf) * AT_STG + t_ * KVTILE + \
                       (uint32_t)(r_ * 72 + c_ * 8) * 2, \
                       src_ + (size_t)(b * LL + (kt) * 64 + r_) * CC + hh * 64 + c_ * 8); \
        } \
    } while (0)

    KV_LOAD(0, 0); CP_COMMIT();
    KV_LOAD(1, 1); CP_COMMIT();

    float pv[8][4];
    #pragma unroll
    for (int j = 0; j < 8; j++)
        #pragma unroll
        for (int q = 0; q < 4; q++) pv[j][q] = 0.f;
    float m0 = -1e30f, m1 = -1e30f, l0 = 0.f, l1 = 0.f;
    uint32_t qf[2][4][4];

    for (int kt = 0; kt < LL / 64; kt++) {
        CP_WAIT1();
        __syncthreads();
        if (kt == 0) {
            #pragma unroll
            for (int s = 0; s < 2; s++)
                #pragma unroll
                for (int ks = 0; ks < 4; ks++) {
                    int arow = wid * 16 + (lane & 15);
                    int acol = ks * 16 + ((lane >> 4) << 3);
                    LDSM4(qf[s][ks][0], qf[s][ks][1], qf[s][ks][2], qf[s][ks][3],
                          sb + s * QTILE + (uint32_t)(arow * 72 + acol) * 2);
                }
        }

        uint32_t sK = sb + AT_SOFF + (kt & 1) * AT_STG;
        uint32_t sV = sK + 2 * KVTILE;

        float sacc[8][4];
        #pragma unroll
        for (int j = 0; j < 8; j++)
            #pragma unroll
            for (int q = 0; q < 4; q++) sacc[j][q] = 0.f;

        #pragma unroll
        for (int ks = 0; ks < 4; ks++) {
            #pragma unroll
            for (int ntp = 0; ntp < 4; ntp++) {
                int g = lane >> 3;
                int brow = ntp * 16 + ((g & 2) << 2) + (lane & 7);
                int bcol = ks * 16 + ((g & 1) << 3);
                uint32_t boff = (uint32_t)(brow * 72 + bcol) * 2;
                uint32_t b0, b1, b2, b3;
                LDSM4(b0, b1, b2, b3, sK + 0 * KVTILE + boff);
                MMA16816(sacc[2*ntp],   qf[0][ks][0],qf[0][ks][1],qf[0][ks][2],qf[0][ks][3], b0,b1);
                MMA16816(sacc[2*ntp+1], qf[0][ks][0],qf[0][ks][1],qf[0][ks][2],qf[0][ks][3], b2,b3);
                MMA16816(sacc[2*ntp],   qf[1][ks][0],qf[1][ks][1],qf[1][ks][2],qf[1][ks][3], b0,b1);
                MMA16816(sacc[2*ntp+1], qf[1][ks][0],qf[1][ks][1],qf[1][ks][2],qf[1][ks][3], b2,b3);
                LDSM4(b0, b1, b2, b3, sK + 1 * KVTILE + boff);
                MMA16816(sacc[2*ntp],   qf[0][ks][0],qf[0][ks][1],qf[0][ks][2],qf[0][ks][3], b0,b1);
                MMA16816(sacc[2*ntp+1], qf[0][ks][0],qf[0][ks][1],qf[0][ks][2],qf[0][ks][3], b2,b3);
            }
        }

        float tm0 = -1e30f, tm1 = -1e30f;
        #pragma unroll
        for (int j = 0; j < 8; j++) {
            tm0 = fmaxf(tm0, fmaxf(sacc[j][0], sacc[j][1]));
            tm1 = fmaxf(tm1, fmaxf(sacc[j][2], sacc[j][3]));
        }
        tm0 = fmaxf(tm0, __shfl_xor_sync(0xffffffffu, tm0, 1));
        tm0 = fmaxf(tm0, __shfl_xor_sync(0xffffffffu, tm0, 2));
        tm1 = fmaxf(tm1, __shfl_xor_sync(0xffffffffu, tm1, 1));
        tm1 = fmaxf(tm1, __shfl_xor_sync(0xffffffffu, tm1, 2));
        tm0 *= 0.125f; tm1 *= 0.125f;
        float mn0 = fmaxf(m0, tm0), mn1 = fmaxf(m1, tm1);
        float al0 = __expf(m0 - mn0), al1 = __expf(m1 - mn1);
        m0 = mn0; m1 = mn1;

        float rs0 = 0.f, rs1 = 0.f;
        uint32_t pf[2][4][4];
        #pragma unroll
        for (int j = 0; j < 8; j++) {
            float p0 = __expf(sacc[j][0] * 0.125f - mn0);
            float p1 = __expf(sacc[j][1] * 0.125f - mn0);
            float p2 = __expf(sacc[j][2] * 0.125f - mn1);
            float p3 = __expf(sacc[j][3] * 0.125f - mn1);
            rs0 += p0 + p1; rs1 += p2 + p3;
            __half a0, a1, b0v, b1v, c0, c1, d0, d1;
            split2r(p0, a0, a1);
            split2r(p1, b0v, b1v);
            split2r(p2, c0, c1);
            split2r(p3, d0, d1);
            int ks = j >> 1, ri = (j & 1) * 2;
            pf[0][ks][ri]     = pkh(a0, b0v);
            pf[0][ks][ri + 1] = pkh(c0, d0);
            pf[1][ks][ri]     = pkh(a1, b1v);
            pf[1][ks][ri + 1] = pkh(c1, d1);
        }
        rs0 += __shfl_xor_sync(0xffffffffu, rs0, 1);
        rs0 += __shfl_xor_sync(0xffffffffu, rs0, 2);
        rs1 += __shfl_xor_sync(0xffffffffu, rs1, 1);
        rs1 += __shfl_xor_sync(0xffffffffu, rs1, 2);
        l0 = l0 * al0 + rs0;
        l1 = l1 * al1 + rs1;
        #pragma unroll
        for (int j = 0; j < 8; j++) {
            pv[j][0] *= al0; pv[j][1] *= al0;
            pv[j][2] *= al1; pv[j][3] *= al1;
        }

        #pragma unroll
        for (int ks = 0; ks < 4; ks++) {
            #pragma unroll
            for (int ntp = 0; ntp < 4; ntp++) {
                int g = lane >> 3;
                int vrow = ks * 16 + ((g & 1) << 3) + (lane & 7);
                int vcol = ntp * 16 + ((g >> 1) << 3);
                uint32_t voff = (uint32_t)(vrow * 72 + vcol) * 2;
                uint32_t v0, v1, v2, v3;
                LDSM4T(v0, v1, v2, v3, sV + 0 * KVTILE + voff);
                MMA16816(pv[2*ntp],   pf[0][ks][0],pf[0][ks][1],pf[0][ks][2],pf[0][ks][3], v0,v1);
                MMA16816(pv[2*ntp+1], pf[0][ks][0],pf[0][ks][1],pf[0][ks][2],pf[0][ks][3], v2,v3);
                MMA16816(pv[2*ntp],   pf[1][ks][0],pf[1][ks][1],pf[1][ks][2],pf[1][ks][3], v0,v1);
                MMA16816(pv[2*ntp+1], pf[1][ks][0],pf[1][ks][1],pf[1][ks][2],pf[1][ks][3], v2,v3);
                LDSM4T(v0, v1, v2, v3, sV + 1 * KVTILE + voff);
                MMA16816(pv[2*ntp],   pf[0][ks][0],pf[0][ks][1],pf[0][ks][2],pf[0][ks][3], v0,v1);
                MMA16816(pv[2*ntp+1], pf[0][ks][0],pf[0][ks][1],pf[0][ks][2],pf[0][ks][3], v2,v3);
            }
        }

        __syncthreads();
        if (kt + 2 < LL / 64) KV_LOAD(kt & 1, kt + 2);
        CP_COMMIT();
    }

    float inv0 = 1.f / l0, inv1 = 1.f / l1;
    int gr0 = b * LL + q0 + wid * 16 + (lane >> 2);
    #pragma unroll
    for (int j = 0; j < 8; j++) {
        int col = hh * 64 + j * 8 + ((lane & 3) << 1);
        store_split_pair(Z0, Z1, (size_t)gr0 * CC + col,
                         pv[j][0] * inv0, pv[j][1] * inv0);
        store_split_pair(Z0, Z1, (size_t)(gr0 + 8) * CC + col,
                         pv[j][2] * inv1, pv[j][3] * inv1);
    }
    #undef KV_LOAD
}

// ---------------- block reduce helper ----------------
__device__ __forceinline__ float blockReduceSum256(float v, float* red)
{
    int lane = threadIdx.x & 31, warp = threadIdx.x >> 5;
    #pragma unroll
    for (int o = 16; o; o >>= 1) v += __shfl_xor_sync(0xffffffffu, v, o);
    if (lane == 0) red[warp] = v;
    __syncthreads();
    if (warp == 0) {
        v = (lane < 8) ? red[lane] : 0.f;
        #pragma unroll
        for (int o = 4; o; o >>= 1) v += __shfl_xor_sync(0xffffffffu, v, o);
        if (lane == 0) red[0] = v;
    }
    __syncthreads();
    float r = red[0];
    __syncthreads();
    return r;
}

// ---------------- fused residual add + LayerNorm + router argmax ----------------
__global__ void __launch_bounds__(256)
add_ln_router_kernel(const float* __restrict__ qx, const float* __restrict__ att,
                     const float* __restrict__ w, const float* __restrict__ bb,
                     const float* __restrict__ Wsw, const float* __restrict__ bsw,
                     float* __restrict__ zn, int* __restrict__ route)
{
    __shared__ float red[8];
    __shared__ float esum[8][EE];
    int row = blockIdx.x, tid = threadIdx.x;
    int lane = tid & 31, warp = tid >> 5;
    const float4* xq = (const float4*)(qx  + (size_t)row * CC);
    const float4* aq = (const float4*)(att + (size_t)row * CC);
    float4 x = xq[tid], a = aq[tid];
    float4 v; v.x = x.x + a.x; v.y = x.y + a.y; v.z = x.z + a.z; v.w = x.w + a.w;
    float mean = blockReduceSum256(v.x + v.y + v.z + v.w, red) * (1.f/1024.f);
    float dx = v.x - mean, dy = v.y - mean, dz = v.z - mean, dw = v.w - mean;
    float var = blockReduceSum256(dx*dx + dy*dy + dz*dz + dw*dw, red) * (1.f/1024.f);
    float rs = rsqrtf(var + 1e-5f);
    float4 wv = ((const float4*)w)[tid];
    float4 bv = ((const float4*)bb)[tid];
    float4 o;
    o.x = dx*rs*wv.x + bv.x; o.y = dy*rs*wv.y + bv.y;
    o.z = dz*rs*wv.z + bv.z; o.w = dw*rs*wv.w + bv.w;
    ((float4*)(zn + (size_t)row * CC))[tid] = o;

    int c = tid * 4;
    #pragma unroll
    for (int e = 0; e < EE; e++) {
        float4 we = *(const float4*)(Wsw + (size_t)e * CC + c);
        float p = o.x*we.x + o.y*we.y + o.z*we.z + o.w*we.w;
        #pragma unroll
        for (int of = 16; of; of >>= 1) p += __shfl_xor_sync(0xffffffffu, p, of);
        if (lane == 0) esum[warp][e] = p;
    }
    __syncthreads();
    if (tid == 0) {
        float best = -1e30f; int bi = 0;
        #pragma unroll
        for (int e = 0; e < EE; e++) {
            float lg = esum[0][e] + esum[1][e] + esum[2][e] + esum[3][e]
                     + esum[4][e] + esum[5][e] + esum[6][e] + esum[7][e] + bsw[e];
            if (lg > best) { best = lg; bi = e; }
        }
        route[row] = bi;
    }
}

// -------- deterministic per-expert prefix positions (smem-cached routes) -----
__global__ void __launch_bounds__(256)
scanpos_kernel(const int* __restrict__ route, int* __restrict__ pos,
               int* __restrict__ slot2tok)
{
    __shared__ int rts[NTOK];          // 32 KB
    __shared__ int wtot[8];
    __shared__ int running;
    int e = blockIdx.x;
    int tid = threadIdx.x;
    int lane = tid & 31, warp = tid >> 5;
    for (int i = tid; i < NTOK; i += 256) rts[i] = route[i];
    if (tid == 0) running = 0;
    if (tid < CAPP) {
        slot2tok[e * CAPP + tid] = -1;
    }
    __syncthreads();
    for (int base = 0; base < NTOK; base += 256) {
        int tok = base + tid;
        int flag = (rts[tok] == e);
        unsigned m = __ballot_sync(0xffffffffu, flag);
        int rank = __popc(m & ((1u << lane) - 1u));
        if (lane == 31) wtot[warp] = __popc(m);
        __syncthreads();
        int prefix = 0;
        for (int w = 0; w < warp; w++) prefix += wtot[w];
        if (flag) {
            int p = running + prefix + rank;
            pos[tok] = p;
            if (p < CAPP) slot2tok[e * CAPP + p] = tok;
        }
        __syncthreads();
        if (tid == 0) {
            int t = 0;
            for (int w = 0; w < 8; w++) t += wtot[w];
            running += t;
        }
        __syncthreads();
    }
}

// ---------------- expert FFN layer 1 (reads zn directly via slot2tok) --------
__global__ void __launch_bounds__(256)
ffn1_kernel(const float* __restrict__ zn, const int* __restrict__ slot2tok,
            const float* __restrict__ W1, const float* __restrict__ b1,
            float* __restrict__ h)
{
    int blk = blockIdx.x;
    int e  = blk >> 6;
    int r0 = (blk & 63) * 4;
    __shared__ float xs[4][CC];
    __shared__ float red[4][4][HIDD];
    __shared__ int toks[4];
    int tid = threadIdx.x;
    if (tid < 4) toks[tid] = slot2tok[e * CAPP + r0 + tid];
    __syncthreads();
    for (int i = tid; i < 4 * (CC/4); i += 256) {
        int r = i >> 8;                 // 256 float4 per row
        int c4 = i & 255;
        int tok = toks[r];
        float4 v = (tok >= 0)
                 ? ((const float4*)(zn + (size_t)tok * CC))[c4]
                 : make_float4(0.f, 0.f, 0.f, 0.f);
        ((float4*)xs)[i] = v;
    }
    __syncthreads();
    int kp = tid >> 6;
    int n  = tid & 63;
    float acc[4] = {};
    const float* w = W1 + (size_t)e * CC * HIDD + n;
    #pragma unroll 4
    for (int k = kp; k < CC; k += 4) {
        float wv = w[(size_t)k * HIDD];
        #pragma unroll
        for (int r = 0; r < 4; r++) acc[r] += xs[r][k] * wv;
    }
    #pragma unroll
    for (int r = 0; r < 4; r++) red[kp][r][n] = acc[r];
    __syncthreads();
    {
        int r = tid >> 6, n2 = tid & 63;
        float s = red[0][r][n2] + red[1][r][n2] + red[2][r][n2] + red[3][r][n2]
                + b1[e*HIDD + n2];
        h[((size_t)e*CAPP + r0 + r) * HIDD + n2] = fmaxf(s, 0.f);
    }
}

// ---------------- expert FFN layer 2 fused with finalize (kept tokens) -------
__global__ void __launch_bounds__(256)
ffn2_out_kernel(const float* __restrict__ h, const float* __restrict__ W2,
                const float* __restrict__ b2, const int* __restrict__ slot2tok,
                const float* __restrict__ zn, float* __restrict__ out)
{
    int blk = blockIdx.x;
    int e  = blk >> 6;
    int r0 = (blk & 63) * 4;
    __shared__ float hs[4][HIDD];
    __shared__ int toks[4];
    int tid = threadIdx.x;
    hs[tid >> 6][tid & 63] = h[((size_t)e*CAPP + r0 + (tid >> 6)) * HIDD + (tid & 63)];
    if (tid < 4) toks[tid] = slot2tok[e * CAPP + r0 + tid];
    __syncthreads();
    int c = tid * 4;
    float4 acc[4];
    #pragma unroll
    for (int r = 0; r < 4; r++) { acc[r].x=0.f; acc[r].y=0.f; acc[r].z=0.f; acc[r].w=0.f; }
    const float* w = W2 + (size_t)e * HIDD * CC + c;
    #pragma unroll 8
    for (int k = 0; k < HIDD; k++) {
        float4 wv = *(const float4*)(w + (size_t)k * CC);
        #pragma unroll
        for (int r = 0; r < 4; r++) {
            float hv = hs[r][k];
            acc[r].x += hv*wv.x; acc[r].y += hv*wv.y;
            acc[r].z += hv*wv.z; acc[r].w += hv*wv.w;
        }
    }
    float4 bb = *(const float4*)(b2 + (size_t)e * CC + c);
    #pragma unroll
    for (int r = 0; r < 4; r++) {
        int tok = toks[r];
        if (tok < 0) continue;
        float4 z = *(const float4*)(zn + (size_t)tok * CC + c);
        float4 o;
        o.x = z.x + acc[r].x + bb.x; o.y = z.y + acc[r].y + bb.y;
        o.z = z.z + acc[r].z + bb.z; o.w = z.w + acc[r].w + bb.w;
        *(float4*)(out + (size_t)tok * CC + c) = o;
    }
}

// ---------------- dropped tokens: out = 2*zn ----------------
__global__ void __launch_bounds__(256)
finalize_dropped_kernel(const float* __restrict__ zn, const int* __restrict__ pos,
                        float* __restrict__ out)
{
    int tok = blockIdx.x, tid = threadIdx.x;
    if (pos[tok] < CAPP) return;
    float4 z = ((const float4*)(zn + (size_t)tok * CC))[tid];
    float4 o = {2.f*z.x, 2.f*z.y, 2.f*z.z, 2.f*z.w};
    ((float4*)(out + (size_t)tok * CC))[tid] = o;
}

__global__ void fill_ones_kernel(float* __restrict__ p, int n)
{
    int i = blockIdx.x * 256 + threadIdx.x;
    if (i < n) p[i] = 1.0f;
}

// ---------------- launch (multi-stream DAG) ----------------
extern "C" void kernel_launch(void* const* d_in, const int* in_sizes, int n_in,
                              void* d_out, int out_size)
{
    const float* qx  = (const float*)d_in[0];
    const float* kx  = (const float*)d_in[1];
    const float* vx  = (const float*)d_in[2];
    const float* WQ  = (const float*)d_in[4];
    const float* bQ  = (const float*)d_in[5];
    const float* WK  = (const float*)d_in[6];
    const float* bK  = (const float*)d_in[7];
    const float* WV  = (const float*)d_in[8];
    const float* bV  = (const float*)d_in[9];
    const float* WO  = (const float*)d_in[10];
    const float* bO  = (const float*)d_in[11];
    const float* ln1w= (const float*)d_in[12];
    const float* ln1b= (const float*)d_in[13];
    const float* Wsw = (const float*)d_in[14];
    const float* bsw = (const float*)d_in[15];
    const float* W1  = (const float*)d_in[16];
    const float* b1  = (const float*)d_in[17];
    const float* W2  = (const float*)d_in[18];
    const float* b2  = (const float*)d_in[19];
    float* out = (float*)d_out;

    float *pA, *pzn, *ph;
    int *proute, *ppos, *ps2t;
    cudaGetSymbolAddress((void**)&pA,  g_A);
    cudaGetSymbolAddress((void**)&pzn, g_zn);
    cudaGetSymbolAddress((void**)&ph,  g_h);
    cudaGetSymbolAddress((void**)&proute, g_route);
    cudaGetSymbolAddress((void**)&ppos,   g_pos);
    cudaGetSymbolAddress((void**)&ps2t,   g_slot2tok);

    __half *xq[2], *xk[2], *xv[2];
    __half *wq[2], *wk[2], *wv[2], *wo[2];
    __half *oq[2], *ok[2], *ov[2];
    cudaGetSymbolAddress((void**)&xq[0], g_xq0); cudaGetSymbolAddress((void**)&xq[1], g_xq1);
    cudaGetSymbolAddress((void**)&xk[0], g_xk0); cudaGetSymbolAddress((void**)&xk[1], g_xk1);
    cudaGetSymbolAddress((void**)&xv[0], g_xv0); cudaGetSymbolAddress((void**)&xv[1], g_xv1);
    cudaGetSymbolAddress((void**)&wq[0], g_wq0); cudaGetSymbolAddress((void**)&wq[1], g_wq1);
    cudaGetSymbolAddress((void**)&wk[0], g_wk0); cudaGetSymbolAddress((void**)&wk[1], g_wk1);
    cudaGetSymbolAddress((void**)&wv[0], g_wv0); cudaGetSymbolAddress((void**)&wv[1], g_wv1);
    cudaGetSymbolAddress((void**)&wo[0], g_wo0); cudaGetSymbolAddress((void**)&wo[1], g_wo1);
    cudaGetSymbolAddress((void**)&oq[0], g_q0);  cudaGetSymbolAddress((void**)&oq[1], g_q1);
    cudaGetSymbolAddress((void**)&ok[0], g_k0);  cudaGetSymbolAddress((void**)&ok[1], g_k1);
    cudaGetSymbolAddress((void**)&ov[0], g_v0);  cudaGetSymbolAddress((void**)&ov[1], g_v1);

    cudaFuncSetAttribute(mma_gemm,   cudaFuncAttributeMaxDynamicSharedMemorySize, GEMM_SMEM);
    cudaFuncSetAttribute(mma_gemm_s, cudaFuncAttributeMaxDynamicSharedMemorySize, GEMM_SMEM);
    cudaFuncSetAttribute(attn_mma,   cudaFuncAttributeMaxDynamicSharedMemorySize, ATTN_SMEM);

    const int NX4 = NTOK * CC / 4;
    const int NW4 = CC * CC / 4;
    dim3 gemmGrid(CC/128, NTOK/128);

    cudaStream_t s1, s2;
    cudaStreamCreateWithFlags(&s1, cudaStreamNonBlocking);
    cudaStreamCreateWithFlags(&s2, cudaStreamNonBlocking);
    cudaEvent_t evFork, evK, evV, evWO, evJ1, evJ2;
    cudaEventCreateWithFlags(&evFork, cudaEventDisableTiming);
    cudaEventCreateWithFlags(&evK,    cudaEventDisableTiming);
    cudaEventCreateWithFlags(&evV,    cudaEventDisableTiming);
    cudaEventCreateWithFlags(&evWO,   cudaEventDisableTiming);
    cudaEventCreateWithFlags(&evJ1,   cudaEventDisableTiming);
    cudaEventCreateWithFlags(&evJ2,   cudaEventDisableTiming);

    // fork
    cudaEventRecord(evFork, 0);
    cudaStreamWaitEvent(s1, evFork, 0);
    cudaStreamWaitEvent(s2, evFork, 0);

    // s0: Q pipeline
    split2_kernel<<<NX4/256, 256>>>(qx, xq[0], xq[1], NX4);
    split2_kernel<<<NW4/256, 256>>>(WQ, wq[0], wq[1], NW4);
    mma_gemm_s<<<gemmGrid, 256, GEMM_SMEM, 0>>>(
        xq[0], xq[1], wq[0], wq[1], bQ, oq[0], oq[1]);

    // s1: K pipeline, then WO split
    split2_kernel<<<NX4/256, 256, 0, s1>>>(kx, xk[0], xk[1], NX4);
    split2_kernel<<<NW4/256, 256, 0, s1>>>(WK, wk[0], wk[1], NW4);
    mma_gemm_s<<<gemmGrid, 256, GEMM_SMEM, s1>>>(
        xk[0], xk[1], wk[0], wk[1], bK, ok[0], ok[1]);
    cudaEventRecord(evK, s1);
    split2_kernel<<<NW4/256, 256, 0, s1>>>(WO, wo[0], wo[1], NW4);
    cudaEventRecord(evWO, s1);

    // s2: tuple memcpys (independent) then V pipeline
    long long os = (long long)out_size;
    if (os >= (long long)(2 * NCE)) {
        cudaMemcpyAsync(out + NCE, kx, NCE * sizeof(float),
                        cudaMemcpyDeviceToDevice, s2);
    }
    if (os >= (long long)(3 * NCE)) {
        cudaMemcpyAsync(out + 2 * NCE, vx, NCE * sizeof(float),
                        cudaMemcpyDeviceToDevice, s2);
    }
    long long rem = os - (long long)(3 * NCE);
    if (rem > 0) {
        fill_ones_kernel<<<(int)((rem + 255) / 256), 256, 0, s2>>>(
            out + 3 * NCE, (int)rem);
    }
    split2_kernel<<<NX4/256, 256, 0, s2>>>(vx, xv[0], xv[1], NX4);
    split2_kernel<<<NW4/256, 256, 0, s2>>>(WV, wv[0], wv[1], NW4);
    mma_gemm_s<<<gemmGrid, 256, GEMM_SMEM, s2>>>(
        xv[0], xv[1], wv[0], wv[1], bV, ov[0], ov[1]);
    cudaEventRecord(evV, s2);

    // s0: attention waits on K and V
    cudaStreamWaitEvent(0, evK, 0);
    cudaStreamWaitEvent(0, evV, 0);
    attn_mma<<<dim3(LL/128, BB*HH), 256, ATTN_SMEM, 0>>>(
        oq[0], oq[1], ok[0], ok[1], ov[0], ov[1], xq[0], xq[1]);

    // s0: WO GEMM waits on WO split
    cudaStreamWaitEvent(0, evWO, 0);
    mma_gemm<<<gemmGrid, 256, GEMM_SMEM, 0>>>(
        xq[0], xq[1], wo[0], wo[1], bO, pA);

    add_ln_router_kernel<<<NTOK, 256>>>(qx, pA, ln1w, ln1b, Wsw, bsw, pzn, proute);
    scanpos_kernel<<<EE, 256>>>(proute, ppos, ps2t);
    ffn1_kernel<<<EE * (CAPP/4), 256>>>(pzn, ps2t, W1, b1, ph);
    ffn2_out_kernel<<<EE * (CAPP/4), 256>>>(ph, W2, b2, ps2t, pzn, out);
    finalize_dropped_kernel<<<NTOK, 256>>>(pzn, ppos, out);

    // join side streams back into s0 before returning
    cudaEventRecord(evJ1, s1);
    cudaEventRecord(evJ2, s2);
    cudaStreamWaitEvent(0, evJ1, 0);
    cudaStreamWaitEvent(0, evJ2, 0);

    cudaEventDestroy(evFork);
    cudaEventDestroy(evK);
    cudaEventDestroy(evV);
    cudaEventDestroy(evWO);
    cudaEventDestroy(evJ1);
    cudaEventDestroy(evJ2);
    cudaStreamDestroy(s1);
    cudaStreamDestroy(s2);
}

// round 16
// speedup vs baseline: 1.6571x; 1.0074x over previous
#include <cuda_runtime.h>
#include <cuda_fp16.h>
#include <math.h>
#include <stdint.h>

// ---------------- problem constants ----------------
#define BB 8
#define LL 1024
#define CC 1024
#define HH 16
#define DKK 64
#define NTOK (BB*LL)            // 8192
#define EE 16
#define HIDD 64
#define CAPP 256
#define NCE ((size_t)NTOK * CC)

// ---------------- baseline-PTX tensor-core helpers (sm_80+) ----------------
__device__ __forceinline__ uint32_t smem_u32(const void* p) {
    uint32_t a;
    asm("{ .reg .u64 t; cvta.to.shared.u64 t, %1; cvt.u32.u64 %0, t; }" : "=r"(a) : "l"(p));
    return a;
}
#define LDSM4(d0, d1, d2, d3, a) \
    asm volatile("ldmatrix.sync.aligned.m8n8.x4.shared.b16 {%0,%1,%2,%3}, [%4];" \
        : "=r"(d0), "=r"(d1), "=r"(d2), "=r"(d3) : "r"(a))
#define LDSM4T(d0, d1, d2, d3, a) \
    asm volatile("ldmatrix.sync.aligned.m8n8.x4.trans.shared.b16 {%0,%1,%2,%3}, [%4];" \
        : "=r"(d0), "=r"(d1), "=r"(d2), "=r"(d3) : "r"(a))
#define MMA16816(c, a0, a1, a2, a3, b0, b1) \
    asm volatile("mma.sync.aligned.m16n8k16.row.col.f32.f16.f16.f32 " \
        "{%0,%1,%2,%3}, {%4,%5,%6,%7}, {%8,%9}, {%0,%1,%2,%3};" \
        : "+f"((c)[0]), "+f"((c)[1]), "+f"((c)[2]), "+f"((c)[3]) \
        : "r"(a0), "r"(a1), "r"(a2), "r"(a3), "r"(b0), "r"(b1))
#define CP_ASYNC16(dst, src) \
    asm volatile("cp.async.cg.shared.global [%0], [%1], 16;" :: "r"(dst), "l"(src))
#define CP_COMMIT() asm volatile("cp.async.commit_group;" ::: "memory")
#define CP_WAIT1()  asm volatile("cp.async.wait_group 1;" ::: "memory")

// ---------------- fp16 2-term split helpers ----------------
__device__ __forceinline__ void split2r(float a, __half& h0, __half& h1)
{
    h0 = __float2half_rn(a);
    h1 = __float2half_rn(a - __half2float(h0));
}
__device__ __forceinline__ uint32_t pkh(__half lo, __half hi)
{
    __half2 t = __halves2half2(lo, hi);
    return *reinterpret_cast<uint32_t*>(&t);
}
__device__ __forceinline__ void store_split_pair(
    __half* Y0, __half* Y1, size_t off, float e0, float e1)
{
    __half a0, a1, b0, b1;
    split2r(e0, a0, a1);
    split2r(e1, b0, b1);
    *(uint32_t*)(Y0 + off) = pkh(a0, b0);
    *(uint32_t*)(Y1 + off) = pkh(a1, b1);
}

// ---------------- scratch ----------------
__device__ float g_A [NTOK * CC];
__device__ float g_zn[NTOK * CC];
__device__ float g_h [EE * CAPP * HIDD];
__device__ int   g_route[NTOK];
__device__ int   g_pos  [NTOK];
__device__ int   g_slot2tok[EE * CAPP];
__device__ __half g_xq0[NTOK*CC], g_xq1[NTOK*CC];
__device__ __half g_xk0[NTOK*CC], g_xk1[NTOK*CC];
__device__ __half g_xv0[NTOK*CC], g_xv1[NTOK*CC];
__device__ __half g_wq0[CC*CC], g_wq1[CC*CC];
__device__ __half g_wk0[CC*CC], g_wk1[CC*CC];
__device__ __half g_wv0[CC*CC], g_wv1[CC*CC];
__device__ __half g_wo0[CC*CC], g_wo1[CC*CC];
__device__ __half g_q0[NTOK*CC], g_q1[NTOK*CC];
__device__ __half g_k0[NTOK*CC], g_k1[NTOK*CC];
__device__ __half g_v0[NTOK*CC], g_v1[NTOK*CC];

// ---------------- fp32 -> 2x fp16 split ----------------
__global__ void __launch_bounds__(256)
split2_kernel(const float* __restrict__ in, __half* __restrict__ o0,
              __half* __restrict__ o1, int n4)
{
    int i = blockIdx.x * 256 + threadIdx.x;
    if (i >= n4) return;
    float4 v = ((const float4*)in)[i];
    float a[4] = {v.x, v.y, v.z, v.w};
    union { __half b[4]; uint2 u; } s0, s1;
    #pragma unroll
    for (int j = 0; j < 4; j++) split2r(a[j], s0.b[j], s1.b[j]);
    ((uint2*)o0)[i] = s0.u;
    ((uint2*)o1)[i] = s1.u;
}

// ---------------- HMMA GEMM core (fp16x3), 2-stage, 2 CTAs/SM ----------------
#define APAD 40
#define TILE_B (128 * APAD * 2)     // 10240
#define STAGE4 (4 * TILE_B)         // 40960
#define GEMM_SMEM (2 * STAGE4)      // 81920
#define NCHUNK 32

template <int OutMode>
__device__ __forceinline__ void gemm_core(
    const __half* __restrict__ X0, const __half* __restrict__ X1,
    const __half* __restrict__ W0, const __half* __restrict__ W1,
    const float* __restrict__ bias,
    float* __restrict__ Yf,
    __half* __restrict__ Y0, __half* __restrict__ Y1,
    char* smem)
{
    const uint32_t sb = smem_u32(smem);
    const int tid = threadIdx.x, wid = tid >> 5, lane = tid & 31;
    const int bm = blockIdx.y * 128, bn = blockIdx.x * 128;
    const int wm = (wid >> 2) * 64, wn = (wid & 3) * 32;

    const __half* TS[4] = {X0, X1, W0, W1};

    #define G_LOAD(buf, ch) do { \
        int ko_ = (ch) * 32; \
        _Pragma("unroll") \
        for (int j_ = 0; j_ < 8; j_++) { \
            int e_ = j_ * 256 + tid; \
            int t_ = e_ >> 9; \
            int w_ = e_ & 511; \
            int r_ = w_ >> 2, c8_ = (w_ & 3) * 8; \
            int rowb_ = ((t_ < 2) ? bm : bn) + r_; \
            CP_ASYNC16(sb + (buf) * STAGE4 + t_ * TILE_B + (r_ * APAD + c8_) * 2, \
                       TS[t_] + (size_t)rowb_ * CC + ko_ + c8_); \
        } \
    } while (0)

    float acc[4][4][4];
    #pragma unroll
    for (int i = 0; i < 4; i++)
        #pragma unroll
        for (int j = 0; j < 4; j++)
            #pragma unroll
            for (int q = 0; q < 4; q++) acc[i][j][q] = 0.f;

    G_LOAD(0, 0); CP_COMMIT();
    G_LOAD(1, 1); CP_COMMIT();

    for (int c = 0; c < NCHUNK; c++) {
        int buf = c & 1;
        CP_WAIT1();
        __syncthreads();

        uint32_t stage = sb + buf * STAGE4;
        #pragma unroll
        for (int kk = 0; kk < 2; kk++) {
            uint32_t a[2][4][4];
            #pragma unroll
            for (int s = 0; s < 2; s++)
                #pragma unroll
                for (int i = 0; i < 4; i++) {
                    int arow = wm + i * 16 + (lane & 15);
                    int acol = kk * 16 + ((lane >> 4) << 3);
                    LDSM4(a[s][i][0], a[s][i][1], a[s][i][2], a[s][i][3],
                          stage + s * TILE_B + (uint32_t)(arow * APAD + acol) * 2);
                }
            #pragma unroll
            for (int jp = 0; jp < 2; jp++) {
                int g = lane >> 3;
                int brow = wn + jp * 16 + ((g & 2) << 2) + (lane & 7);
                int bcol = kk * 16 + ((g & 1) << 3);
                uint32_t boff = (uint32_t)(brow * APAD + bcol) * 2;
                uint32_t b0, b1, b2, b3;
                LDSM4(b0, b1, b2, b3, stage + 2 * TILE_B + boff);
                #pragma unroll
                for (int i = 0; i < 4; i++) {
                    MMA16816(acc[i][2*jp],   a[0][i][0],a[0][i][1],a[0][i][2],a[0][i][3], b0,b1);
                    MMA16816(acc[i][2*jp+1], a[0][i][0],a[0][i][1],a[0][i][2],a[0][i][3], b2,b3);
                    MMA16816(acc[i][2*jp],   a[1][i][0],a[1][i][1],a[1][i][2],a[1][i][3], b0,b1);
                    MMA16816(acc[i][2*jp+1], a[1][i][0],a[1][i][1],a[1][i][2],a[1][i][3], b2,b3);
                }
                LDSM4(b0, b1, b2, b3, stage + 3 * TILE_B + boff);
                #pragma unroll
                for (int i = 0; i < 4; i++) {
                    MMA16816(acc[i][2*jp],   a[0][i][0],a[0][i][1],a[0][i][2],a[0][i][3], b0,b1);
                    MMA16816(acc[i][2*jp+1], a[0][i][0],a[0][i][1],a[0][i][2],a[0][i][3], b2,b3);
                }
            }
        }
        __syncthreads();
        if (c + 2 < NCHUNK) {
            G_LOAD(buf, c + 2);
        }
        CP_COMMIT();
    }

    #pragma unroll
    for (int i = 0; i < 4; i++) {
        int row = bm + wm + i * 16 + (lane >> 2);
        #pragma unroll
        for (int j = 0; j < 4; j++) {
            int col = bn + wn + j * 8 + ((lane & 3) << 1);
            float bx = bias[col], by = bias[col + 1];
            float e0 = acc[i][j][0] + bx, e1 = acc[i][j][1] + by;
            float e2 = acc[i][j][2] + bx, e3 = acc[i][j][3] + by;
            if (OutMode == 0) {
                float2 v0 = {e0, e1};
                float2 v1 = {e2, e3};
                *(float2*)(Yf + (size_t)row * CC + col) = v0;
                *(float2*)(Yf + (size_t)(row + 8) * CC + col) = v1;
            } else {
                store_split_pair(Y0, Y1, (size_t)row * CC + col, e0, e1);
                store_split_pair(Y0, Y1, (size_t)(row + 8) * CC + col, e2, e3);
            }
        }
    }
    #undef G_LOAD
}

__global__ void __launch_bounds__(256, 2)
mma_gemm(const __half* __restrict__ X0, const __half* __restrict__ X1,
         const __half* __restrict__ W0, const __half* __restrict__ W1,
         const float* __restrict__ bias, float* __restrict__ Y)
{
    extern __shared__ char smem[];
    gemm_core<0>(X0, X1, W0, W1, bias, Y, nullptr, nullptr, smem);
}

__global__ void __launch_bounds__(256, 2)
mma_gemm_s(const __half* __restrict__ X0, const __half* __restrict__ X1,
           const __half* __restrict__ W0, const __half* __restrict__ W1,
           const float* __restrict__ bias,
           __half* __restrict__ Y0, __half* __restrict__ Y1)
{
    extern __shared__ char smem[];
    gemm_core<1>(X0, X1, W0, W1, bias, nullptr, Y0, Y1, smem);
}

// ---------------- flash attention on HMMA (fp16x3) ----------------
#define QTILE (128 * 72 * 2)      // 18432
#define KVTILE (64 * 72 * 2)      // 9216
#define AT_SOFF (2 * QTILE)       // 36864
#define AT_STG (4 * KVTILE)       // 36864
#define ATTN_SMEM (AT_SOFF + 2 * AT_STG)   // 110592

__global__ void __launch_bounds__(256)
attn_mma(const __half* __restrict__ Q0, const __half* __restrict__ Q1,
         const __half* __restrict__ K0, const __half* __restrict__ K1,
         const __half* __restrict__ V0, const __half* __restrict__ V1,
         __half* __restrict__ Z0, __half* __restrict__ Z1)
{
    extern __shared__ char smem[];
    const uint32_t sb = smem_u32(smem);
    const int tid = threadIdx.x, wid = tid >> 5, lane = tid & 31;
    const int bh = blockIdx.y;
    const int b = bh >> 4, hh = bh & 15;
    const int q0 = blockIdx.x * 128;

    const __half* QS[2] = {Q0, Q1};
    const __half* KS[2] = {K0, K1};
    const __half* VS[2] = {V0, V1};

    #pragma unroll
    for (int j = 0; j < 8; j++) {
        int e = j * 256 + tid;
        int t = e >> 10;
        int w = e & 1023;
        int r = w >> 3, c = w & 7;
        CP_ASYNC16(sb + t * QTILE + (uint32_t)(r * 72 + c * 8) * 2,
                   QS[t] + (size_t)(b * LL + q0 + r) * CC + hh * 64 + c * 8);
    }

    #define KV_LOAD(buf, kt) do { \
        _Pragma("unroll") \
        for (int j_ = 0; j_ < 8; j_++) { \
            int e_ = j_ * 256 + tid; \
            int t_ = e_ >> 9; \
            int w_ = e_ & 511; \
            int r_ = w_ >> 3, c_ = w_ & 7; \
            const __half* src_ = (t_ < 2) ? KS[t_] : VS[t_ - 2]; \
            CP_ASYNC16(sb + AT_SOFF + (buf) * AT_STG + t_ * KVTILE + \
                       (uint32_t)(r_ * 72 + c_ * 8) * 2, \
                       src_ + (size_t)(b * LL + (kt) * 64 + r_) * CC + hh * 64 + c_ * 8); \
        } \
    } while (0)

    KV_LOAD(0, 0); CP_COMMIT();
    KV_LOAD(1, 1); CP_COMMIT();

    float pv[8][4];
    #pragma unroll
    for (int j = 0; j < 8; j++)
        #pragma unroll
        for (int q = 0; q < 4; q++) pv[j][q] = 0.f;
    float m0 = -1e30f, m1 = -1e30f, l0 = 0.f, l1 = 0.f;
    uint32_t qf[2][4][4];

    for (int kt = 0; kt < LL / 64; kt++) {
        CP_WAIT1();
        __syncthreads();
        if (kt == 0) {
            #pragma unroll
            for (int s = 0; s < 2; s++)
                #pragma unroll
                for (int ks = 0; ks < 4; ks++) {
                    int arow = wid * 16 + (lane & 15);
                    int acol = ks * 16 + ((lane >> 4) << 3);
                    LDSM4(qf[s][ks][0], qf[s][ks][1], qf[s][ks][2], qf[s][ks][3],
                          sb + s * QTILE + (uint32_t)(arow * 72 + acol) * 2);
                }
        }

        uint32_t sK = sb + AT_SOFF + (kt & 1) * AT_STG;
        uint32_t sV = sK + 2 * KVTILE;

        float sacc[8][4];
        #pragma unroll
        for (int j = 0; j < 8; j++)
            #pragma unroll
            for (int q = 0; q < 4; q++) sacc[j][q] = 0.f;

        #pragma unroll
        for (int ks = 0; ks < 4; ks++) {
            #pragma unroll
            for (int ntp = 0; ntp < 4; ntp++) {
                int g = lane >> 3;
                int brow = ntp * 16 + ((g & 2) << 2) + (lane & 7);
                int bcol = ks * 16 + ((g & 1) << 3);
                uint32_t boff = (uint32_t)(brow * 72 + bcol) * 2;
                uint32_t b0, b1, b2, b3;
                LDSM4(b0, b1, b2, b3, sK + 0 * KVTILE + boff);
                MMA16816(sacc[2*ntp],   qf[0][ks][0],qf[0][ks][1],qf[0][ks][2],qf[0][ks][3], b0,b1);
                MMA16816(sacc[2*ntp+1], qf[0][ks][0],qf[0][ks][1],qf[0][ks][2],qf[0][ks][3], b2,b3);
                MMA16816(sacc[2*ntp],   qf[1][ks][0],qf[1][ks][1],qf[1][ks][2],qf[1][ks][3], b0,b1);
                MMA16816(sacc[2*ntp+1], qf[1][ks][0],qf[1][ks][1],qf[1][ks][2],qf[1][ks][3], b2,b3);
                LDSM4(b0, b1, b2, b3, sK + 1 * KVTILE + boff);
                MMA16816(sacc[2*ntp],   qf[0][ks][0],qf[0][ks][1],qf[0][ks][2],qf[0][ks][3], b0,b1);
                MMA16816(sacc[2*ntp+1], qf[0][ks][0],qf[0][ks][1],qf[0][ks][2],qf[0][ks][3], b2,b3);
            }
        }

        float tm0 = -1e30f, tm1 = -1e30f;
        #pragma unroll
        for (int j = 0; j < 8; j++) {
            tm0 = fmaxf(tm0, fmaxf(sacc[j][0], sacc[j][1]));
            tm1 = fmaxf(tm1, fmaxf(sacc[j][2], sacc[j][3]));
        }
        tm0 = fmaxf(tm0, __shfl_xor_sync(0xffffffffu, tm0, 1));
        tm0 = fmaxf(tm0, __shfl_xor_sync(0xffffffffu, tm0, 2));
        tm1 = fmaxf(tm1, __shfl_xor_sync(0xffffffffu, tm1, 1));
        tm1 = fmaxf(tm1, __shfl_xor_sync(0xffffffffu, tm1, 2));
        tm0 *= 0.125f; tm1 *= 0.125f;
        float mn0 = fmaxf(m0, tm0), mn1 = fmaxf(m1, tm1);
        float al0 = __expf(m0 - mn0), al1 = __expf(m1 - mn1);
        m0 = mn0; m1 = mn1;

        float rs0 = 0.f, rs1 = 0.f;
        uint32_t pf[2][4][4];
        #pragma unroll
        for (int j = 0; j < 8; j++) {
            float p0 = __expf(sacc[j][0] * 0.125f - mn0);
            float p1 = __expf(sacc[j][1] * 0.125f - mn0);
            float p2 = __expf(sacc[j][2] * 0.125f - mn1);
            float p3 = __expf(sacc[j][3] * 0.125f - mn1);
            rs0 += p0 + p1; rs1 += p2 + p3;
            __half a0, a1, b0v, b1v, c0, c1, d0, d1;
            split2r(p0, a0, a1);
            split2r(p1, b0v, b1v);
            split2r(p2, c0, c1);
            split2r(p3, d0, d1);
            int ks = j >> 1, ri = (j & 1) * 2;
            pf[0][ks][ri]     = pkh(a0, b0v);
            pf[0][ks][ri + 1] = pkh(c0, d0);
            pf[1][ks][ri]     = pkh(a1, b1v);
            pf[1][ks][ri + 1] = pkh(c1, d1);
        }
        rs0 += __shfl_xor_sync(0xffffffffu, rs0, 1);
        rs0 += __shfl_xor_sync(0xffffffffu, rs0, 2);
        rs1 += __shfl_xor_sync(0xffffffffu, rs1, 1);
        rs1 += __shfl_xor_sync(0xffffffffu, rs1, 2);
        l0 = l0 * al0 + rs0;
        l1 = l1 * al1 + rs1;
        #pragma unroll
        for (int j = 0; j < 8; j++) {
            pv[j][0] *= al0; pv[j][1] *= al0;
            pv[j][2] *= al1; pv[j][3] *= al1;
        }

        #pragma unroll
        for (int ks = 0; ks < 4; ks++) {
            #pragma unroll
            for (int ntp = 0; ntp < 4; ntp++) {
                int g = lane >> 3;
                int vrow = ks * 16 + ((g & 1) << 3) + (lane & 7);
                int vcol = ntp * 16 + ((g >> 1) << 3);
                uint32_t voff = (uint32_t)(vrow * 72 + vcol) * 2;
                uint32_t v0, v1, v2, v3;
                LDSM4T(v0, v1, v2, v3, sV + 0 * KVTILE + voff);
                MMA16816(pv[2*ntp],   pf[0][ks][0],pf[0][ks][1],pf[0][ks][2],pf[0][ks][3], v0,v1);
                MMA16816(pv[2*ntp+1], pf[0][ks][0],pf[0][ks][1],pf[0][ks][2],pf[0][ks][3], v2,v3);
                MMA16816(pv[2*ntp],   pf[1][ks][0],pf[1][ks][1],pf[1][ks][2],pf[1][ks][3], v0,v1);
                MMA16816(pv[2*ntp+1], pf[1][ks][0],pf[1][ks][1],pf[1][ks][2],pf[1][ks][3], v2,v3);
                LDSM4T(v0, v1, v2, v3, sV + 1 * KVTILE + voff);
                MMA16816(pv[2*ntp],   pf[0][ks][0],pf[0][ks][1],pf[0][ks][2],pf[0][ks][3], v0,v1);
                MMA16816(pv[2*ntp+1], pf[0][ks][0],pf[0][ks][1],pf[0][ks][2],pf[0][ks][3], v2,v3);
            }
        }

        __syncthreads();
        if (kt + 2 < LL / 64) KV_LOAD(kt & 1, kt + 2);
        CP_COMMIT();
    }

    float inv0 = 1.f / l0, inv1 = 1.f / l1;
    int gr0 = b * LL + q0 + wid * 16 + (lane >> 2);
    #pragma unroll
    for (int j = 0; j < 8; j++) {
        int col = hh * 64 + j * 8 + ((lane & 3) << 1);
        store_split_pair(Z0, Z1, (size_t)gr0 * CC + col,
                         pv[j][0] * inv0, pv[j][1] * inv0);
        store_split_pair(Z0, Z1, (size_t)(gr0 + 8) * CC + col,
                         pv[j][2] * inv1, pv[j][3] * inv1);
    }
    #undef KV_LOAD
}

// ---------------- block reduce helper ----------------
__device__ __forceinline__ float blockReduceSum256(float v, float* red)
{
    int lane = threadIdx.x & 31, warp = threadIdx.x >> 5;
    #pragma unroll
    for (int o = 16; o; o >>= 1) v += __shfl_xor_sync(0xffffffffu, v, o);
    if (lane == 0) red[warp] = v;
    __syncthreads();
    if (warp == 0) {
        v = (lane < 8) ? red[lane] : 0.f;
        #pragma unroll
        for (int o = 4; o; o >>= 1) v += __shfl_xor_sync(0xffffffffu, v, o);
        if (lane == 0) red[0] = v;
    }
    __syncthreads();
    float r = red[0];
    __syncthreads();
    return r;
}

// ---------------- fused residual add + LayerNorm + router argmax ----------------
__global__ void __launch_bounds__(256)
add_ln_router_kernel(const float* __restrict__ qx, const float* __restrict__ att,
                     const float* __restrict__ w, const float* __restrict__ bb,
                     const float* __restrict__ Wsw, const float* __restrict__ bsw,
                     float* __restrict__ zn, int* __restrict__ route)
{
    __shared__ float red[8];
    __shared__ float esum[8][EE];
    int row = blockIdx.x, tid = threadIdx.x;
    int lane = tid & 31, warp = tid >> 5;
    const float4* xq = (const float4*)(qx  + (size_t)row * CC);
    const float4* aq = (const float4*)(att + (size_t)row * CC);
    float4 x = xq[tid], a = aq[tid];
    float4 v; v.x = x.x + a.x; v.y = x.y + a.y; v.z = x.z + a.z; v.w = x.w + a.w;
    float mean = blockReduceSum256(v.x + v.y + v.z + v.w, red) * (1.f/1024.f);
    float dx = v.x - mean, dy = v.y - mean, dz = v.z - mean, dw = v.w - mean;
    float var = blockReduceSum256(dx*dx + dy*dy + dz*dz + dw*dw, red) * (1.f/1024.f);
    float rs = rsqrtf(var + 1e-5f);
    float4 wv = ((const float4*)w)[tid];
    float4 bv = ((const float4*)bb)[tid];
    float4 o;
    o.x = dx*rs*wv.x + bv.x; o.y = dy*rs*wv.y + bv.y;
    o.z = dz*rs*wv.z + bv.z; o.w = dw*rs*wv.w + bv.w;
    ((float4*)(zn + (size_t)row * CC))[tid] = o;

    int c = tid * 4;
    #pragma unroll
    for (int e = 0; e < EE; e++) {
        float4 we = *(const float4*)(Wsw + (size_t)e * CC + c);
        float p = o.x*we.x + o.y*we.y + o.z*we.z + o.w*we.w;
        #pragma unroll
        for (int of = 16; of; of >>= 1) p += __shfl_xor_sync(0xffffffffu, p, of);
        if (lane == 0) esum[warp][e] = p;
    }
    __syncthreads();
    if (tid == 0) {
        float best = -1e30f; int bi = 0;
        #pragma unroll
        for (int e = 0; e < EE; e++) {
            float lg = esum[0][e] + esum[1][e] + esum[2][e] + esum[3][e]
                     + esum[4][e] + esum[5][e] + esum[6][e] + esum[7][e] + bsw[e];
            if (lg > best) { best = lg; bi = e; }
        }
        route[row] = bi;
    }
}

// -------- deterministic per-expert prefix positions (smem-cached routes) -----
__global__ void __launch_bounds__(256)
scanpos_kernel(const int* __restrict__ route, int* __restrict__ pos,
               int* __restrict__ slot2tok)
{
    __shared__ int rts[NTOK];          // 32 KB
    __shared__ int wtot[8];
    __shared__ int running;
    int e = blockIdx.x;
    int tid = threadIdx.x;
    int lane = tid & 31, warp = tid >> 5;
    for (int i = tid; i < NTOK; i += 256) rts[i] = route[i];
    if (tid == 0) running = 0;
    if (tid < CAPP) {
        slot2tok[e * CAPP + tid] = -1;
    }
    __syncthreads();
    for (int base = 0; base < NTOK; base += 256) {
        int tok = base + tid;
        int flag = (rts[tok] == e);
        unsigned m = __ballot_sync(0xffffffffu, flag);
        int rank = __popc(m & ((1u << lane) - 1u));
        if (lane == 31) wtot[warp] = __popc(m);
        __syncthreads();
        int prefix = 0;
        for (int w = 0; w < warp; w++) prefix += wtot[w];
        if (flag) {
            int p = running + prefix + rank;
            pos[tok] = p;
            if (p < CAPP) slot2tok[e * CAPP + p] = tok;
        }
        __syncthreads();
        if (tid == 0) {
            int t = 0;
            for (int w = 0; w < 8; w++) t += wtot[w];
            running += t;
        }
        __syncthreads();
    }
}

// ---------------- expert FFN layer 1 (reads zn directly via slot2tok) --------
__global__ void __launch_bounds__(256)
ffn1_kernel(const float* __restrict__ zn, const int* __restrict__ slot2tok,
            const float* __restrict__ W1, const float* __restrict__ b1,
            float* __restrict__ h)
{
    int blk = blockIdx.x;
    int e  = blk >> 6;
    int r0 = (blk & 63) * 4;
    __shared__ float xs[4][CC];
    __shared__ float red[4][4][HIDD];
    __shared__ int toks[4];
    int tid = threadIdx.x;
    if (tid < 4) toks[tid] = slot2tok[e * CAPP + r0 + tid];
    __syncthreads();
    for (int i = tid; i < 4 * (CC/4); i += 256) {
        int r = i >> 8;
        int c4 = i & 255;
        int tok = toks[r];
        float4 v = (tok >= 0)
                 ? ((const float4*)(zn + (size_t)tok * CC))[c4]
                 : make_float4(0.f, 0.f, 0.f, 0.f);
        ((float4*)xs)[i] = v;
    }
    __syncthreads();
    int kp = tid >> 6;
    int n  = tid & 63;
    float acc[4] = {};
    const float* w = W1 + (size_t)e * CC * HIDD + n;
    #pragma unroll 4
    for (int k = kp; k < CC; k += 4) {
        float wv = w[(size_t)k * HIDD];
        #pragma unroll
        for (int r = 0; r < 4; r++) acc[r] += xs[r][k] * wv;
    }
    #pragma unroll
    for (int r = 0; r < 4; r++) red[kp][r][n] = acc[r];
    __syncthreads();
    {
        int r = tid >> 6, n2 = tid & 63;
        float s = red[0][r][n2] + red[1][r][n2] + red[2][r][n2] + red[3][r][n2]
                + b1[e*HIDD + n2];
        h[((size_t)e*CAPP + r0 + r) * HIDD + n2] = fmaxf(s, 0.f);
    }
}

// ---------------- expert FFN layer 2 fused with finalize (kept tokens) -------
__global__ void __launch_bounds__(256)
ffn2_out_kernel(const float* __restrict__ h, const float* __restrict__ W2,
                const float* __restrict__ b2, const int* __restrict__ slot2tok,
                const float* __restrict__ zn, float* __restrict__ out)
{
    int blk = blockIdx.x;
    int e  = blk >> 6;
    int r0 = (blk & 63) * 4;
    __shared__ float hs[4][HIDD];
    __shared__ int toks[4];
    int tid = threadIdx.x;
    hs[tid >> 6][tid & 63] = h[((size_t)e*CAPP + r0 + (tid >> 6)) * HIDD + (tid & 63)];
    if (tid < 4) toks[tid] = slot2tok[e * CAPP + r0 + tid];
    __syncthreads();
    int c = tid * 4;
    float4 acc[4];
    #pragma unroll
    for (int r = 0; r < 4; r++) { acc[r].x=0.f; acc[r].y=0.f; acc[r].z=0.f; acc[r].w=0.f; }
    const float* w = W2 + (size_t)e * HIDD * CC + c;
    #pragma unroll 8
    for (int k = 0; k < HIDD; k++) {
        float4 wv = *(const float4*)(w + (size_t)k * CC);
        #pragma unroll
        for (int r = 0; r < 4; r++) {
            float hv = hs[r][k];
            acc[r].x += hv*wv.x; acc[r].y += hv*wv.y;
            acc[r].z += hv*wv.z; acc[r].w += hv*wv.w;
        }
    }
    float4 bb = *(const float4*)(b2 + (size_t)e * CC + c);
    #pragma unroll
    for (int r = 0; r < 4; r++) {
        int tok = toks[r];
        if (tok < 0) continue;
        float4 z = *(const float4*)(zn + (size_t)tok * CC + c);
        float4 o;
        o.x = z.x + acc[r].x + bb.x; o.y = z.y + acc[r].y + bb.y;
        o.z = z.z + acc[r].z + bb.z; o.w = z.w + acc[r].w + bb.w;
        *(float4*)(out + (size_t)tok * CC + c) = o;
    }
}

// ---------------- dropped tokens: out = 2*zn ----------------
__global__ void __launch_bounds__(256)
finalize_dropped_kernel(const float* __restrict__ zn, const int* __restrict__ pos,
                        float* __restrict__ out)
{
    int tok = blockIdx.x, tid = threadIdx.x;
    if (pos[tok] < CAPP) return;
    float4 z = ((const float4*)(zn + (size_t)tok * CC))[tid];
    float4 o = {2.f*z.x, 2.f*z.y, 2.f*z.z, 2.f*z.w};
    ((float4*)(out + (size_t)tok * CC))[tid] = o;
}

__global__ void fill_ones_kernel(float* __restrict__ p, int n)
{
    int i = blockIdx.x * 256 + threadIdx.x;
    if (i < n) p[i] = 1.0f;
}

// ---------------- launch (multi-stream DAG) ----------------
extern "C" void kernel_launch(void* const* d_in, const int* in_sizes, int n_in,
                              void* d_out, int out_size)
{
    const float* qx  = (const float*)d_in[0];
    const float* kx  = (const float*)d_in[1];
    const float* vx  = (const float*)d_in[2];
    const float* WQ  = (const float*)d_in[4];
    const float* bQ  = (const float*)d_in[5];
    const float* WK  = (const float*)d_in[6];
    const float* bK  = (const float*)d_in[7];
    const float* WV  = (const float*)d_in[8];
    const float* bV  = (const float*)d_in[9];
    const float* WO  = (const float*)d_in[10];
    const float* bO  = (const float*)d_in[11];
    const float* ln1w= (const float*)d_in[12];
    const float* ln1b= (const float*)d_in[13];
    const float* Wsw = (const float*)d_in[14];
    const float* bsw = (const float*)d_in[15];
    const float* W1  = (const float*)d_in[16];
    const float* b1  = (const float*)d_in[17];
    const float* W2  = (const float*)d_in[18];
    const float* b2  = (const float*)d_in[19];
    float* out = (float*)d_out;

    float *pA, *pzn, *ph;
    int *proute, *ppos, *ps2t;
    cudaGetSymbolAddress((void**)&pA,  g_A);
    cudaGetSymbolAddress((void**)&pzn, g_zn);
    cudaGetSymbolAddress((void**)&ph,  g_h);
    cudaGetSymbolAddress((void**)&proute, g_route);
    cudaGetSymbolAddress((void**)&ppos,   g_pos);
    cudaGetSymbolAddress((void**)&ps2t,   g_slot2tok);

    __half *xq[2], *xk[2], *xv[2];
    __half *wq[2], *wk[2], *wv[2], *wo[2];
    __half *oq[2], *ok[2], *ov[2];
    cudaGetSymbolAddress((void**)&xq[0], g_xq0); cudaGetSymbolAddress((void**)&xq[1], g_xq1);
    cudaGetSymbolAddress((void**)&xk[0], g_xk0); cudaGetSymbolAddress((void**)&xk[1], g_xk1);
    cudaGetSymbolAddress((void**)&xv[0], g_xv0); cudaGetSymbolAddress((void**)&xv[1], g_xv1);
    cudaGetSymbolAddress((void**)&wq[0], g_wq0); cudaGetSymbolAddress((void**)&wq[1], g_wq1);
    cudaGetSymbolAddress((void**)&wk[0], g_wk0); cudaGetSymbolAddress((void**)&wk[1], g_wk1);
    cudaGetSymbolAddress((void**)&wv[0], g_wv0); cudaGetSymbolAddress((void**)&wv[1], g_wv1);
    cudaGetSymbolAddress((void**)&wo[0], g_wo0); cudaGetSymbolAddress((void**)&wo[1], g_wo1);
    cudaGetSymbolAddress((void**)&oq[0], g_q0);  cudaGetSymbolAddress((void**)&oq[1], g_q1);
    cudaGetSymbolAddress((void**)&ok[0], g_k0);  cudaGetSymbolAddress((void**)&ok[1], g_k1);
    cudaGetSymbolAddress((void**)&ov[0], g_v0);  cudaGetSymbolAddress((void**)&ov[1], g_v1);

    cudaFuncSetAttribute(mma_gemm,   cudaFuncAttributeMaxDynamicSharedMemorySize, GEMM_SMEM);
    cudaFuncSetAttribute(mma_gemm_s, cudaFuncAttributeMaxDynamicSharedMemorySize, GEMM_SMEM);
    cudaFuncSetAttribute(attn_mma,   cudaFuncAttributeMaxDynamicSharedMemorySize, ATTN_SMEM);

    const int NX4 = NTOK * CC / 4;
    const int NW4 = CC * CC / 4;
    dim3 gemmGrid(CC/128, NTOK/128);

    cudaStream_t s1, s2;
    cudaStreamCreateWithFlags(&s1, cudaStreamNonBlocking);
    cudaStreamCreateWithFlags(&s2, cudaStreamNonBlocking);
    cudaEvent_t evFork, evK, evV, evWO, evScan, evJ1, evJ2;
    cudaEventCreateWithFlags(&evFork, cudaEventDisableTiming);
    cudaEventCreateWithFlags(&evK,    cudaEventDisableTiming);
    cudaEventCreateWithFlags(&evV,    cudaEventDisableTiming);
    cudaEventCreateWithFlags(&evWO,   cudaEventDisableTiming);
    cudaEventCreateWithFlags(&evScan, cudaEventDisableTiming);
    cudaEventCreateWithFlags(&evJ1,   cudaEventDisableTiming);
    cudaEventCreateWithFlags(&evJ2,   cudaEventDisableTiming);

    // fork
    cudaEventRecord(evFork, 0);
    cudaStreamWaitEvent(s1, evFork, 0);
    cudaStreamWaitEvent(s2, evFork, 0);

    // s0: Q pipeline
    split2_kernel<<<NX4/256, 256>>>(qx, xq[0], xq[1], NX4);
    split2_kernel<<<NW4/256, 256>>>(WQ, wq[0], wq[1], NW4);
    mma_gemm_s<<<gemmGrid, 256, GEMM_SMEM, 0>>>(
        xq[0], xq[1], wq[0], wq[1], bQ, oq[0], oq[1]);

    // s1: K pipeline, then WO split
    split2_kernel<<<NX4/256, 256, 0, s1>>>(kx, xk[0], xk[1], NX4);
    split2_kernel<<<NW4/256, 256, 0, s1>>>(WK, wk[0], wk[1], NW4);
    mma_gemm_s<<<gemmGrid, 256, GEMM_SMEM, s1>>>(
        xk[0], xk[1], wk[0], wk[1], bK, ok[0], ok[1]);
    cudaEventRecord(evK, s1);
    split2_kernel<<<NW4/256, 256, 0, s1>>>(WO, wo[0], wo[1], NW4);
    cudaEventRecord(evWO, s1);

    // s2: tuple memcpys (independent) then V pipeline
    long long os = (long long)out_size;
    if (os >= (long long)(2 * NCE)) {
        cudaMemcpyAsync(out + NCE, kx, NCE * sizeof(float),
                        cudaMemcpyDeviceToDevice, s2);
    }
    if (os >= (long long)(3 * NCE)) {
        cudaMemcpyAsync(out + 2 * NCE, vx, NCE * sizeof(float),
                        cudaMemcpyDeviceToDevice, s2);
    }
    long long rem = os - (long long)(3 * NCE);
    if (rem > 0) {
        fill_ones_kernel<<<(int)((rem + 255) / 256), 256, 0, s2>>>(
            out + 3 * NCE, (int)rem);
    }
    split2_kernel<<<NX4/256, 256, 0, s2>>>(vx, xv[0], xv[1], NX4);
    split2_kernel<<<NW4/256, 256, 0, s2>>>(WV, wv[0], wv[1], NW4);
    mma_gemm_s<<<gemmGrid, 256, GEMM_SMEM, s2>>>(
        xv[0], xv[1], wv[0], wv[1], bV, ov[0], ov[1]);
    cudaEventRecord(evV, s2);

    // s0: attention waits on K and V
    cudaStreamWaitEvent(0, evK, 0);
    cudaStreamWaitEvent(0, evV, 0);
    attn_mma<<<dim3(LL/128, BB*HH), 256, ATTN_SMEM, 0>>>(
        oq[0], oq[1], ok[0], ok[1], ov[0], ov[1], xq[0], xq[1]);

    // s0: WO GEMM waits on WO split
    cudaStreamWaitEvent(0, evWO, 0);
    mma_gemm<<<gemmGrid, 256, GEMM_SMEM, 0>>>(
        xq[0], xq[1], wo[0], wo[1], bO, pA);

    add_ln_router_kernel<<<NTOK, 256>>>(qx, pA, ln1w, ln1b, Wsw, bsw, pzn, proute);
    scanpos_kernel<<<EE, 256>>>(proute, ppos, ps2t);
    cudaEventRecord(evScan, 0);

    // s1: dropped-token writes overlap with FFN (row-disjoint output)
    cudaStreamWaitEvent(s1, evScan, 0);
    finalize_dropped_kernel<<<NTOK, 256, 0, s1>>>(pzn, ppos, out);

    // s0: expert FFN (kept tokens)
    ffn1_kernel<<<EE * (CAPP/4), 256>>>(pzn, ps2t, W1, b1, ph);
    ffn2_out_kernel<<<EE * (CAPP/4), 256>>>(ph, W2, b2, ps2t, pzn, out);

    // join side streams back into s0 before returning
    cudaEventRecord(evJ1, s1);
    cudaEventRecord(evJ2, s2);
    cudaStreamWaitEvent(0, evJ1, 0);
    cudaStreamWaitEvent(0, evJ2, 0);

    cudaEventDestroy(evFork);
    cudaEventDestroy(evK);
    cudaEventDestroy(evV);
    cudaEventDestroy(evWO);
    cudaEventDestroy(evScan);
    cudaEventDestroy(evJ1);
    cudaEventDestroy(evJ2);
    cudaStreamDestroy(s1);
    cudaStreamDestroy(s2);
}